// round 4
// baseline (speedup 1.0000x reference)
#include <cuda_runtime.h>
#include <math.h>
#include <stdint.h>

// ---------------------------------------------------------------------------
// Problem constants: B=8, C=64, H=W=32, HW=1024, D=32
// ---------------------------------------------------------------------------
static constexpr long M8 = 8ll * 1024 * 1024;

// Scratch: 7 big [8,1024,1024] buffers (56M) + small pool (~5.9M); 68M floats.
__device__ float g_buf[68ll * 1024 * 1024];

// ===========================================================================
// 3xTF32 tensor-core batched GEMM.
//   C[b] (MxN, row-major, ldc) = opA(A[b]) * opB(B[b])
//   AMODE 0: A stored [M][lda] (k contiguous, "MK")   AMODE 1: A stored [K][lda] ("KM")
//   BMODE 0: B stored [N][ldb] ("NK", i.e. C = A*B^T) BMODE 1: B stored [K][ldb] ("KN")
// Tiles 128x128, K-chunk 16, 256 threads (8 warps, each 64x32).
// fp32 emulated via tf32 split: x = hi + lo; C = AhBh + AhBl + AlBh (~1e-6 err).
// Requires K % 16 == 0, M,N % 8 == 0. Edge tiles guarded.
// ===========================================================================
__device__ __forceinline__ void tf32_split(float x, uint32_t& h, uint32_t& l)
{
    uint32_t hb;
    asm("cvt.rna.tf32.f32 %0, %1;" : "=r"(hb) : "f"(x));
    float hf = __uint_as_float(hb);
    float lof = x - hf;
    uint32_t lb;
    asm("cvt.rna.tf32.f32 %0, %1;" : "=r"(lb) : "f"(lof));
    h = hb; l = lb;
}

__device__ __forceinline__ void mma_tf32(float* c, const uint32_t* a, const uint32_t* b)
{
    asm volatile(
        "mma.sync.aligned.m16n8k8.row.col.f32.tf32.tf32.f32 "
        "{%0,%1,%2,%3}, {%4,%5,%6,%7}, {%8,%9}, {%0,%1,%2,%3};\n"
        : "+f"(c[0]), "+f"(c[1]), "+f"(c[2]), "+f"(c[3])
        : "r"(a[0]), "r"(a[1]), "r"(a[2]), "r"(a[3]), "r"(b[0]), "r"(b[1]));
}

template<int AMODE, int BMODE>
__global__ void __launch_bounds__(256, 1)
tgemm_kernel(const float* __restrict__ A, const float* __restrict__ B,
             float* __restrict__ C, int M, int N, int K,
             int lda, int ldb, int ldc, long sA, long sB, long sC)
{
    __shared__ uint32_t AsH[16][132], AsL[16][132];
    __shared__ uint32_t BsH[16][132], BsL[16][132];

    const int tid  = threadIdx.x;
    const int lane = tid & 31;
    const int warp = tid >> 5;
    const int wm = (warp >> 2) * 64;   // 0 or 64
    const int wn = (warp & 3) * 32;    // 0..96
    const int g = lane >> 2, t = lane & 3;
    const int m0 = blockIdx.y * 128, n0 = blockIdx.x * 128;
    const float* Ab = A + (long)blockIdx.z * sA;
    const float* Bb = B + (long)blockIdx.z * sB;
    float* Cb = C + (long)blockIdx.z * sC;

    float acc[4][4][4];
#pragma unroll
    for (int i = 0; i < 4; i++)
#pragma unroll
        for (int j = 0; j < 4; j++)
#pragma unroll
            for (int r = 0; r < 4; r++) acc[i][j][r] = 0.f;

    for (int k0 = 0; k0 < K; k0 += 16) {
        // ---------------- stage A (hi/lo split) into As[k][m] ----------------
        if (AMODE == 0) {
            int r = tid >> 1, c8 = (tid & 1) * 8;
            float av[8] = {0,0,0,0,0,0,0,0};
            if (m0 + r < M) {
                const float* p = Ab + (long)(m0 + r) * lda + k0 + c8;
                float4 v0 = *(const float4*)p, v1 = *(const float4*)(p + 4);
                av[0]=v0.x; av[1]=v0.y; av[2]=v0.z; av[3]=v0.w;
                av[4]=v1.x; av[5]=v1.y; av[6]=v1.z; av[7]=v1.w;
            }
#pragma unroll
            for (int u = 0; u < 8; u++) {
                uint32_t h, l; tf32_split(av[u], h, l);
                AsH[c8 + u][r] = h; AsL[c8 + u][r] = l;
            }
        } else {
            int kr = tid >> 4, mc = (tid & 15) * 8;
            float av[8] = {0,0,0,0,0,0,0,0};
            if (m0 + mc < M) {
                const float* p = Ab + (long)(k0 + kr) * lda + m0 + mc;
                float4 v0 = *(const float4*)p, v1 = *(const float4*)(p + 4);
                av[0]=v0.x; av[1]=v0.y; av[2]=v0.z; av[3]=v0.w;
                av[4]=v1.x; av[5]=v1.y; av[6]=v1.z; av[7]=v1.w;
            }
#pragma unroll
            for (int u = 0; u < 8; u++) {
                uint32_t h, l; tf32_split(av[u], h, l);
                AsH[kr][mc + u] = h; AsL[kr][mc + u] = l;
            }
        }
        // ---------------- stage B into Bs[k][n] ----------------
        if (BMODE == 0) {
            int r = tid >> 1, c8 = (tid & 1) * 8;
            float bv[8] = {0,0,0,0,0,0,0,0};
            if (n0 + r < N) {
                const float* p = Bb + (long)(n0 + r) * ldb + k0 + c8;
                float4 v0 = *(const float4*)p, v1 = *(const float4*)(p + 4);
                bv[0]=v0.x; bv[1]=v0.y; bv[2]=v0.z; bv[3]=v0.w;
                bv[4]=v1.x; bv[5]=v1.y; bv[6]=v1.z; bv[7]=v1.w;
            }
#pragma unroll
            for (int u = 0; u < 8; u++) {
                uint32_t h, l; tf32_split(bv[u], h, l);
                BsH[c8 + u][r] = h; BsL[c8 + u][r] = l;
            }
        } else {
            int kr = tid >> 4, nc = (tid & 15) * 8;
            float bv[8] = {0,0,0,0,0,0,0,0};
            if (n0 + nc < N) {
                const float* p = Bb + (long)(k0 + kr) * ldb + n0 + nc;
                float4 v0 = *(const float4*)p, v1 = *(const float4*)(p + 4);
                bv[0]=v0.x; bv[1]=v0.y; bv[2]=v0.z; bv[3]=v0.w;
                bv[4]=v1.x; bv[5]=v1.y; bv[6]=v1.z; bv[7]=v1.w;
            }
#pragma unroll
            for (int u = 0; u < 8; u++) {
                uint32_t h, l; tf32_split(bv[u], h, l);
                BsH[kr][nc + u] = h; BsL[kr][nc + u] = l;
            }
        }
        __syncthreads();

        // ---------------- compute: two k8 steps ----------------
#pragma unroll
        for (int kk = 0; kk < 16; kk += 8) {
            uint32_t aH[4][4], aL[4][4], bH[4][2], bL[4][2];
#pragma unroll
            for (int i = 0; i < 4; i++) {
                int m = wm + i * 16 + g;
                aH[i][0] = AsH[kk + t][m];     aH[i][1] = AsH[kk + t][m + 8];
                aH[i][2] = AsH[kk + t + 4][m]; aH[i][3] = AsH[kk + t + 4][m + 8];
                aL[i][0] = AsL[kk + t][m];     aL[i][1] = AsL[kk + t][m + 8];
                aL[i][2] = AsL[kk + t + 4][m]; aL[i][3] = AsL[kk + t + 4][m + 8];
            }
#pragma unroll
            for (int j = 0; j < 4; j++) {
                int n = wn + j * 8 + g;
                bH[j][0] = BsH[kk + t][n]; bH[j][1] = BsH[kk + t + 4][n];
                bL[j][0] = BsL[kk + t][n]; bL[j][1] = BsL[kk + t + 4][n];
            }
#pragma unroll
            for (int i = 0; i < 4; i++)
#pragma unroll
                for (int j = 0; j < 4; j++) {
                    mma_tf32(acc[i][j], aH[i], bH[j]);
                    mma_tf32(acc[i][j], aH[i], bL[j]);
                    mma_tf32(acc[i][j], aL[i], bH[j]);
                }
        }
        __syncthreads();
    }

    // ---------------- epilogue ----------------
#pragma unroll
    for (int i = 0; i < 4; i++) {
#pragma unroll
        for (int j = 0; j < 4; j++) {
            int row0 = m0 + wm + i * 16 + g;
            int col  = n0 + wn + j * 8 + 2 * t;
            if (col < N) {
                if (row0 < M) {
                    float2 v = make_float2(acc[i][j][0], acc[i][j][1]);
                    *(float2*)(Cb + (long)row0 * ldc + col) = v;
                }
                if (row0 + 8 < M) {
                    float2 v = make_float2(acc[i][j][2], acc[i][j][3]);
                    *(float2*)(Cb + (long)(row0 + 8) * ldc + col) = v;
                }
            }
        }
    }
}

static void launch_tgemm(int amode, int bmode,
                         const float* A, const float* B, float* C,
                         int M, int N, int K, int lda, int ldb, int ldc,
                         long sA, long sB, long sC, int batch)
{
    dim3 grid((N + 127) / 128, (M + 127) / 128, batch);
    if (amode == 0 && bmode == 0)
        tgemm_kernel<0,0><<<grid, 256>>>(A, B, C, M, N, K, lda, ldb, ldc, sA, sB, sC);
    else if (amode == 0 && bmode == 1)
        tgemm_kernel<0,1><<<grid, 256>>>(A, B, C, M, N, K, lda, ldb, ldc, sA, sB, sC);
    else if (amode == 1 && bmode == 0)
        tgemm_kernel<1,0><<<grid, 256>>>(A, B, C, M, N, K, lda, ldb, ldc, sA, sB, sC);
    else
        tgemm_kernel<1,1><<<grid, 256>>>(A, B, C, M, N, K, lda, ldb, ldc, sA, sB, sC);
}

// ===========================================================================
// FFMA SGEMM for the small channel-path matrices (unchanged from R3)
// ===========================================================================
template <bool TA, bool TB>
__global__ void __launch_bounds__(256, 2)
gemm_kernel(const float* __restrict__ A, const float* __restrict__ B,
            float* __restrict__ Cmat, const float* __restrict__ bias,
            int M, int N, int K, long sA, long sB, long sC)
{
    __shared__ float As[16][128];
    __shared__ float Bs[16][128];

    const int tid = threadIdx.x;
    const int m0 = blockIdx.y * 128;
    const int n0 = blockIdx.x * 128;
    const float* Ab = A + (long)blockIdx.z * sA;
    const float* Bb = B + (long)blockIdx.z * sB;
    float* Cb = Cmat + (long)blockIdx.z * sC;

    float acc[8][8];
#pragma unroll
    for (int i = 0; i < 8; i++)
#pragma unroll
        for (int j = 0; j < 8; j++) acc[i][j] = 0.f;

    const int rowt = (tid >> 4) * 8;
    const int colt = (tid & 15) * 8;

    for (int k0 = 0; k0 < K; k0 += 16) {
        if (!TA) {
            int ar = tid >> 1;
            int ac = (tid & 1) * 8;
            float4 v0 = {0.f,0.f,0.f,0.f}, v1 = {0.f,0.f,0.f,0.f};
            if (m0 + ar < M) {
                const float* p = Ab + (long)(m0 + ar) * K + k0 + ac;
                v0 = *(const float4*)p;
                v1 = *(const float4*)(p + 4);
            }
            As[ac+0][ar] = v0.x; As[ac+1][ar] = v0.y; As[ac+2][ar] = v0.z; As[ac+3][ar] = v0.w;
            As[ac+4][ar] = v1.x; As[ac+5][ar] = v1.y; As[ac+6][ar] = v1.z; As[ac+7][ar] = v1.w;
        } else {
            int kr = tid >> 4;
            int mc = (tid & 15) * 8;
            float4 v0 = {0.f,0.f,0.f,0.f}, v1 = {0.f,0.f,0.f,0.f};
            if (m0 + mc < M) {
                const float* p = Ab + (long)(k0 + kr) * M + m0 + mc;
                v0 = *(const float4*)p;
                v1 = *(const float4*)(p + 4);
            }
            *(float4*)&As[kr][mc]     = v0;
            *(float4*)&As[kr][mc + 4] = v1;
        }
        if (TB) {
            int br = tid >> 1;
            int bc = (tid & 1) * 8;
            float4 v0 = {0.f,0.f,0.f,0.f}, v1 = {0.f,0.f,0.f,0.f};
            if (n0 + br < N) {
                const float* p = Bb + (long)(n0 + br) * K + k0 + bc;
                v0 = *(const float4*)p;
                v1 = *(const float4*)(p + 4);
            }
            Bs[bc+0][br] = v0.x; Bs[bc+1][br] = v0.y; Bs[bc+2][br] = v0.z; Bs[bc+3][br] = v0.w;
            Bs[bc+4][br] = v1.x; Bs[bc+5][br] = v1.y; Bs[bc+6][br] = v1.z; Bs[bc+7][br] = v1.w;
        } else {
            int kr = tid >> 4;
            int nc = (tid & 15) * 8;
            float4 v0 = {0.f,0.f,0.f,0.f}, v1 = {0.f,0.f,0.f,0.f};
            if (n0 + nc < N) {
                const float* p = Bb + (long)(k0 + kr) * N + n0 + nc;
                v0 = *(const float4*)p;
                v1 = *(const float4*)(p + 4);
            }
            *(float4*)&Bs[kr][nc]     = v0;
            *(float4*)&Bs[kr][nc + 4] = v1;
        }
        __syncthreads();

#pragma unroll
        for (int kk = 0; kk < 16; kk++) {
            float4 a0 = *(const float4*)&As[kk][rowt];
            float4 a1 = *(const float4*)&As[kk][rowt + 4];
            float4 b0 = *(const float4*)&Bs[kk][colt];
            float4 b1 = *(const float4*)&Bs[kk][colt + 4];
            float ra[8] = {a0.x,a0.y,a0.z,a0.w,a1.x,a1.y,a1.z,a1.w};
            float rb[8] = {b0.x,b0.y,b0.z,b0.w,b1.x,b1.y,b1.z,b1.w};
#pragma unroll
            for (int i = 0; i < 8; i++)
#pragma unroll
                for (int j = 0; j < 8; j++)
                    acc[i][j] += ra[i] * rb[j];
        }
        __syncthreads();
    }

#pragma unroll
    for (int i = 0; i < 8; i++) {
        int m = m0 + rowt + i;
        if (m < M) {
            float bv = bias ? bias[m] : 0.f;
            int n = n0 + colt;
            if (n < N) {
                float4 o0 = make_float4(acc[i][0]+bv, acc[i][1]+bv, acc[i][2]+bv, acc[i][3]+bv);
                float4 o1 = make_float4(acc[i][4]+bv, acc[i][5]+bv, acc[i][6]+bv, acc[i][7]+bv);
                float* cp = Cb + (long)m * N + n;
                *(float4*)cp       = o0;
                *(float4*)(cp + 4) = o1;
            }
        }
    }
}

// ---------------------------------------------------------------------------
// Row softmax: one block per row. A = softmax(L) rowwise.
// ---------------------------------------------------------------------------
__global__ void row_softmax_k(const float* __restrict__ L, float* __restrict__ A, int N)
{
    long row = blockIdx.x;
    const float* p = L + row * (long)N;
    float* q = A + row * (long)N;
    int t = threadIdx.x;
    __shared__ float sh[8];

    float m = -3.4e38f;
    for (int i = t; i < N; i += 256) m = fmaxf(m, p[i]);
#pragma unroll
    for (int o = 16; o; o >>= 1) m = fmaxf(m, __shfl_xor_sync(0xffffffffu, m, o));
    if ((t & 31) == 0) sh[t >> 5] = m;
    __syncthreads();
    float mm = sh[0];
#pragma unroll
    for (int w = 1; w < 8; w++) mm = fmaxf(mm, sh[w]);
    __syncthreads();

    float s = 0.f;
    for (int i = t; i < N; i += 256) s += expf(p[i] - mm);
#pragma unroll
    for (int o = 16; o; o >>= 1) s += __shfl_xor_sync(0xffffffffu, s, o);
    if ((t & 31) == 0) sh[t >> 5] = s;
    __syncthreads();
    float ss = 0.f;
#pragma unroll
    for (int w = 0; w < 8; w++) ss += sh[w];
    float inv = 1.f / ss;

    for (int i = t; i < N; i += 256) q[i] = expf(p[i] - mm) * inv;
}

// ---------------------------------------------------------------------------
// Column softmax of L [8][1024][1024], written transposed-in-place layout:
//   AT[b,k,i] = exp(L[b,k,i] - max_k) / sum_k  (== attn(x2f,x1f) stored [k][i])
// ---------------------------------------------------------------------------
__global__ void col_softmax_T_k(const float* __restrict__ L, float* __restrict__ AT)
{
    int c  = threadIdx.x & 63;
    int kg = threadIdx.x >> 6;
    int i  = blockIdx.x * 64 + c;
    const float* Lb = L  + (long)blockIdx.y * 1048576;
    float*       Ab = AT + (long)blockIdx.y * 1048576;
    __shared__ float red[4][64];

    float m = -3.4e38f;
    for (int k = kg; k < 1024; k += 4) m = fmaxf(m, Lb[(k << 10) + i]);
    red[kg][c] = m;
    __syncthreads();
    m = fmaxf(fmaxf(red[0][c], red[1][c]), fmaxf(red[2][c], red[3][c]));
    __syncthreads();

    float s = 0.f;
    for (int k = kg; k < 1024; k += 4) s += expf(Lb[(k << 10) + i] - m);
    red[kg][c] = s;
    __syncthreads();
    s = red[0][c] + red[1][c] + red[2][c] + red[3][c];
    float inv = 1.f / s;

    for (int k = kg; k < 1024; k += 4)
        Ab[(k << 10) + i] = expf(Lb[(k << 10) + i] - m) * inv;
}

// ---------------------------------------------------------------------------
// Keys cubic kernel, a = -0.5 (matches jax _fill_keys_cubic_kernel)
// ---------------------------------------------------------------------------
__device__ __forceinline__ float keys_cubic(float x)
{
    x = fabsf(x);
    if (x < 1.f) return ((1.5f * x - 2.5f) * x) * x + 1.f;
    if (x < 2.f) return ((-0.5f * x + 2.5f) * x - 4.f) * x + 2.f;
    return 0.f;
}

// Bicubic downsample by 2 with antialias (8 taps/dim), edge-renormalized.
__global__ void downsample_k(const float* __restrict__ x, float* __restrict__ y)
{
    int idx = blockIdx.x * 256 + threadIdx.x;
    if (idx >= 8 * 64 * 256) return;
    int ox = idx & 15;
    int oy = (idx >> 4) & 15;
    int bc = idx >> 8;

    int jy0 = 2 * oy - 3, jx0 = 2 * ox - 3;
    float wy[8], wx[8];
    float sy = 0.f, sx = 0.f;
#pragma unroll
    for (int t = 0; t < 8; t++) {
        float w = keys_cubic(fabsf(3.5f - t) * 0.5f);
        int jy = jy0 + t;
        wy[t] = (jy >= 0 && jy < 32) ? w : 0.f; sy += wy[t];
        int jx = jx0 + t;
        wx[t] = (jx >= 0 && jx < 32) ? w : 0.f; sx += wx[t];
    }
    float iy = 1.f / sy, ix = 1.f / sx;
#pragma unroll
    for (int t = 0; t < 8; t++) { wy[t] *= iy; wx[t] *= ix; }

    const float* src = x + (long)bc * 1024;
    float acc = 0.f;
#pragma unroll
    for (int t = 0; t < 8; t++) {
        int jy = min(max(jy0 + t, 0), 31);
        float r = 0.f;
#pragma unroll
        for (int u = 0; u < 8; u++) {
            int jx = min(max(jx0 + u, 0), 31);
            r += wx[u] * src[jy * 32 + jx];
        }
        acc += wy[t] * r;
    }
    y[idx] = acc;
}

// Bicubic upsample x4 (4 taps/dim), src [8,256,256] -> dst [8,1024,1024]
__global__ void upsample_k(const float* __restrict__ s, float* __restrict__ d)
{
    long idx = (long)blockIdx.x * 256 + threadIdx.x;
    if (idx >= 8ll * 1024 * 1024) return;
    int J = (int)(idx & 1023);
    int I = (int)((idx >> 10) & 1023);
    int b = (int)(idx >> 20);

    int i0, j0;
    float wi[4], wj[4];
    {
        float sf = (I + 0.5f) * 0.25f - 0.5f;
        float fl = floorf(sf);
        float f  = sf - fl;
        int base = (int)fl - 1;
        float tot = 0.f;
#pragma unroll
        for (int t = 0; t < 4; t++) {
            float w = keys_cubic(f + 1.f - t);
            int j = base + t;
            if (j < 0 || j >= 256) w = 0.f;
            wi[t] = w; tot += w;
        }
        float inv = 1.f / tot;
#pragma unroll
        for (int t = 0; t < 4; t++) wi[t] *= inv;
        i0 = base;
    }
    {
        float sf = (J + 0.5f) * 0.25f - 0.5f;
        float fl = floorf(sf);
        float f  = sf - fl;
        int base = (int)fl - 1;
        float tot = 0.f;
#pragma unroll
        for (int t = 0; t < 4; t++) {
            float w = keys_cubic(f + 1.f - t);
            int j = base + t;
            if (j < 0 || j >= 256) w = 0.f;
            wj[t] = w; tot += w;
        }
        float inv = 1.f / tot;
#pragma unroll
        for (int t = 0; t < 4; t++) wj[t] *= inv;
        j0 = base;
    }

    const float* sp = s + (long)b * 65536;
    float acc = 0.f;
#pragma unroll
    for (int t = 0; t < 4; t++) {
        int ii = min(max(i0 + t, 0), 255);
        float r = 0.f;
#pragma unroll
        for (int u = 0; u < 4; u++) {
            int jj = min(max(j0 + u, 0), 255);
            r += wj[u] * sp[ii * 256 + jj];
        }
        acc += wi[t] * r;
    }
    d[idx] = acc;
}

// ---------------------------------------------------------------------------
// BN stats over (B, HW) for T in [B][C][HW] layout -> mv[c], mv[64+c]
// ---------------------------------------------------------------------------
__global__ void bn_stats_k(const float* __restrict__ T, float* __restrict__ mv)
{
    int c = blockIdx.x;
    int t = threadIdx.x;
    float s = 0.f, s2 = 0.f;
    for (int i = t; i < 8192; i += 256) {
        float v = T[(long)(i >> 10) * 65536 + c * 1024 + (i & 1023)];
        s += v; s2 += v * v;
    }
    __shared__ float sh1[8], sh2[8];
#pragma unroll
    for (int o = 16; o; o >>= 1) {
        s  += __shfl_xor_sync(0xffffffffu, s, o);
        s2 += __shfl_xor_sync(0xffffffffu, s2, o);
    }
    if ((t & 31) == 0) { sh1[t >> 5] = s; sh2[t >> 5] = s2; }
    __syncthreads();
    if (t == 0) {
        float ts = 0.f, ts2 = 0.f;
#pragma unroll
        for (int w = 0; w < 8; w++) { ts += sh1[w]; ts2 += sh2[w]; }
        float mean = ts * (1.f / 8192.f);
        float var  = ts2 * (1.f / 8192.f) - mean * mean;
        mv[c] = mean;
        mv[64 + c] = fmaxf(var, 0.f);
    }
}

// BN stats for T in transposed [B][HW][C] layout
__global__ void bn_stats_t_k(const float* __restrict__ T, float* __restrict__ mv)
{
    int c = blockIdx.x;
    int t = threadIdx.x;
    float s = 0.f, s2 = 0.f;
    for (int i = t; i < 8192; i += 256) {
        float v = T[(long)(i >> 10) * 65536 + (i & 1023) * 64 + c];
        s += v; s2 += v * v;
    }
    __shared__ float sh1[8], sh2[8];
#pragma unroll
    for (int o = 16; o; o >>= 1) {
        s  += __shfl_xor_sync(0xffffffffu, s, o);
        s2 += __shfl_xor_sync(0xffffffffu, s2, o);
    }
    if ((t & 31) == 0) { sh1[t >> 5] = s; sh2[t >> 5] = s2; }
    __syncthreads();
    if (t == 0) {
        float ts = 0.f, ts2 = 0.f;
#pragma unroll
        for (int w = 0; w < 8; w++) { ts += sh1[w]; ts2 += sh2[w]; }
        float mean = ts * (1.f / 8192.f);
        float var  = ts2 * (1.f / 8192.f) - mean * mean;
        mv[c] = mean;
        mv[64 + c] = fmaxf(var, 0.f);
    }
}

// ---------------------------------------------------------------------------
// Finalize. ch_o in [B][C][HW]; hw_o in TRANSPOSED [B][HW][C] layout.
// ---------------------------------------------------------------------------
__global__ void finalize_k(const float* __restrict__ x1, const float* __restrict__ x2,
                           const float* __restrict__ ch1o, const float* __restrict__ ch2o,
                           const float* __restrict__ hw1t, const float* __restrict__ hw2t,
                           const float* __restrict__ mv,
                           const float* __restrict__ gamma, const float* __restrict__ beta,
                           float* __restrict__ out)
{
    int idx = blockIdx.x * 256 + threadIdx.x;
    if (idx >= 524288) return;
    int c = (idx >> 10) & 63;
    long hwi = ((long)(idx >> 16)) * 65536 + (long)(idx & 1023) * 64 + c;
    float g = gamma[c], be = beta[c];

    float xa = x1[idx], xb = x2[idx];

    float v, r;
    v = (ch1o[idx] - mv[c])       * rsqrtf(mv[64 + c]  + 1e-5f) * g + be + xa;
    r = fmaxf(v, 0.f);
    v = (hw1t[hwi] - mv[256 + c]) * rsqrtf(mv[320 + c] + 1e-5f) * g + be + xa;
    out[idx] = 0.5f * (r + fmaxf(v, 0.f));

    v = (ch2o[idx] - mv[128 + c]) * rsqrtf(mv[192 + c] + 1e-5f) * g + be + xb;
    r = fmaxf(v, 0.f);
    v = (hw2t[hwi] - mv[384 + c]) * rsqrtf(mv[448 + c] + 1e-5f) * g + be + xb;
    out[524288 + idx] = 0.5f * (r + fmaxf(v, 0.f));
}

// ---------------------------------------------------------------------------
// FFMA GEMM dispatch (small channel-path matrices)
// ---------------------------------------------------------------------------
static void launch_gemm(bool ta, bool tb,
                        const float* A, const float* B, float* C, const float* bias,
                        int M, int N, int K, long sA, long sB, long sC, int batch)
{
    dim3 grid((N + 127) / 128, (M + 127) / 128, batch);
    if (!ta && !tb)      gemm_kernel<false, false><<<grid, 256>>>(A, B, C, bias, M, N, K, sA, sB, sC);
    else if (!ta && tb)  gemm_kernel<false, true ><<<grid, 256>>>(A, B, C, bias, M, N, K, sA, sB, sC);
    else if (ta && !tb)  gemm_kernel<true,  false><<<grid, 256>>>(A, B, C, bias, M, N, K, sA, sB, sC);
    else                 gemm_kernel<true,  true ><<<grid, 256>>>(A, B, C, bias, M, N, K, sA, sB, sC);
}

extern "C" void kernel_launch(void* const* d_in, const int* in_sizes, int n_in,
                              void* d_out, int out_size)
{
    const float* x1     = (const float*)d_in[0];   // [8,64,32,32]
    const float* x2     = (const float*)d_in[1];
    const float* w_down = (const float*)d_in[2];   // [32,64]
    const float* b_down = (const float*)d_in[3];   // [32]
    const float* w_up   = (const float*)d_in[4];   // [64,32]
    const float* b_up   = (const float*)d_in[5];   // [64]
    const float* gamma  = (const float*)d_in[6];   // [64]
    const float* beta   = (const float*)d_in[7];   // [64]
    float* out = (float*)d_out;

    float* base = nullptr;
    cudaGetSymbolAddress((void**)&base, g_buf);

    // Big [8M] buffers; HW1 aliases X1F, HW2 aliases X2F (dead after LB gemm).
    float* X1F  = base + 0 * M8;
    float* X2F  = base + 1 * M8;
    float* LB   = base + 2 * M8;
    float* A12  = base + 3 * M8;
    float* A21T = base + 4 * M8;
    float* UP1  = base + 5 * M8;
    float* UP2  = base + 6 * M8;
    float* HW1  = X1F;   // reuse
    float* HW2  = X2F;   // reuse

    float* S = base + 7 * M8;
    float* XD1   = S; S += 262144;
    float* XD2   = S; S += 262144;
    float* X1C   = S; S += 32768;
    float* X2C   = S; S += 32768;
    float* X1CD  = S; S += 8192;
    float* X2CD  = S; S += 8192;
    float* LC    = S; S += 32768;
    float* AC12  = S; S += 32768;
    float* AC21  = S; S += 32768;
    float* LCD   = S; S += 8192;
    float* ACD12 = S; S += 8192;
    float* ACD21 = S; S += 8192;
    float* TT    = S; S += 16384;
    float* U1T   = S; S += 32768;
    float* U2T   = S; S += 32768;
    float* CH1   = S; S += 32768;
    float* CH2   = S; S += 32768;
    float* CH1O  = S; S += 524288;
    float* CH2O  = S; S += 524288;
    float* XDN1  = S; S += 131072;
    float* XDN2  = S; S += 131072;
    float* X1FD  = S; S += 524288;
    float* X2FD  = S; S += 524288;
    float* LFD   = S; S += 524288;
    float* AFD12 = S; S += 524288;
    float* AFD21 = S; S += 524288;
    float* HW1OT = S; S += 524288;   // [B][HW][C]
    float* HW2OT = S; S += 524288;   // [B][HW][C]
    float* MV    = S; S += 512;

    // ===================== channel path (small, FFMA) =====================
    launch_gemm(false, true, x1, x1, X1C, nullptr, 64, 64, 1024, 65536, 65536, 4096, 8);
    launch_gemm(false, true, x2, x2, X2C, nullptr, 64, 64, 1024, 65536, 65536, 4096, 8);
    launch_gemm(false, false, w_down, x1, XD1, b_down, 32, 1024, 64, 0, 65536, 32768, 8);
    launch_gemm(false, false, w_down, x2, XD2, b_down, 32, 1024, 64, 0, 65536, 32768, 8);
    launch_gemm(false, true, XD1, XD1, X1CD, nullptr, 32, 32, 1024, 32768, 32768, 1024, 8);
    launch_gemm(false, true, XD2, XD2, X2CD, nullptr, 32, 32, 1024, 32768, 32768, 1024, 8);
    launch_gemm(false, true, X1C, X2C, LC, nullptr, 64, 64, 64, 4096, 4096, 4096, 8);
    row_softmax_k<<<512, 256>>>(LC, AC12, 64);
    launch_gemm(false, true, X2C, X1C, LC, nullptr, 64, 64, 64, 4096, 4096, 4096, 8);
    row_softmax_k<<<512, 256>>>(LC, AC21, 64);
    launch_gemm(false, true, X1CD, X2CD, LCD, nullptr, 32, 32, 32, 1024, 1024, 1024, 8);
    row_softmax_k<<<256, 256>>>(LCD, ACD12, 32);
    launch_gemm(false, true, X2CD, X1CD, LCD, nullptr, 32, 32, 32, 1024, 1024, 1024, 8);
    row_softmax_k<<<256, 256>>>(LCD, ACD21, 32);
    launch_gemm(false, false, w_up, ACD12, TT, b_up, 64, 32, 32, 0, 1024, 2048, 8);
    launch_gemm(false, true,  w_up, TT, U1T, b_up, 64, 64, 32, 0, 2048, 4096, 8);
    launch_gemm(false, false, w_up, ACD21, TT, b_up, 64, 32, 32, 0, 1024, 2048, 8);
    launch_gemm(false, true,  w_up, TT, U2T, b_up, 64, 64, 32, 0, 2048, 4096, 8);
    launch_gemm(false, true, AC12, U1T, CH1, nullptr, 64, 64, 64, 4096, 4096, 4096, 8);
    launch_gemm(false, true, AC21, U2T, CH2, nullptr, 64, 64, 64, 4096, 4096, 4096, 8);
    launch_gemm(false, false, CH1, x1, CH1O, nullptr, 64, 1024, 64, 4096, 65536, 65536, 8);
    launch_gemm(false, false, CH2, x2, CH2O, nullptr, 64, 1024, 64, 4096, 65536, 65536, 8);

    // ===================== feature path (tensor cores, 3xTF32) =====================
    // feature grams: X?F = x^T x  (KM x KN)
    launch_tgemm(1, 1, x1, x1, X1F, 1024, 1024, 64, 1024, 1024, 1024, 65536, 65536, 1048576, 8);
    launch_tgemm(1, 1, x2, x2, X2F, 1024, 1024, 64, 1024, 1024, 1024, 65536, 65536, 1048576, 8);
    // bicubic downsample 32->16
    downsample_k<<<512, 256>>>(x1, XDN1);
    downsample_k<<<512, 256>>>(x2, XDN2);
    // down feature grams [8,256,256]
    launch_tgemm(1, 1, XDN1, XDN1, X1FD, 256, 256, 64, 256, 256, 256, 16384, 16384, 65536, 8);
    launch_tgemm(1, 1, XDN2, XDN2, X2FD, 256, 256, 64, 256, 256, 256, 16384, 16384, 65536, 8);
    // down feature attentions (NT)
    launch_tgemm(0, 0, X1FD, X2FD, LFD, 256, 256, 256, 256, 256, 256, 65536, 65536, 65536, 8);
    row_softmax_k<<<2048, 256>>>(LFD, AFD12, 256);
    launch_tgemm(0, 0, X2FD, X1FD, LFD, 256, 256, 256, 256, 256, 256, 65536, 65536, 65536, 8);
    row_softmax_k<<<2048, 256>>>(LFD, AFD21, 256);
    // bicubic upsample x4
    upsample_k<<<32768, 256>>>(AFD12, UP1);
    upsample_k<<<32768, 256>>>(AFD21, UP2);
    // big logits L = X1F @ X2F^T (shared both directions)
    launch_tgemm(0, 0, X1F, X2F, LB, 1024, 1024, 1024, 1024, 1024, 1024, 1048576, 1048576, 1048576, 8);
    row_softmax_k<<<8192, 256>>>(LB, A12, 1024);
    {
        dim3 g(16, 8);
        col_softmax_T_k<<<g, 256>>>(LB, A21T);
    }
    // hw1 = A12 @ UP1 (MK x KN); hw2 = A21T^T @ UP2 (KM x KN)
    launch_tgemm(0, 1, A12,  UP1, HW1, 1024, 1024, 1024, 1024, 1024, 1024, 1048576, 1048576, 1048576, 8);
    launch_tgemm(1, 1, A21T, UP2, HW2, 1024, 1024, 1024, 1024, 1024, 1024, 1048576, 1048576, 1048576, 8);
    // hw_o transposed: HW?OT[p][c] = sum_q HW[p][q] x[c][q]  (MK x NK, N=64)
    launch_tgemm(0, 0, HW1, x1, HW1OT, 1024, 64, 1024, 1024, 1024, 64, 1048576, 65536, 65536, 8);
    launch_tgemm(0, 0, HW2, x2, HW2OT, 1024, 64, 1024, 1024, 1024, 64, 1048576, 65536, 65536, 8);

    // ===================== BN + residual + relu + average =====================
    bn_stats_k<<<64, 256>>>(CH1O, MV);
    bn_stats_k<<<64, 256>>>(CH2O, MV + 128);
    bn_stats_t_k<<<64, 256>>>(HW1OT, MV + 256);
    bn_stats_t_k<<<64, 256>>>(HW2OT, MV + 384);
    finalize_k<<<2048, 256>>>(x1, x2, CH1O, CH2O, HW1OT, HW2OT, MV, gamma, beta, out);
}

// round 5
// speedup vs baseline: 1.0070x; 1.0070x over previous
#include <cuda_runtime.h>
#include <math.h>
#include <stdint.h>

// ---------------------------------------------------------------------------
// Problem constants: B=8, C=64, H=W=32, HW=1024, D=32
// ---------------------------------------------------------------------------
static constexpr long M8 = 8ll * 1024 * 1024;

__device__ float g_buf[68ll * 1024 * 1024];

// ===========================================================================
// 3xTF32 tensor-core batched GEMM (v2: uint2 H/L smem + reg double-buffer).
//   C[b] (MxN, row-major, ldc) = opA(A[b]) * opB(B[b])
//   AMODE 0: A stored [M][lda] ("MK")   AMODE 1: A stored [K][lda] ("KM")
//   BMODE 0: B stored [N][ldb] ("NK" -> C=A*B^T)  BMODE 1: B stored [K][ldb] ("KN")
// Tiles 128x128, K-chunk 16, 256 threads (8 warps, 64x32 each).
// fp32 via tf32 split: x = hi + lo; C = AhBh + AhBl + AlBh (~1e-4 rel err).
// Requires K % 16 == 0, M,N % 8 == 0.
// ===========================================================================
__device__ __forceinline__ uint2 tf32_split2(float x)
{
    uint32_t hb;
    asm("cvt.rna.tf32.f32 %0, %1;" : "=r"(hb) : "f"(x));
    float lof = x - __uint_as_float(hb);
    uint32_t lb;
    asm("cvt.rna.tf32.f32 %0, %1;" : "=r"(lb) : "f"(lof));
    return make_uint2(hb, lb);
}

__device__ __forceinline__ void mma_tf32(float* c,
    uint32_t a0, uint32_t a1, uint32_t a2, uint32_t a3,
    uint32_t b0, uint32_t b1)
{
    asm volatile(
        "mma.sync.aligned.m16n8k8.row.col.f32.tf32.tf32.f32 "
        "{%0,%1,%2,%3}, {%4,%5,%6,%7}, {%8,%9}, {%0,%1,%2,%3};\n"
        : "+f"(c[0]), "+f"(c[1]), "+f"(c[2]), "+f"(c[3])
        : "r"(a0), "r"(a1), "r"(a2), "r"(a3), "r"(b0), "r"(b1));
}

template<int AMODE, int BMODE>
__global__ void __launch_bounds__(256)
tgemm_kernel(const float* __restrict__ A, const float* __restrict__ B,
             float* __restrict__ C, int M, int N, int K,
             int lda, int ldb, int ldc, long sA, long sB, long sC)
{
    __shared__ uint2 As2[16][136];   // .x = hi tf32, .y = lo tf32, indexed [k][m]
    __shared__ uint2 Bs2[16][136];   // [k][n]

    const int tid  = threadIdx.x;
    const int lane = tid & 31;
    const int warp = tid >> 5;
    const int wm = (warp >> 2) * 64;
    const int wn = (warp & 3) * 32;
    const int g = lane >> 2, t = lane & 3;
    const int m0 = blockIdx.y * 128, n0 = blockIdx.x * 128;
    const float* Ab = A + (long)blockIdx.z * sA;
    const float* Bb = B + (long)blockIdx.z * sB;
    float* Cb = C + (long)blockIdx.z * sC;

    float acc[4][4][4];
#pragma unroll
    for (int i = 0; i < 4; i++)
#pragma unroll
        for (int j = 0; j < 4; j++)
#pragma unroll
            for (int r = 0; r < 4; r++) acc[i][j][r] = 0.f;

    float aSt[8], bSt[8];

    // ---- global-load helpers (register staging) ----
    auto loadA = [&](int k0) {
#pragma unroll
        for (int u = 0; u < 8; u++) aSt[u] = 0.f;
        if (AMODE == 0) {
            int r = tid >> 1, c8 = (tid & 1) * 8;
            if (m0 + r < M) {
                const float* p = Ab + (long)(m0 + r) * lda + k0 + c8;
                float4 v0 = *(const float4*)p, v1 = *(const float4*)(p + 4);
                aSt[0]=v0.x; aSt[1]=v0.y; aSt[2]=v0.z; aSt[3]=v0.w;
                aSt[4]=v1.x; aSt[5]=v1.y; aSt[6]=v1.z; aSt[7]=v1.w;
            }
        } else {
            int kr = tid >> 4, mc = (tid & 15) * 8;
            if (m0 + mc < M) {
                const float* p = Ab + (long)(k0 + kr) * lda + m0 + mc;
                float4 v0 = *(const float4*)p, v1 = *(const float4*)(p + 4);
                aSt[0]=v0.x; aSt[1]=v0.y; aSt[2]=v0.z; aSt[3]=v0.w;
                aSt[4]=v1.x; aSt[5]=v1.y; aSt[6]=v1.z; aSt[7]=v1.w;
            }
        }
    };
    auto loadB = [&](int k0) {
#pragma unroll
        for (int u = 0; u < 8; u++) bSt[u] = 0.f;
        if (BMODE == 0) {
            int r = tid >> 1, c8 = (tid & 1) * 8;
            if (n0 + r < N) {
                const float* p = Bb + (long)(n0 + r) * ldb + k0 + c8;
                float4 v0 = *(const float4*)p, v1 = *(const float4*)(p + 4);
                bSt[0]=v0.x; bSt[1]=v0.y; bSt[2]=v0.z; bSt[3]=v0.w;
                bSt[4]=v1.x; bSt[5]=v1.y; bSt[6]=v1.z; bSt[7]=v1.w;
            }
        } else {
            int kr = tid >> 4, nc = (tid & 15) * 8;
            if (n0 + nc < N) {
                const float* p = Bb + (long)(k0 + kr) * ldb + n0 + nc;
                float4 v0 = *(const float4*)p, v1 = *(const float4*)(p + 4);
                bSt[0]=v0.x; bSt[1]=v0.y; bSt[2]=v0.z; bSt[3]=v0.w;
                bSt[4]=v1.x; bSt[5]=v1.y; bSt[6]=v1.z; bSt[7]=v1.w;
            }
        }
    };

    loadA(0); loadB(0);

    for (int k0 = 0; k0 < K; k0 += 16) {
        // ---- split + store current staged chunk ----
        if (AMODE == 0) {
            int r = tid >> 1, c8 = (tid & 1) * 8;
#pragma unroll
            for (int u = 0; u < 8; u++) As2[c8 + u][r] = tf32_split2(aSt[u]);
        } else {
            int kr = tid >> 4, mc = (tid & 15) * 8;
#pragma unroll
            for (int u = 0; u < 8; u++) As2[kr][mc + u] = tf32_split2(aSt[u]);
        }
        if (BMODE == 0) {
            int r = tid >> 1, c8 = (tid & 1) * 8;
#pragma unroll
            for (int u = 0; u < 8; u++) Bs2[c8 + u][r] = tf32_split2(bSt[u]);
        } else {
            int kr = tid >> 4, nc = (tid & 15) * 8;
#pragma unroll
            for (int u = 0; u < 8; u++) Bs2[kr][nc + u] = tf32_split2(bSt[u]);
        }
        __syncthreads();

        // ---- prefetch next chunk (overlaps compute) ----
        if (k0 + 16 < K) { loadA(k0 + 16); loadB(k0 + 16); }

        // ---- compute: two k8 steps ----
#pragma unroll
        for (int kk = 0; kk < 16; kk += 8) {
            uint2 a[4][4], b[4][2];
#pragma unroll
            for (int i = 0; i < 4; i++) {
                int m = wm + i * 16 + g;
                a[i][0] = As2[kk + t][m];
                a[i][1] = As2[kk + t][m + 8];
                a[i][2] = As2[kk + t + 4][m];
                a[i][3] = As2[kk + t + 4][m + 8];
            }
#pragma unroll
            for (int j = 0; j < 4; j++) {
                int n = wn + j * 8 + g;
                b[j][0] = Bs2[kk + t][n];
                b[j][1] = Bs2[kk + t + 4][n];
            }
#pragma unroll
            for (int i = 0; i < 4; i++)
#pragma unroll
                for (int j = 0; j < 4; j++) {
                    mma_tf32(acc[i][j], a[i][0].x, a[i][1].x, a[i][2].x, a[i][3].x,
                             b[j][0].x, b[j][1].x);
                    mma_tf32(acc[i][j], a[i][0].x, a[i][1].x, a[i][2].x, a[i][3].x,
                             b[j][0].y, b[j][1].y);
                    mma_tf32(acc[i][j], a[i][0].y, a[i][1].y, a[i][2].y, a[i][3].y,
                             b[j][0].x, b[j][1].x);
                }
        }
        __syncthreads();
    }

    // ---- epilogue ----
#pragma unroll
    for (int i = 0; i < 4; i++) {
#pragma unroll
        for (int j = 0; j < 4; j++) {
            int row0 = m0 + wm + i * 16 + g;
            int col  = n0 + wn + j * 8 + 2 * t;
            if (col < N) {
                if (row0 < M) {
                    float2 v = make_float2(acc[i][j][0], acc[i][j][1]);
                    *(float2*)(Cb + (long)row0 * ldc + col) = v;
                }
                if (row0 + 8 < M) {
                    float2 v = make_float2(acc[i][j][2], acc[i][j][3]);
                    *(float2*)(Cb + (long)(row0 + 8) * ldc + col) = v;
                }
            }
        }
    }
}

static void launch_tgemm(int amode, int bmode,
                         const float* A, const float* B, float* C,
                         int M, int N, int K, int lda, int ldb, int ldc,
                         long sA, long sB, long sC, int batch)
{
    dim3 grid((N + 127) / 128, (M + 127) / 128, batch);
    if (amode == 0 && bmode == 0)
        tgemm_kernel<0,0><<<grid, 256>>>(A, B, C, M, N, K, lda, ldb, ldc, sA, sB, sC);
    else if (amode == 0 && bmode == 1)
        tgemm_kernel<0,1><<<grid, 256>>>(A, B, C, M, N, K, lda, ldb, ldc, sA, sB, sC);
    else if (amode == 1 && bmode == 0)
        tgemm_kernel<1,0><<<grid, 256>>>(A, B, C, M, N, K, lda, ldb, ldc, sA, sB, sC);
    else
        tgemm_kernel<1,1><<<grid, 256>>>(A, B, C, M, N, K, lda, ldb, ldc, sA, sB, sC);
}

// ===========================================================================
// FFMA SGEMM for the small channel-path matrices
// ===========================================================================
template <bool TA, bool TB>
__global__ void __launch_bounds__(256, 2)
gemm_kernel(const float* __restrict__ A, const float* __restrict__ B,
            float* __restrict__ Cmat, const float* __restrict__ bias,
            int M, int N, int K, long sA, long sB, long sC)
{
    __shared__ float As[16][128];
    __shared__ float Bs[16][128];

    const int tid = threadIdx.x;
    const int m0 = blockIdx.y * 128;
    const int n0 = blockIdx.x * 128;
    const float* Ab = A + (long)blockIdx.z * sA;
    const float* Bb = B + (long)blockIdx.z * sB;
    float* Cb = Cmat + (long)blockIdx.z * sC;

    float acc[8][8];
#pragma unroll
    for (int i = 0; i < 8; i++)
#pragma unroll
        for (int j = 0; j < 8; j++) acc[i][j] = 0.f;

    const int rowt = (tid >> 4) * 8;
    const int colt = (tid & 15) * 8;

    for (int k0 = 0; k0 < K; k0 += 16) {
        if (!TA) {
            int ar = tid >> 1;
            int ac = (tid & 1) * 8;
            float4 v0 = {0.f,0.f,0.f,0.f}, v1 = {0.f,0.f,0.f,0.f};
            if (m0 + ar < M) {
                const float* p = Ab + (long)(m0 + ar) * K + k0 + ac;
                v0 = *(const float4*)p;
                v1 = *(const float4*)(p + 4);
            }
            As[ac+0][ar] = v0.x; As[ac+1][ar] = v0.y; As[ac+2][ar] = v0.z; As[ac+3][ar] = v0.w;
            As[ac+4][ar] = v1.x; As[ac+5][ar] = v1.y; As[ac+6][ar] = v1.z; As[ac+7][ar] = v1.w;
        } else {
            int kr = tid >> 4;
            int mc = (tid & 15) * 8;
            float4 v0 = {0.f,0.f,0.f,0.f}, v1 = {0.f,0.f,0.f,0.f};
            if (m0 + mc < M) {
                const float* p = Ab + (long)(k0 + kr) * M + m0 + mc;
                v0 = *(const float4*)p;
                v1 = *(const float4*)(p + 4);
            }
            *(float4*)&As[kr][mc]     = v0;
            *(float4*)&As[kr][mc + 4] = v1;
        }
        if (TB) {
            int br = tid >> 1;
            int bc = (tid & 1) * 8;
            float4 v0 = {0.f,0.f,0.f,0.f}, v1 = {0.f,0.f,0.f,0.f};
            if (n0 + br < N) {
                const float* p = Bb + (long)(n0 + br) * K + k0 + bc;
                v0 = *(const float4*)p;
                v1 = *(const float4*)(p + 4);
            }
            Bs[bc+0][br] = v0.x; Bs[bc+1][br] = v0.y; Bs[bc+2][br] = v0.z; Bs[bc+3][br] = v0.w;
            Bs[bc+4][br] = v1.x; Bs[bc+5][br] = v1.y; Bs[bc+6][br] = v1.z; Bs[bc+7][br] = v1.w;
        } else {
            int kr = tid >> 4;
            int nc = (tid & 15) * 8;
            float4 v0 = {0.f,0.f,0.f,0.f}, v1 = {0.f,0.f,0.f,0.f};
            if (n0 + nc < N) {
                const float* p = Bb + (long)(k0 + kr) * N + n0 + nc;
                v0 = *(const float4*)p;
                v1 = *(const float4*)(p + 4);
            }
            *(float4*)&Bs[kr][nc]     = v0;
            *(float4*)&Bs[kr][nc + 4] = v1;
        }
        __syncthreads();

#pragma unroll
        for (int kk = 0; kk < 16; kk++) {
            float4 a0 = *(const float4*)&As[kk][rowt];
            float4 a1 = *(const float4*)&As[kk][rowt + 4];
            float4 b0 = *(const float4*)&Bs[kk][colt];
            float4 b1 = *(const float4*)&Bs[kk][colt + 4];
            float ra[8] = {a0.x,a0.y,a0.z,a0.w,a1.x,a1.y,a1.z,a1.w};
            float rb[8] = {b0.x,b0.y,b0.z,b0.w,b1.x,b1.y,b1.z,b1.w};
#pragma unroll
            for (int i = 0; i < 8; i++)
#pragma unroll
                for (int j = 0; j < 8; j++)
                    acc[i][j] += ra[i] * rb[j];
        }
        __syncthreads();
    }

#pragma unroll
    for (int i = 0; i < 8; i++) {
        int m = m0 + rowt + i;
        if (m < M) {
            float bv = bias ? bias[m] : 0.f;
            int n = n0 + colt;
            if (n < N) {
                float4 o0 = make_float4(acc[i][0]+bv, acc[i][1]+bv, acc[i][2]+bv, acc[i][3]+bv);
                float4 o1 = make_float4(acc[i][4]+bv, acc[i][5]+bv, acc[i][6]+bv, acc[i][7]+bv);
                float* cp = Cb + (long)m * N + n;
                *(float4*)cp       = o0;
                *(float4*)(cp + 4) = o1;
            }
        }
    }
}

// ---------------------------------------------------------------------------
// Row softmax
// ---------------------------------------------------------------------------
__global__ void row_softmax_k(const float* __restrict__ L, float* __restrict__ A, int N)
{
    long row = blockIdx.x;
    const float* p = L + row * (long)N;
    float* q = A + row * (long)N;
    int t = threadIdx.x;
    __shared__ float sh[8];

    float m = -3.4e38f;
    for (int i = t; i < N; i += 256) m = fmaxf(m, p[i]);
#pragma unroll
    for (int o = 16; o; o >>= 1) m = fmaxf(m, __shfl_xor_sync(0xffffffffu, m, o));
    if ((t & 31) == 0) sh[t >> 5] = m;
    __syncthreads();
    float mm = sh[0];
#pragma unroll
    for (int w = 1; w < 8; w++) mm = fmaxf(mm, sh[w]);
    __syncthreads();

    float s = 0.f;
    for (int i = t; i < N; i += 256) s += expf(p[i] - mm);
#pragma unroll
    for (int o = 16; o; o >>= 1) s += __shfl_xor_sync(0xffffffffu, s, o);
    if ((t & 31) == 0) sh[t >> 5] = s;
    __syncthreads();
    float ss = 0.f;
#pragma unroll
    for (int w = 0; w < 8; w++) ss += sh[w];
    float inv = 1.f / ss;

    for (int i = t; i < N; i += 256) q[i] = expf(p[i] - mm) * inv;
}

// ---------------------------------------------------------------------------
// Column softmax of L [8][1024][1024], output kept in [k][i] (transposed) layout
// ---------------------------------------------------------------------------
__global__ void col_softmax_T_k(const float* __restrict__ L, float* __restrict__ AT)
{
    int c  = threadIdx.x & 63;
    int kg = threadIdx.x >> 6;
    int i  = blockIdx.x * 64 + c;
    const float* Lb = L  + (long)blockIdx.y * 1048576;
    float*       Ab = AT + (long)blockIdx.y * 1048576;
    __shared__ float red[4][64];

    float m = -3.4e38f;
    for (int k = kg; k < 1024; k += 4) m = fmaxf(m, Lb[(k << 10) + i]);
    red[kg][c] = m;
    __syncthreads();
    m = fmaxf(fmaxf(red[0][c], red[1][c]), fmaxf(red[2][c], red[3][c]));
    __syncthreads();

    float s = 0.f;
    for (int k = kg; k < 1024; k += 4) s += expf(Lb[(k << 10) + i] - m);
    red[kg][c] = s;
    __syncthreads();
    s = red[0][c] + red[1][c] + red[2][c] + red[3][c];
    float inv = 1.f / s;

    for (int k = kg; k < 1024; k += 4)
        Ab[(k << 10) + i] = expf(Lb[(k << 10) + i] - m) * inv;
}

// ---------------------------------------------------------------------------
// Keys cubic kernel, a = -0.5
// ---------------------------------------------------------------------------
__device__ __forceinline__ float keys_cubic(float x)
{
    x = fabsf(x);
    if (x < 1.f) return ((1.5f * x - 2.5f) * x) * x + 1.f;
    if (x < 2.f) return ((-0.5f * x + 2.5f) * x - 4.f) * x + 2.f;
    return 0.f;
}

__global__ void downsample_k(const float* __restrict__ x, float* __restrict__ y)
{
    int idx = blockIdx.x * 256 + threadIdx.x;
    if (idx >= 8 * 64 * 256) return;
    int ox = idx & 15;
    int oy = (idx >> 4) & 15;
    int bc = idx >> 8;

    int jy0 = 2 * oy - 3, jx0 = 2 * ox - 3;
    float wy[8], wx[8];
    float sy = 0.f, sx = 0.f;
#pragma unroll
    for (int t = 0; t < 8; t++) {
        float w = keys_cubic(fabsf(3.5f - t) * 0.5f);
        int jy = jy0 + t;
        wy[t] = (jy >= 0 && jy < 32) ? w : 0.f; sy += wy[t];
        int jx = jx0 + t;
        wx[t] = (jx >= 0 && jx < 32) ? w : 0.f; sx += wx[t];
    }
    float iy = 1.f / sy, ix = 1.f / sx;
#pragma unroll
    for (int t = 0; t < 8; t++) { wy[t] *= iy; wx[t] *= ix; }

    const float* src = x + (long)bc * 1024;
    float acc = 0.f;
#pragma unroll
    for (int t = 0; t < 8; t++) {
        int jy = min(max(jy0 + t, 0), 31);
        float r = 0.f;
#pragma unroll
        for (int u = 0; u < 8; u++) {
            int jx = min(max(jx0 + u, 0), 31);
            r += wx[u] * src[jy * 32 + jx];
        }
        acc += wy[t] * r;
    }
    y[idx] = acc;
}

__global__ void upsample_k(const float* __restrict__ s, float* __restrict__ d)
{
    long idx = (long)blockIdx.x * 256 + threadIdx.x;
    if (idx >= 8ll * 1024 * 1024) return;
    int J = (int)(idx & 1023);
    int I = (int)((idx >> 10) & 1023);
    int b = (int)(idx >> 20);

    int i0, j0;
    float wi[4], wj[4];
    {
        float sf = (I + 0.5f) * 0.25f - 0.5f;
        float fl = floorf(sf);
        float f  = sf - fl;
        int base = (int)fl - 1;
        float tot = 0.f;
#pragma unroll
        for (int t = 0; t < 4; t++) {
            float w = keys_cubic(f + 1.f - t);
            int j = base + t;
            if (j < 0 || j >= 256) w = 0.f;
            wi[t] = w; tot += w;
        }
        float inv = 1.f / tot;
#pragma unroll
        for (int t = 0; t < 4; t++) wi[t] *= inv;
        i0 = base;
    }
    {
        float sf = (J + 0.5f) * 0.25f - 0.5f;
        float fl = floorf(sf);
        float f  = sf - fl;
        int base = (int)fl - 1;
        float tot = 0.f;
#pragma unroll
        for (int t = 0; t < 4; t++) {
            float w = keys_cubic(f + 1.f - t);
            int j = base + t;
            if (j < 0 || j >= 256) w = 0.f;
            wj[t] = w; tot += w;
        }
        float inv = 1.f / tot;
#pragma unroll
        for (int t = 0; t < 4; t++) wj[t] *= inv;
        j0 = base;
    }

    const float* sp = s + (long)b * 65536;
    float acc = 0.f;
#pragma unroll
    for (int t = 0; t < 4; t++) {
        int ii = min(max(i0 + t, 0), 255);
        float r = 0.f;
#pragma unroll
        for (int u = 0; u < 4; u++) {
            int jj = min(max(j0 + u, 0), 255);
            r += wj[u] * sp[ii * 256 + jj];
        }
        acc += wi[t] * r;
    }
    d[idx] = acc;
}

// ---------------------------------------------------------------------------
// BN stats, [B][C][HW] layout
// ---------------------------------------------------------------------------
__global__ void bn_stats_k(const float* __restrict__ T, float* __restrict__ mv)
{
    int c = blockIdx.x;
    int t = threadIdx.x;
    float s = 0.f, s2 = 0.f;
    for (int i = t; i < 8192; i += 256) {
        float v = T[(long)(i >> 10) * 65536 + c * 1024 + (i & 1023)];
        s += v; s2 += v * v;
    }
    __shared__ float sh1[8], sh2[8];
#pragma unroll
    for (int o = 16; o; o >>= 1) {
        s  += __shfl_xor_sync(0xffffffffu, s, o);
        s2 += __shfl_xor_sync(0xffffffffu, s2, o);
    }
    if ((t & 31) == 0) { sh1[t >> 5] = s; sh2[t >> 5] = s2; }
    __syncthreads();
    if (t == 0) {
        float ts = 0.f, ts2 = 0.f;
#pragma unroll
        for (int w = 0; w < 8; w++) { ts += sh1[w]; ts2 += sh2[w]; }
        float mean = ts * (1.f / 8192.f);
        float var  = ts2 * (1.f / 8192.f) - mean * mean;
        mv[c] = mean;
        mv[64 + c] = fmaxf(var, 0.f);
    }
}

// BN stats, transposed [B][HW][C] layout
__global__ void bn_stats_t_k(const float* __restrict__ T, float* __restrict__ mv)
{
    int c = blockIdx.x;
    int t = threadIdx.x;
    float s = 0.f, s2 = 0.f;
    for (int i = t; i < 8192; i += 256) {
        float v = T[(long)(i >> 10) * 65536 + (i & 1023) * 64 + c];
        s += v; s2 += v * v;
    }
    __shared__ float sh1[8], sh2[8];
#pragma unroll
    for (int o = 16; o; o >>= 1) {
        s  += __shfl_xor_sync(0xffffffffu, s, o);
        s2 += __shfl_xor_sync(0xffffffffu, s2, o);
    }
    if ((t & 31) == 0) { sh1[t >> 5] = s; sh2[t >> 5] = s2; }
    __syncthreads();
    if (t == 0) {
        float ts = 0.f, ts2 = 0.f;
#pragma unroll
        for (int w = 0; w < 8; w++) { ts += sh1[w]; ts2 += sh2[w]; }
        float mean = ts * (1.f / 8192.f);
        float var  = ts2 * (1.f / 8192.f) - mean * mean;
        mv[c] = mean;
        mv[64 + c] = fmaxf(var, 0.f);
    }
}

// ---------------------------------------------------------------------------
// Finalize. ch_o in [B][C][HW]; hw_o in transposed [B][HW][C].
// ---------------------------------------------------------------------------
__global__ void finalize_k(const float* __restrict__ x1, const float* __restrict__ x2,
                           const float* __restrict__ ch1o, const float* __restrict__ ch2o,
                           const float* __restrict__ hw1t, const float* __restrict__ hw2t,
                           const float* __restrict__ mv,
                           const float* __restrict__ gamma, const float* __restrict__ beta,
                           float* __restrict__ out)
{
    int idx = blockIdx.x * 256 + threadIdx.x;
    if (idx >= 524288) return;
    int c = (idx >> 10) & 63;
    long hwi = ((long)(idx >> 16)) * 65536 + (long)(idx & 1023) * 64 + c;
    float g = gamma[c], be = beta[c];

    float xa = x1[idx], xb = x2[idx];

    float v, r;
    v = (ch1o[idx] - mv[c])       * rsqrtf(mv[64 + c]  + 1e-5f) * g + be + xa;
    r = fmaxf(v, 0.f);
    v = (hw1t[hwi] - mv[256 + c]) * rsqrtf(mv[320 + c] + 1e-5f) * g + be + xa;
    out[idx] = 0.5f * (r + fmaxf(v, 0.f));

    v = (ch2o[idx] - mv[128 + c]) * rsqrtf(mv[192 + c] + 1e-5f) * g + be + xb;
    r = fmaxf(v, 0.f);
    v = (hw2t[hwi] - mv[384 + c]) * rsqrtf(mv[448 + c] + 1e-5f) * g + be + xb;
    out[524288 + idx] = 0.5f * (r + fmaxf(v, 0.f));
}

// ---------------------------------------------------------------------------
static void launch_gemm(bool ta, bool tb,
                        const float* A, const float* B, float* C, const float* bias,
                        int M, int N, int K, long sA, long sB, long sC, int batch)
{
    dim3 grid((N + 127) / 128, (M + 127) / 128, batch);
    if (!ta && !tb)      gemm_kernel<false, false><<<grid, 256>>>(A, B, C, bias, M, N, K, sA, sB, sC);
    else if (!ta && tb)  gemm_kernel<false, true ><<<grid, 256>>>(A, B, C, bias, M, N, K, sA, sB, sC);
    else if (ta && !tb)  gemm_kernel<true,  false><<<grid, 256>>>(A, B, C, bias, M, N, K, sA, sB, sC);
    else                 gemm_kernel<true,  true ><<<grid, 256>>>(A, B, C, bias, M, N, K, sA, sB, sC);
}

extern "C" void kernel_launch(void* const* d_in, const int* in_sizes, int n_in,
                              void* d_out, int out_size)
{
    const float* x1     = (const float*)d_in[0];
    const float* x2     = (const float*)d_in[1];
    const float* w_down = (const float*)d_in[2];
    const float* b_down = (const float*)d_in[3];
    const float* w_up   = (const float*)d_in[4];
    const float* b_up   = (const float*)d_in[5];
    const float* gamma  = (const float*)d_in[6];
    const float* beta   = (const float*)d_in[7];
    float* out = (float*)d_out;

    float* base = nullptr;
    cudaGetSymbolAddress((void**)&base, g_buf);

    float* X1F  = base + 0 * M8;
    float* X2F  = base + 1 * M8;
    float* LB   = base + 2 * M8;
    float* A12  = base + 3 * M8;
    float* A21T = base + 4 * M8;
    float* UP1  = base + 5 * M8;
    float* UP2  = base + 6 * M8;
    float* HW1  = X1F;   // reuse (dead after LB gemm)
    float* HW2  = X2F;   // reuse

    float* S = base + 7 * M8;
    float* XD1   = S; S += 262144;
    float* XD2   = S; S += 262144;
    float* X1C   = S; S += 32768;
    float* X2C   = S; S += 32768;
    float* X1CD  = S; S += 8192;
    float* X2CD  = S; S += 8192;
    float* LC    = S; S += 32768;
    float* AC12  = S; S += 32768;
    float* AC21  = S; S += 32768;
    float* LCD   = S; S += 8192;
    float* ACD12 = S; S += 8192;
    float* ACD21 = S; S += 8192;
    float* TT    = S; S += 16384;
    float* U1T   = S; S += 32768;
    float* U2T   = S; S += 32768;
    float* CH1   = S; S += 32768;
    float* CH2   = S; S += 32768;
    float* CH1O  = S; S += 524288;
    float* CH2O  = S; S += 524288;
    float* XDN1  = S; S += 131072;
    float* XDN2  = S; S += 131072;
    float* X1FD  = S; S += 524288;
    float* X2FD  = S; S += 524288;
    float* LFD   = S; S += 524288;
    float* AFD12 = S; S += 524288;
    float* AFD21 = S; S += 524288;
    float* HW1OT = S; S += 524288;
    float* HW2OT = S; S += 524288;
    float* MV    = S; S += 512;

    // ===================== channel path (small, FFMA) =====================
    launch_gemm(false, true, x1, x1, X1C, nullptr, 64, 64, 1024, 65536, 65536, 4096, 8);
    launch_gemm(false, true, x2, x2, X2C, nullptr, 64, 64, 1024, 65536, 65536, 4096, 8);
    launch_gemm(false, false, w_down, x1, XD1, b_down, 32, 1024, 64, 0, 65536, 32768, 8);
    launch_gemm(false, false, w_down, x2, XD2, b_down, 32, 1024, 64, 0, 65536, 32768, 8);
    launch_gemm(false, true, XD1, XD1, X1CD, nullptr, 32, 32, 1024, 32768, 32768, 1024, 8);
    launch_gemm(false, true, XD2, XD2, X2CD, nullptr, 32, 32, 1024, 32768, 32768, 1024, 8);
    launch_gemm(false, true, X1C, X2C, LC, nullptr, 64, 64, 64, 4096, 4096, 4096, 8);
    row_softmax_k<<<512, 256>>>(LC, AC12, 64);
    launch_gemm(false, true, X2C, X1C, LC, nullptr, 64, 64, 64, 4096, 4096, 4096, 8);
    row_softmax_k<<<512, 256>>>(LC, AC21, 64);
    launch_gemm(false, true, X1CD, X2CD, LCD, nullptr, 32, 32, 32, 1024, 1024, 1024, 8);
    row_softmax_k<<<256, 256>>>(LCD, ACD12, 32);
    launch_gemm(false, true, X2CD, X1CD, LCD, nullptr, 32, 32, 32, 1024, 1024, 1024, 8);
    row_softmax_k<<<256, 256>>>(LCD, ACD21, 32);
    launch_gemm(false, false, w_up, ACD12, TT, b_up, 64, 32, 32, 0, 1024, 2048, 8);
    launch_gemm(false, true,  w_up, TT, U1T, b_up, 64, 64, 32, 0, 2048, 4096, 8);
    launch_gemm(false, false, w_up, ACD21, TT, b_up, 64, 32, 32, 0, 1024, 2048, 8);
    launch_gemm(false, true,  w_up, TT, U2T, b_up, 64, 64, 32, 0, 2048, 4096, 8);
    launch_gemm(false, true, AC12, U1T, CH1, nullptr, 64, 64, 64, 4096, 4096, 4096, 8);
    launch_gemm(false, true, AC21, U2T, CH2, nullptr, 64, 64, 64, 4096, 4096, 4096, 8);
    launch_gemm(false, false, CH1, x1, CH1O, nullptr, 64, 1024, 64, 4096, 65536, 65536, 8);
    launch_gemm(false, false, CH2, x2, CH2O, nullptr, 64, 1024, 64, 4096, 65536, 65536, 8);

    // ===================== feature path (tensor cores, 3xTF32) =====================
    launch_tgemm(1, 1, x1, x1, X1F, 1024, 1024, 64, 1024, 1024, 1024, 65536, 65536, 1048576, 8);
    launch_tgemm(1, 1, x2, x2, X2F, 1024, 1024, 64, 1024, 1024, 1024, 65536, 65536, 1048576, 8);
    downsample_k<<<512, 256>>>(x1, XDN1);
    downsample_k<<<512, 256>>>(x2, XDN2);
    launch_tgemm(1, 1, XDN1, XDN1, X1FD, 256, 256, 64, 256, 256, 256, 16384, 16384, 65536, 8);
    launch_tgemm(1, 1, XDN2, XDN2, X2FD, 256, 256, 64, 256, 256, 256, 16384, 16384, 65536, 8);
    launch_tgemm(0, 0, X1FD, X2FD, LFD, 256, 256, 256, 256, 256, 256, 65536, 65536, 65536, 8);
    row_softmax_k<<<2048, 256>>>(LFD, AFD12, 256);
    launch_tgemm(0, 0, X2FD, X1FD, LFD, 256, 256, 256, 256, 256, 256, 65536, 65536, 65536, 8);
    row_softmax_k<<<2048, 256>>>(LFD, AFD21, 256);
    upsample_k<<<32768, 256>>>(AFD12, UP1);
    upsample_k<<<32768, 256>>>(AFD21, UP2);
    launch_tgemm(0, 0, X1F, X2F, LB, 1024, 1024, 1024, 1024, 1024, 1024, 1048576, 1048576, 1048576, 8);
    row_softmax_k<<<8192, 256>>>(LB, A12, 1024);
    {
        dim3 g(16, 8);
        col_softmax_T_k<<<g, 256>>>(LB, A21T);
    }
    launch_tgemm(0, 1, A12,  UP1, HW1, 1024, 1024, 1024, 1024, 1024, 1024, 1048576, 1048576, 1048576, 8);
    launch_tgemm(1, 1, A21T, UP2, HW2, 1024, 1024, 1024, 1024, 1024, 1024, 1048576, 1048576, 1048576, 8);
    launch_tgemm(0, 0, HW1, x1, HW1OT, 1024, 64, 1024, 1024, 1024, 64, 1048576, 65536, 65536, 8);
    launch_tgemm(0, 0, HW2, x2, HW2OT, 1024, 64, 1024, 1024, 1024, 64, 1048576, 65536, 65536, 8);

    // ===================== BN + residual + relu + average =====================
    bn_stats_k<<<64, 256>>>(CH1O, MV);
    bn_stats_k<<<64, 256>>>(CH2O, MV + 128);
    bn_stats_t_k<<<64, 256>>>(HW1OT, MV + 256);
    bn_stats_t_k<<<64, 256>>>(HW2OT, MV + 384);
    finalize_k<<<2048, 256>>>(x1, x2, CH1O, CH2O, HW1OT, HW2OT, MV, gamma, beta, out);
}

// round 6
// speedup vs baseline: 1.7622x; 1.7499x over previous
#include <cuda_runtime.h>
#include <math.h>

// ---------------------------------------------------------------------------
// Problem constants: B=8, C=64, H=W=32, HW=1024, D=32
// Rank-64 factorization: L = x1^T (x1 x2^T) x2 ; hw1o^T = A12 (UP1 x1^T), etc.
// ---------------------------------------------------------------------------
static constexpr long M8 = 8ll * 1024 * 1024;

__device__ float g_buf[68ll * 1024 * 1024];

// ===========================================================================
// FFMA batched SGEMM: C[b] (MxN) = opA(A[b]) * opB(B[b]) (+ bias[m])
//   TA=false: A is [M][K]; TA=true: A is [K][M] (lda=M)
//   TB=false: B is [K][N]; TB=true:  B is [N][K] (C = A*B^T)
// Tile 128x128, KT=16, 256 threads, 8x8 microtile. K%16==0, M,N%8==0.
// ===========================================================================
template <bool TA, bool TB>
__global__ void __launch_bounds__(256, 2)
gemm_kernel(const float* __restrict__ A, const float* __restrict__ B,
            float* __restrict__ Cmat, const float* __restrict__ bias,
            int M, int N, int K, long sA, long sB, long sC)
{
    __shared__ float As[16][128];
    __shared__ float Bs[16][128];

    const int tid = threadIdx.x;
    const int m0 = blockIdx.y * 128;
    const int n0 = blockIdx.x * 128;
    const float* Ab = A + (long)blockIdx.z * sA;
    const float* Bb = B + (long)blockIdx.z * sB;
    float* Cb = Cmat + (long)blockIdx.z * sC;

    float acc[8][8];
#pragma unroll
    for (int i = 0; i < 8; i++)
#pragma unroll
        for (int j = 0; j < 8; j++) acc[i][j] = 0.f;

    const int rowt = (tid >> 4) * 8;
    const int colt = (tid & 15) * 8;

    for (int k0 = 0; k0 < K; k0 += 16) {
        if (!TA) {
            int ar = tid >> 1;
            int ac = (tid & 1) * 8;
            float4 v0 = {0.f,0.f,0.f,0.f}, v1 = {0.f,0.f,0.f,0.f};
            if (m0 + ar < M) {
                const float* p = Ab + (long)(m0 + ar) * K + k0 + ac;
                v0 = *(const float4*)p;
                v1 = *(const float4*)(p + 4);
            }
            As[ac+0][ar] = v0.x; As[ac+1][ar] = v0.y; As[ac+2][ar] = v0.z; As[ac+3][ar] = v0.w;
            As[ac+4][ar] = v1.x; As[ac+5][ar] = v1.y; As[ac+6][ar] = v1.z; As[ac+7][ar] = v1.w;
        } else {
            int kr = tid >> 4;
            int mc = (tid & 15) * 8;
            float4 v0 = {0.f,0.f,0.f,0.f}, v1 = {0.f,0.f,0.f,0.f};
            if (m0 + mc < M) {
                const float* p = Ab + (long)(k0 + kr) * M + m0 + mc;
                v0 = *(const float4*)p;
                v1 = *(const float4*)(p + 4);
            }
            *(float4*)&As[kr][mc]     = v0;
            *(float4*)&As[kr][mc + 4] = v1;
        }
        if (TB) {
            int br = tid >> 1;
            int bc = (tid & 1) * 8;
            float4 v0 = {0.f,0.f,0.f,0.f}, v1 = {0.f,0.f,0.f,0.f};
            if (n0 + br < N) {
                const float* p = Bb + (long)(n0 + br) * K + k0 + bc;
                v0 = *(const float4*)p;
                v1 = *(const float4*)(p + 4);
            }
            Bs[bc+0][br] = v0.x; Bs[bc+1][br] = v0.y; Bs[bc+2][br] = v0.z; Bs[bc+3][br] = v0.w;
            Bs[bc+4][br] = v1.x; Bs[bc+5][br] = v1.y; Bs[bc+6][br] = v1.z; Bs[bc+7][br] = v1.w;
        } else {
            int kr = tid >> 4;
            int nc = (tid & 15) * 8;
            float4 v0 = {0.f,0.f,0.f,0.f}, v1 = {0.f,0.f,0.f,0.f};
            if (n0 + nc < N) {
                const float* p = Bb + (long)(k0 + kr) * N + n0 + nc;
                v0 = *(const float4*)p;
                v1 = *(const float4*)(p + 4);
            }
            *(float4*)&Bs[kr][nc]     = v0;
            *(float4*)&Bs[kr][nc + 4] = v1;
        }
        __syncthreads();

#pragma unroll
        for (int kk = 0; kk < 16; kk++) {
            float4 a0 = *(const float4*)&As[kk][rowt];
            float4 a1 = *(const float4*)&As[kk][rowt + 4];
            float4 b0 = *(const float4*)&Bs[kk][colt];
            float4 b1 = *(const float4*)&Bs[kk][colt + 4];
            float ra[8] = {a0.x,a0.y,a0.z,a0.w,a1.x,a1.y,a1.z,a1.w};
            float rb[8] = {b0.x,b0.y,b0.z,b0.w,b1.x,b1.y,b1.z,b1.w};
#pragma unroll
            for (int i = 0; i < 8; i++)
#pragma unroll
                for (int j = 0; j < 8; j++)
                    acc[i][j] += ra[i] * rb[j];
        }
        __syncthreads();
    }

#pragma unroll
    for (int i = 0; i < 8; i++) {
        int m = m0 + rowt + i;
        if (m < M) {
            float bv = bias ? bias[m] : 0.f;
            int n = n0 + colt;
            if (n < N) {
                float4 o0 = make_float4(acc[i][0]+bv, acc[i][1]+bv, acc[i][2]+bv, acc[i][3]+bv);
                float4 o1 = make_float4(acc[i][4]+bv, acc[i][5]+bv, acc[i][6]+bv, acc[i][7]+bv);
                float* cp = Cb + (long)m * N + n;
                *(float4*)cp       = o0;
                *(float4*)(cp + 4) = o1;
            }
        }
    }
}

// ---------------------------------------------------------------------------
// Row softmax
// ---------------------------------------------------------------------------
__global__ void row_softmax_k(const float* __restrict__ L, float* __restrict__ A, int N)
{
    long row = blockIdx.x;
    const float* p = L + row * (long)N;
    float* q = A + row * (long)N;
    int t = threadIdx.x;
    __shared__ float sh[8];

    float m = -3.4e38f;
    for (int i = t; i < N; i += 256) m = fmaxf(m, p[i]);
#pragma unroll
    for (int o = 16; o; o >>= 1) m = fmaxf(m, __shfl_xor_sync(0xffffffffu, m, o));
    if ((t & 31) == 0) sh[t >> 5] = m;
    __syncthreads();
    float mm = sh[0];
#pragma unroll
    for (int w = 1; w < 8; w++) mm = fmaxf(mm, sh[w]);
    __syncthreads();

    float s = 0.f;
    for (int i = t; i < N; i += 256) s += expf(p[i] - mm);
#pragma unroll
    for (int o = 16; o; o >>= 1) s += __shfl_xor_sync(0xffffffffu, s, o);
    if ((t & 31) == 0) sh[t >> 5] = s;
    __syncthreads();
    float ss = 0.f;
#pragma unroll
    for (int w = 0; w < 8; w++) ss += sh[w];
    float inv = 1.f / ss;

    for (int i = t; i < N; i += 256) q[i] = expf(p[i] - mm) * inv;
}

// ---------------------------------------------------------------------------
// Column softmax of L [8][1024][1024], output in [k][i] (transposed) layout
// ---------------------------------------------------------------------------
__global__ void col_softmax_T_k(const float* __restrict__ L, float* __restrict__ AT)
{
    int c  = threadIdx.x & 63;
    int kg = threadIdx.x >> 6;
    int i  = blockIdx.x * 64 + c;
    const float* Lb = L  + (long)blockIdx.y * 1048576;
    float*       Ab = AT + (long)blockIdx.y * 1048576;
    __shared__ float red[4][64];

    float m = -3.4e38f;
    for (int k = kg; k < 1024; k += 4) m = fmaxf(m, Lb[(k << 10) + i]);
    red[kg][c] = m;
    __syncthreads();
    m = fmaxf(fmaxf(red[0][c], red[1][c]), fmaxf(red[2][c], red[3][c]));
    __syncthreads();

    float s = 0.f;
    for (int k = kg; k < 1024; k += 4) s += expf(Lb[(k << 10) + i] - m);
    red[kg][c] = s;
    __syncthreads();
    s = red[0][c] + red[1][c] + red[2][c] + red[3][c];
    float inv = 1.f / s;

    for (int k = kg; k < 1024; k += 4)
        Ab[(k << 10) + i] = expf(Lb[(k << 10) + i] - m) * inv;
}

// ---------------------------------------------------------------------------
// Keys cubic kernel, a = -0.5
// ---------------------------------------------------------------------------
__device__ __forceinline__ float keys_cubic(float x)
{
    x = fabsf(x);
    if (x < 1.f) return ((1.5f * x - 2.5f) * x) * x + 1.f;
    if (x < 2.f) return ((-0.5f * x + 2.5f) * x - 4.f) * x + 2.f;
    return 0.f;
}

// Bicubic downsample by 2 (antialias, 8 taps, edge-renormalized): [8,64,32,32]->[8,64,16,16]
__global__ void downsample_k(const float* __restrict__ x, float* __restrict__ y)
{
    int idx = blockIdx.x * 256 + threadIdx.x;
    if (idx >= 8 * 64 * 256) return;
    int ox = idx & 15;
    int oy = (idx >> 4) & 15;
    int bc = idx >> 8;

    int jy0 = 2 * oy - 3, jx0 = 2 * ox - 3;
    float wy[8], wx[8];
    float sy = 0.f, sx = 0.f;
#pragma unroll
    for (int t = 0; t < 8; t++) {
        float w = keys_cubic(fabsf(3.5f - t) * 0.5f);
        int jy = jy0 + t;
        wy[t] = (jy >= 0 && jy < 32) ? w : 0.f; sy += wy[t];
        int jx = jx0 + t;
        wx[t] = (jx >= 0 && jx < 32) ? w : 0.f; sx += wx[t];
    }
    float iy = 1.f / sy, ix = 1.f / sx;
#pragma unroll
    for (int t = 0; t < 8; t++) { wy[t] *= iy; wx[t] *= ix; }

    const float* src = x + (long)bc * 1024;
    float acc = 0.f;
#pragma unroll
    for (int t = 0; t < 8; t++) {
        int jy = min(max(jy0 + t, 0), 31);
        float r = 0.f;
#pragma unroll
        for (int u = 0; u < 8; u++) {
            int jx = min(max(jx0 + u, 0), 31);
            r += wx[u] * src[jy * 32 + jx];
        }
        acc += wy[t] * r;
    }
    y[idx] = acc;
}

// Bicubic upsample x4 (4 taps/dim): [8,256,256] -> [8,1024,1024]
__global__ void upsample_k(const float* __restrict__ s, float* __restrict__ d)
{
    long idx = (long)blockIdx.x * 256 + threadIdx.x;
    if (idx >= 8ll * 1024 * 1024) return;
    int J = (int)(idx & 1023);
    int I = (int)((idx >> 10) & 1023);
    int b = (int)(idx >> 20);

    int i0, j0;
    float wi[4], wj[4];
    {
        float sf = (I + 0.5f) * 0.25f - 0.5f;
        float fl = floorf(sf);
        float f  = sf - fl;
        int base = (int)fl - 1;
        float tot = 0.f;
#pragma unroll
        for (int t = 0; t < 4; t++) {
            float w = keys_cubic(f + 1.f - t);
            int j = base + t;
            if (j < 0 || j >= 256) w = 0.f;
            wi[t] = w; tot += w;
        }
        float inv = 1.f / tot;
#pragma unroll
        for (int t = 0; t < 4; t++) wi[t] *= inv;
        i0 = base;
    }
    {
        float sf = (J + 0.5f) * 0.25f - 0.5f;
        float fl = floorf(sf);
        float f  = sf - fl;
        int base = (int)fl - 1;
        float tot = 0.f;
#pragma unroll
        for (int t = 0; t < 4; t++) {
            float w = keys_cubic(f + 1.f - t);
            int j = base + t;
            if (j < 0 || j >= 256) w = 0.f;
            wj[t] = w; tot += w;
        }
        float inv = 1.f / tot;
#pragma unroll
        for (int t = 0; t < 4; t++) wj[t] *= inv;
        j0 = base;
    }

    const float* sp = s + (long)b * 65536;
    float acc = 0.f;
#pragma unroll
    for (int t = 0; t < 4; t++) {
        int ii = min(max(i0 + t, 0), 255);
        float r = 0.f;
#pragma unroll
        for (int u = 0; u < 4; u++) {
            int jj = min(max(j0 + u, 0), 255);
            r += wj[u] * sp[ii * 256 + jj];
        }
        acc += wi[t] * r;
    }
    d[idx] = acc;
}

// ---------------------------------------------------------------------------
// BN stats, [B][C][HW] layout
// ---------------------------------------------------------------------------
__global__ void bn_stats_k(const float* __restrict__ T, float* __restrict__ mv)
{
    int c = blockIdx.x;
    int t = threadIdx.x;
    float s = 0.f, s2 = 0.f;
    for (int i = t; i < 8192; i += 256) {
        float v = T[(long)(i >> 10) * 65536 + c * 1024 + (i & 1023)];
        s += v; s2 += v * v;
    }
    __shared__ float sh1[8], sh2[8];
#pragma unroll
    for (int o = 16; o; o >>= 1) {
        s  += __shfl_xor_sync(0xffffffffu, s, o);
        s2 += __shfl_xor_sync(0xffffffffu, s2, o);
    }
    if ((t & 31) == 0) { sh1[t >> 5] = s; sh2[t >> 5] = s2; }
    __syncthreads();
    if (t == 0) {
        float ts = 0.f, ts2 = 0.f;
#pragma unroll
        for (int w = 0; w < 8; w++) { ts += sh1[w]; ts2 += sh2[w]; }
        float mean = ts * (1.f / 8192.f);
        float var  = ts2 * (1.f / 8192.f) - mean * mean;
        mv[c] = mean;
        mv[64 + c] = fmaxf(var, 0.f);
    }
}

// BN stats, transposed [B][HW][C] layout
__global__ void bn_stats_t_k(const float* __restrict__ T, float* __restrict__ mv)
{
    int c = blockIdx.x;
    int t = threadIdx.x;
    float s = 0.f, s2 = 0.f;
    for (int i = t; i < 8192; i += 256) {
        float v = T[(long)(i >> 10) * 65536 + (i & 1023) * 64 + c];
        s += v; s2 += v * v;
    }
    __shared__ float sh1[8], sh2[8];
#pragma unroll
    for (int o = 16; o; o >>= 1) {
        s  += __shfl_xor_sync(0xffffffffu, s, o);
        s2 += __shfl_xor_sync(0xffffffffu, s2, o);
    }
    if ((t & 31) == 0) { sh1[t >> 5] = s; sh2[t >> 5] = s2; }
    __syncthreads();
    if (t == 0) {
        float ts = 0.f, ts2 = 0.f;
#pragma unroll
        for (int w = 0; w < 8; w++) { ts += sh1[w]; ts2 += sh2[w]; }
        float mean = ts * (1.f / 8192.f);
        float var  = ts2 * (1.f / 8192.f) - mean * mean;
        mv[c] = mean;
        mv[64 + c] = fmaxf(var, 0.f);
    }
}

// ---------------------------------------------------------------------------
// Finalize. ch_o in [B][C][HW]; hw_o in transposed [B][HW][C].
// ---------------------------------------------------------------------------
__global__ void finalize_k(const float* __restrict__ x1, const float* __restrict__ x2,
                           const float* __restrict__ ch1o, const float* __restrict__ ch2o,
                           const float* __restrict__ hw1t, const float* __restrict__ hw2t,
                           const float* __restrict__ mv,
                           const float* __restrict__ gamma, const float* __restrict__ beta,
                           float* __restrict__ out)
{
    int idx = blockIdx.x * 256 + threadIdx.x;
    if (idx >= 524288) return;
    int c = (idx >> 10) & 63;
    long hwi = ((long)(idx >> 16)) * 65536 + (long)(idx & 1023) * 64 + c;
    float g = gamma[c], be = beta[c];

    float xa = x1[idx], xb = x2[idx];

    float v, r;
    v = (ch1o[idx] - mv[c])       * rsqrtf(mv[64 + c]  + 1e-5f) * g + be + xa;
    r = fmaxf(v, 0.f);
    v = (hw1t[hwi] - mv[256 + c]) * rsqrtf(mv[320 + c] + 1e-5f) * g + be + xa;
    out[idx] = 0.5f * (r + fmaxf(v, 0.f));

    v = (ch2o[idx] - mv[128 + c]) * rsqrtf(mv[192 + c] + 1e-5f) * g + be + xb;
    r = fmaxf(v, 0.f);
    v = (hw2t[hwi] - mv[384 + c]) * rsqrtf(mv[448 + c] + 1e-5f) * g + be + xb;
    out[524288 + idx] = 0.5f * (r + fmaxf(v, 0.f));
}

// ---------------------------------------------------------------------------
static void launch_gemm(bool ta, bool tb,
                        const float* A, const float* B, float* C, const float* bias,
                        int M, int N, int K, long sA, long sB, long sC, int batch)
{
    dim3 grid((N + 127) / 128, (M + 127) / 128, batch);
    if (!ta && !tb)      gemm_kernel<false, false><<<grid, 256>>>(A, B, C, bias, M, N, K, sA, sB, sC);
    else if (!ta && tb)  gemm_kernel<false, true ><<<grid, 256>>>(A, B, C, bias, M, N, K, sA, sB, sC);
    else if (ta && !tb)  gemm_kernel<true,  false><<<grid, 256>>>(A, B, C, bias, M, N, K, sA, sB, sC);
    else                 gemm_kernel<true,  true ><<<grid, 256>>>(A, B, C, bias, M, N, K, sA, sB, sC);
}

extern "C" void kernel_launch(void* const* d_in, const int* in_sizes, int n_in,
                              void* d_out, int out_size)
{
    const float* x1     = (const float*)d_in[0];   // [8,64,1024]
    const float* x2     = (const float*)d_in[1];
    const float* w_down = (const float*)d_in[2];   // [32,64]
    const float* b_down = (const float*)d_in[3];   // [32]
    const float* w_up   = (const float*)d_in[4];   // [64,32]
    const float* b_up   = (const float*)d_in[5];   // [64]
    const float* gamma  = (const float*)d_in[6];   // [64]
    const float* beta   = (const float*)d_in[7];   // [64]
    float* out = (float*)d_out;

    float* base = nullptr;
    cudaGetSymbolAddress((void**)&base, g_buf);

    // Big [8M] buffers (only 5 now — no X1F/X2F/HW1/HW2)
    float* LB   = base + 0 * M8;
    float* A12  = base + 1 * M8;
    float* A21T = base + 2 * M8;
    float* UP1  = base + 3 * M8;
    float* UP2  = base + 4 * M8;

    float* S = base + 5 * M8;
    float* XD1   = S; S += 262144;   // [8,32,1024]
    float* XD2   = S; S += 262144;
    float* X1C   = S; S += 32768;
    float* X2C   = S; S += 32768;
    float* X1CD  = S; S += 8192;
    float* X2CD  = S; S += 8192;
    float* LC    = S; S += 32768;
    float* AC12  = S; S += 32768;
    float* AC21  = S; S += 32768;
    float* LCD   = S; S += 8192;
    float* ACD12 = S; S += 8192;
    float* ACD21 = S; S += 8192;
    float* TT    = S; S += 16384;
    float* U1T   = S; S += 32768;
    float* U2T   = S; S += 32768;
    float* CH1   = S; S += 32768;
    float* CH2   = S; S += 32768;
    float* CH1O  = S; S += 524288;   // [8,64,1024]
    float* CH2O  = S; S += 524288;
    float* XDN1  = S; S += 131072;   // [8,64,256]
    float* XDN2  = S; S += 131072;
    float* G12   = S; S += 32768;    // [8,64,64]  x1 x2^T
    float* PP    = S; S += 524288;   // [8,64,1024] G @ x2
    float* GD    = S; S += 32768;    // [8,64,64]
    float* PD    = S; S += 131072;   // [8,64,256]
    float* LFD   = S; S += 524288;   // [8,256,256]
    float* AFD12 = S; S += 524288;
    float* AFD21 = S; S += 524288;
    float* W1    = S; S += 524288;   // [8,1024,64] UP1 @ x1^T
    float* W2    = S; S += 524288;
    float* HW1OT = S; S += 524288;   // [8,1024,64]
    float* HW2OT = S; S += 524288;
    float* MV    = S; S += 512;

    // ===================== channel path (small, FFMA) =====================
    launch_gemm(false, true, x1, x1, X1C, nullptr, 64, 64, 1024, 65536, 65536, 4096, 8);
    launch_gemm(false, true, x2, x2, X2C, nullptr, 64, 64, 1024, 65536, 65536, 4096, 8);
    launch_gemm(false, false, w_down, x1, XD1, b_down, 32, 1024, 64, 0, 65536, 32768, 8);
    launch_gemm(false, false, w_down, x2, XD2, b_down, 32, 1024, 64, 0, 65536, 32768, 8);
    launch_gemm(false, true, XD1, XD1, X1CD, nullptr, 32, 32, 1024, 32768, 32768, 1024, 8);
    launch_gemm(false, true, XD2, XD2, X2CD, nullptr, 32, 32, 1024, 32768, 32768, 1024, 8);
    launch_gemm(false, true, X1C, X2C, LC, nullptr, 64, 64, 64, 4096, 4096, 4096, 8);
    row_softmax_k<<<512, 256>>>(LC, AC12, 64);
    launch_gemm(false, true, X2C, X1C, LC, nullptr, 64, 64, 64, 4096, 4096, 4096, 8);
    row_softmax_k<<<512, 256>>>(LC, AC21, 64);
    launch_gemm(false, true, X1CD, X2CD, LCD, nullptr, 32, 32, 32, 1024, 1024, 1024, 8);
    row_softmax_k<<<256, 256>>>(LCD, ACD12, 32);
    launch_gemm(false, true, X2CD, X1CD, LCD, nullptr, 32, 32, 32, 1024, 1024, 1024, 8);
    row_softmax_k<<<256, 256>>>(LCD, ACD21, 32);
    launch_gemm(false, false, w_up, ACD12, TT, b_up, 64, 32, 32, 0, 1024, 2048, 8);
    launch_gemm(false, true,  w_up, TT, U1T, b_up, 64, 64, 32, 0, 2048, 4096, 8);
    launch_gemm(false, false, w_up, ACD21, TT, b_up, 64, 32, 32, 0, 1024, 2048, 8);
    launch_gemm(false, true,  w_up, TT, U2T, b_up, 64, 64, 32, 0, 2048, 4096, 8);
    launch_gemm(false, true, AC12, U1T, CH1, nullptr, 64, 64, 64, 4096, 4096, 4096, 8);
    launch_gemm(false, true, AC21, U2T, CH2, nullptr, 64, 64, 64, 4096, 4096, 4096, 8);
    launch_gemm(false, false, CH1, x1, CH1O, nullptr, 64, 1024, 64, 4096, 65536, 65536, 8);
    launch_gemm(false, false, CH2, x2, CH2O, nullptr, 64, 1024, 64, 4096, 65536, 65536, 8);

    // ============ feature path via rank-64 factorization (all FFMA) ============
    // L = x1^T (x1 x2^T) x2   — feature grams never materialized
    launch_gemm(false, true,  x1, x2, G12, nullptr, 64, 64, 1024, 65536, 65536, 4096, 8);
    launch_gemm(false, false, G12, x2, PP,  nullptr, 64, 1024, 64, 4096, 65536, 65536, 8);
    launch_gemm(true,  false, x1, PP, LB,   nullptr, 1024, 1024, 64, 65536, 65536, 1048576, 8);
    row_softmax_k<<<8192, 256>>>(LB, A12, 1024);
    {
        dim3 g(16, 8);
        col_softmax_T_k<<<g, 256>>>(LB, A21T);   // attn(x2f,x1f), stored [k][i]
    }

    // downsampled logits, both directions, same factorization
    downsample_k<<<512, 256>>>(x1, XDN1);
    downsample_k<<<512, 256>>>(x2, XDN2);
    // LFD  = xd1^T (xd1 xd2^T) xd2
    launch_gemm(false, true,  XDN1, XDN2, GD, nullptr, 64, 64, 256, 16384, 16384, 4096, 8);
    launch_gemm(false, false, GD, XDN2, PD,   nullptr, 64, 256, 64, 4096, 16384, 16384, 8);
    launch_gemm(true,  false, XDN1, PD, LFD,  nullptr, 256, 256, 64, 16384, 16384, 65536, 8);
    row_softmax_k<<<2048, 256>>>(LFD, AFD12, 256);
    // LFD2 = xd2^T (xd2 xd1^T) xd1
    launch_gemm(false, true,  XDN2, XDN1, GD, nullptr, 64, 64, 256, 16384, 16384, 4096, 8);
    launch_gemm(false, false, GD, XDN1, PD,   nullptr, 64, 256, 64, 4096, 16384, 16384, 8);
    launch_gemm(true,  false, XDN2, PD, LFD,  nullptr, 256, 256, 64, 16384, 16384, 65536, 8);
    row_softmax_k<<<2048, 256>>>(LFD, AFD21, 256);

    // upsample attention maps
    upsample_k<<<32768, 256>>>(AFD12, UP1);
    upsample_k<<<32768, 256>>>(AFD21, UP2);

    // hw outputs without materializing HW:
    //   W1 = UP1 @ x1^T  [8,1024,64];  hw1o^T = A12 @ W1
    launch_gemm(false, true,  UP1, x1, W1, nullptr, 1024, 64, 1024, 1048576, 65536, 65536, 8);
    launch_gemm(false, true,  UP2, x2, W2, nullptr, 1024, 64, 1024, 1048576, 65536, 65536, 8);
    launch_gemm(false, false, A12,  W1, HW1OT, nullptr, 1024, 64, 1024, 1048576, 65536, 65536, 8);
    launch_gemm(true,  false, A21T, W2, HW2OT, nullptr, 1024, 64, 1024, 1048576, 65536, 65536, 8);

    // ===================== BN + residual + relu + average =====================
    bn_stats_k<<<64, 256>>>(CH1O, MV);
    bn_stats_k<<<64, 256>>>(CH2O, MV + 128);
    bn_stats_t_k<<<64, 256>>>(HW1OT, MV + 256);
    bn_stats_t_k<<<64, 256>>>(HW2OT, MV + 384);
    finalize_k<<<2048, 256>>>(x1, x2, CH1O, CH2O, HW1OT, HW2OT, MV, gamma, beta, out);
}

// round 7
// speedup vs baseline: 6.2891x; 3.5689x over previous
#include <cuda_runtime.h>
#include <math.h>

// ---------------------------------------------------------------------------
// B=8, C=64, HW=1024, D=32.
// Rank-64 factorization:  L = x1^T (x1 x2^T) x2  (feature grams never built)
// Upsample linearity:     UP = U A U^T  =>  W = UP x^T = U (A (xU)^T)
// Fused attention:        HW1OT = rowsoftmax(L) @ W1 ; HW2OT = colsoftmax(L)^T @ W2
// ---------------------------------------------------------------------------
__device__ float g_buf[17ll * 1024 * 1024];

// ===========================================================================
// gemm64: C[b](MxN) = opA(A[b]) * opB(B[b]) (+bias[m]); tile 64x64, KT=16,
// 256 threads, 4x4 microtile. K%16==0, M,N%4==0.
//  TA=0: A [M][K] ; TA=1: A [K][M] (stride M)
//  TB=0: B [K][N] ; TB=1: B [N][K] (C = A B^T)
// ===========================================================================
template <bool TA, bool TB>
__global__ void __launch_bounds__(256)
gemm64_kernel(const float* __restrict__ A, const float* __restrict__ B,
              float* __restrict__ C, const float* __restrict__ bias,
              int M, int N, int K, long sA, long sB, long sC)
{
    __shared__ float As[16][68];
    __shared__ float Bs[16][68];
    const int tid = threadIdx.x;
    const int m0 = blockIdx.y * 64, n0 = blockIdx.x * 64;
    const float* Ab = A + (long)blockIdx.z * sA;
    const float* Bb = B + (long)blockIdx.z * sB;
    float* Cb = C + (long)blockIdx.z * sC;
    const int rowt = (tid >> 4) * 4, colt = (tid & 15) * 4;
    float acc[4][4] = {};

    for (int k0 = 0; k0 < K; k0 += 16) {
        float4 av = {0,0,0,0}, bv = {0,0,0,0};
        if (!TA) {
            int r = tid >> 2, c = (tid & 3) * 4;
            if (m0 + r < M) av = *(const float4*)(Ab + (long)(m0 + r) * K + k0 + c);
            As[c+0][r]=av.x; As[c+1][r]=av.y; As[c+2][r]=av.z; As[c+3][r]=av.w;
        } else {
            int kr = tid >> 4, mc = (tid & 15) * 4;
            if (m0 + mc < M) av = *(const float4*)(Ab + (long)(k0 + kr) * M + m0 + mc);
            *(float4*)&As[kr][mc] = av;
        }
        if (!TB) {
            int kr = tid >> 4, nc = (tid & 15) * 4;
            if (n0 + nc < N) bv = *(const float4*)(Bb + (long)(k0 + kr) * N + n0 + nc);
            *(float4*)&Bs[kr][nc] = bv;
        } else {
            int r = tid >> 2, c = (tid & 3) * 4;
            if (n0 + r < N) bv = *(const float4*)(Bb + (long)(n0 + r) * K + k0 + c);
            Bs[c+0][r]=bv.x; Bs[c+1][r]=bv.y; Bs[c+2][r]=bv.z; Bs[c+3][r]=bv.w;
        }
        __syncthreads();
#pragma unroll
        for (int kk = 0; kk < 16; kk++) {
            float4 a = *(const float4*)&As[kk][rowt];
            float4 b = *(const float4*)&Bs[kk][colt];
            float ra[4] = {a.x,a.y,a.z,a.w}, rb[4] = {b.x,b.y,b.z,b.w};
#pragma unroll
            for (int i = 0; i < 4; i++)
#pragma unroll
                for (int j = 0; j < 4; j++) acc[i][j] += ra[i] * rb[j];
        }
        __syncthreads();
    }
    if (n0 + colt < N) {
#pragma unroll
        for (int i = 0; i < 4; i++) {
            int m = m0 + rowt + i;
            if (m < M) {
                float bb = bias ? bias[m] : 0.f;
                float4 o = make_float4(acc[i][0]+bb, acc[i][1]+bb, acc[i][2]+bb, acc[i][3]+bb);
                *(float4*)(Cb + (long)m * N + n0 + colt) = o;
            }
        }
    }
}

static void launch_gemm64(bool ta, bool tb,
                          const float* A, const float* B, float* C, const float* bias,
                          int M, int N, int K, long sA, long sB, long sC, int batch)
{
    dim3 grid((N + 63) / 64, (M + 63) / 64, batch);
    if (!ta && !tb)      gemm64_kernel<false,false><<<grid,256>>>(A,B,C,bias,M,N,K,sA,sB,sC);
    else if (!ta && tb)  gemm64_kernel<false,true ><<<grid,256>>>(A,B,C,bias,M,N,K,sA,sB,sC);
    else if (ta && !tb)  gemm64_kernel<true ,false><<<grid,256>>>(A,B,C,bias,M,N,K,sA,sB,sC);
    else                 gemm64_kernel<true ,true ><<<grid,256>>>(A,B,C,bias,M,N,K,sA,sB,sC);
}

// ===========================================================================
// Split-K gram: P[(b*nsplit+s)] (64x64 fixed stride) = X[b][:, ks] Y[b][:, ks]^T
// grid (nsplit, batch). M,N <= 64, klen % 16 == 0.
// ===========================================================================
__global__ void __launch_bounds__(256)
gram_k(const float* __restrict__ X, const float* __restrict__ Y,
       float* __restrict__ P, int M, int N, int K, int klen, long sX, long sY)
{
    __shared__ float Xs[16][68], Ys[16][68];
    const int tid = threadIdx.x;
    const float* Xb = X + (long)blockIdx.y * sX;
    const float* Yb = Y + (long)blockIdx.y * sY;
    const int kbase = blockIdx.x * klen;
    const int rowt = (tid >> 4) * 4, colt = (tid & 15) * 4;
    const int r = tid >> 2, c = (tid & 3) * 4;
    float acc[4][4] = {};

    for (int k0 = kbase; k0 < kbase + klen; k0 += 16) {
        float4 xv = {0,0,0,0}, yv = {0,0,0,0};
        if (r < M) xv = *(const float4*)(Xb + (long)r * K + k0 + c);
        if (r < N) yv = *(const float4*)(Yb + (long)r * K + k0 + c);
        Xs[c+0][r]=xv.x; Xs[c+1][r]=xv.y; Xs[c+2][r]=xv.z; Xs[c+3][r]=xv.w;
        Ys[c+0][r]=yv.x; Ys[c+1][r]=yv.y; Ys[c+2][r]=yv.z; Ys[c+3][r]=yv.w;
        __syncthreads();
#pragma unroll
        for (int kk = 0; kk < 16; kk++) {
            float4 a = *(const float4*)&Xs[kk][rowt];
            float4 b = *(const float4*)&Ys[kk][colt];
            float ra[4]={a.x,a.y,a.z,a.w}, rb[4]={b.x,b.y,b.z,b.w};
#pragma unroll
            for (int i = 0; i < 4; i++)
#pragma unroll
                for (int j = 0; j < 4; j++) acc[i][j] += ra[i] * rb[j];
        }
        __syncthreads();
    }
    float* Pp = P + ((long)blockIdx.y * gridDim.x + blockIdx.x) * 4096;
    if (colt < N) {
#pragma unroll
        for (int i = 0; i < 4; i++)
            if (rowt + i < M)
                *(float4*)(Pp + (rowt + i) * 64 + colt) =
                    make_float4(acc[i][0], acc[i][1], acc[i][2], acc[i][3]);
    }
}

__global__ void gram_reduce_k(const float* __restrict__ P, float* __restrict__ C,
                              int M, int N, int nsplit)
{
    int idx = blockIdx.x * 256 + threadIdx.x;
    int tot = 8 * M * N;
    if (idx >= tot) return;
    int n = idx % N, m = (idx / N) % M, b = idx / (M * N);
    float s = 0.f;
    for (int k = 0; k < nsplit; k++)
        s += P[((long)b * nsplit + k) * 4096 + m * 64 + n];
    C[(long)b * M * N + m * N + n] = s;
}

// ---------------------------------------------------------------------------
// Row softmax (general width)
// ---------------------------------------------------------------------------
__global__ void row_softmax_k(const float* __restrict__ L, float* __restrict__ A, int N)
{
    long row = blockIdx.x;
    const float* p = L + row * (long)N;
    float* q = A + row * (long)N;
    int t = threadIdx.x;
    __shared__ float sh[8];

    float m = -3.4e38f;
    for (int i = t; i < N; i += 256) m = fmaxf(m, p[i]);
#pragma unroll
    for (int o = 16; o; o >>= 1) m = fmaxf(m, __shfl_xor_sync(0xffffffffu, m, o));
    if ((t & 31) == 0) sh[t >> 5] = m;
    __syncthreads();
    float mm = sh[0];
#pragma unroll
    for (int w = 1; w < 8; w++) mm = fmaxf(mm, sh[w]);
    __syncthreads();

    float s = 0.f;
    for (int i = t; i < N; i += 256) s += __expf(p[i] - mm);
#pragma unroll
    for (int o = 16; o; o >>= 1) s += __shfl_xor_sync(0xffffffffu, s, o);
    if ((t & 31) == 0) sh[t >> 5] = s;
    __syncthreads();
    float ss = 0.f;
#pragma unroll
    for (int w = 0; w < 8; w++) ss += sh[w];
    float inv = 1.f / ss;

    for (int i = t; i < N; i += 256) q[i] = __expf(p[i] - mm) * inv;
}

// ---------------------------------------------------------------------------
// Row / column stats of LB [8][1024][1024]: max and 1/sum(exp)
// ---------------------------------------------------------------------------
__global__ void row_stats_k(const float* __restrict__ L,
                            float* __restrict__ Mo, float* __restrict__ Io)
{
    long row = blockIdx.x;
    const float* p = L + row * 1024;
    int t = threadIdx.x;
    __shared__ float sh[8];

    float m = -3.4e38f;
    for (int i = t; i < 1024; i += 256) m = fmaxf(m, p[i]);
#pragma unroll
    for (int o = 16; o; o >>= 1) m = fmaxf(m, __shfl_xor_sync(0xffffffffu, m, o));
    if ((t & 31) == 0) sh[t >> 5] = m;
    __syncthreads();
    float mm = sh[0];
#pragma unroll
    for (int w = 1; w < 8; w++) mm = fmaxf(mm, sh[w]);
    __syncthreads();

    float s = 0.f;
    for (int i = t; i < 1024; i += 256) s += __expf(p[i] - mm);
#pragma unroll
    for (int o = 16; o; o >>= 1) s += __shfl_xor_sync(0xffffffffu, s, o);
    if ((t & 31) == 0) sh[t >> 5] = s;
    __syncthreads();
    if (t == 0) {
        float ss = 0.f;
#pragma unroll
        for (int w = 0; w < 8; w++) ss += sh[w];
        Mo[row] = mm;
        Io[row] = 1.f / ss;
    }
}

__global__ void col_stats_k(const float* __restrict__ L,
                            float* __restrict__ Mo, float* __restrict__ Io)
{
    int cc = threadIdx.x & 63;
    int kg = threadIdx.x >> 6;
    int i  = blockIdx.x * 64 + cc;
    const float* Lb = L + (long)blockIdx.y * 1048576;
    __shared__ float red[4][64];

    float m = -3.4e38f;
    for (int k = kg; k < 1024; k += 4) m = fmaxf(m, Lb[(k << 10) + i]);
    red[kg][cc] = m;
    __syncthreads();
    m = fmaxf(fmaxf(red[0][cc], red[1][cc]), fmaxf(red[2][cc], red[3][cc]));
    __syncthreads();

    float s = 0.f;
    for (int k = kg; k < 1024; k += 4) s += __expf(Lb[(k << 10) + i] - m);
    red[kg][cc] = s;
    __syncthreads();
    if (kg == 0) {
        float ss = red[0][cc] + red[1][cc] + red[2][cc] + red[3][cc];
        Mo[blockIdx.y * 1024 + i] = m;
        Io[blockIdx.y * 1024 + i] = 1.f / ss;
    }
}

// ===========================================================================
// Fused softmax(A)·W GEMMs. L [8][1024][1024], W [8][1024][64], O [8][1024][64].
// av_row: O[i,:] = (1/s_i) sum_k exp(L[i,k]-m_i) W[k,:]     (row softmax)
// av_col: O[p,:] = (1/s_p) sum_q exp(L[q,p]-m_p) W[q,:]     (col softmax ^T)
// Tile 64(M)x64(N=full), grid (16, 8).
// ===========================================================================
__global__ void __launch_bounds__(256)
av_row_k(const float* __restrict__ L, const float* __restrict__ W,
         const float* __restrict__ Ms, const float* __restrict__ Is,
         float* __restrict__ O)
{
    __shared__ float Ls[16][68], Ws[16][68];
    __shared__ float sm[64], si[64];
    const int tid = threadIdx.x;
    const int b = blockIdx.y, m0 = blockIdx.x * 64;
    if (tid < 64) { sm[tid] = Ms[b * 1024 + m0 + tid]; si[tid] = Is[b * 1024 + m0 + tid]; }
    __syncthreads();
    const float* Lb = L + (long)b * 1048576;
    const float* Wb = W + (long)b * 65536;
    const int rowt = (tid >> 4) * 4, colt = (tid & 15) * 4;
    const int r = tid >> 2, c = (tid & 3) * 4;
    const int kr = tid >> 4, nc = (tid & 15) * 4;
    float acc[4][4] = {};

    for (int k0 = 0; k0 < 1024; k0 += 16) {
        float4 v = *(const float4*)(Lb + (long)(m0 + r) * 1024 + k0 + c);
        float mr = sm[r];
        Ls[c+0][r] = __expf(v.x - mr);
        Ls[c+1][r] = __expf(v.y - mr);
        Ls[c+2][r] = __expf(v.z - mr);
        Ls[c+3][r] = __expf(v.w - mr);
        *(float4*)&Ws[kr][nc] = *(const float4*)(Wb + (long)(k0 + kr) * 64 + nc);
        __syncthreads();
#pragma unroll
        for (int kk = 0; kk < 16; kk++) {
            float4 a = *(const float4*)&Ls[kk][rowt];
            float4 w = *(const float4*)&Ws[kk][colt];
            float ra[4]={a.x,a.y,a.z,a.w}, rb[4]={w.x,w.y,w.z,w.w};
#pragma unroll
            for (int i = 0; i < 4; i++)
#pragma unroll
                for (int j = 0; j < 4; j++) acc[i][j] += ra[i] * rb[j];
        }
        __syncthreads();
    }
    float* Ob = O + (long)b * 65536;
#pragma unroll
    for (int i = 0; i < 4; i++) {
        float sc = si[rowt + i];
        *(float4*)(Ob + (long)(m0 + rowt + i) * 64 + colt) =
            make_float4(acc[i][0]*sc, acc[i][1]*sc, acc[i][2]*sc, acc[i][3]*sc);
    }
}

__global__ void __launch_bounds__(256)
av_col_k(const float* __restrict__ L, const float* __restrict__ W,
         const float* __restrict__ Ms, const float* __restrict__ Is,
         float* __restrict__ O)
{
    __shared__ float Ls[16][68], Ws[16][68];
    __shared__ float sm[64], si[64];
    const int tid = threadIdx.x;
    const int b = blockIdx.y, m0 = blockIdx.x * 64;
    if (tid < 64) { sm[tid] = Ms[b * 1024 + m0 + tid]; si[tid] = Is[b * 1024 + m0 + tid]; }
    __syncthreads();
    const float* Lb = L + (long)b * 1048576;
    const float* Wb = W + (long)b * 65536;
    const int rowt = (tid >> 4) * 4, colt = (tid & 15) * 4;
    const int kr = tid >> 4, mc = (tid & 15) * 4;
    float acc[4][4] = {};

    for (int k0 = 0; k0 < 1024; k0 += 16) {
        float4 v = *(const float4*)(Lb + (long)(k0 + kr) * 1024 + m0 + mc);
        float4 e = make_float4(__expf(v.x - sm[mc+0]), __expf(v.y - sm[mc+1]),
                               __expf(v.z - sm[mc+2]), __expf(v.w - sm[mc+3]));
        *(float4*)&Ls[kr][mc] = e;
        *(float4*)&Ws[kr][mc] = *(const float4*)(Wb + (long)(k0 + kr) * 64 + mc);
        __syncthreads();
#pragma unroll
        for (int kk = 0; kk < 16; kk++) {
            float4 a = *(const float4*)&Ls[kk][rowt];
            float4 w = *(const float4*)&Ws[kk][colt];
            float ra[4]={a.x,a.y,a.z,a.w}, rb[4]={w.x,w.y,w.z,w.w};
#pragma unroll
            for (int i = 0; i < 4; i++)
#pragma unroll
                for (int j = 0; j < 4; j++) acc[i][j] += ra[i] * rb[j];
        }
        __syncthreads();
    }
    float* Ob = O + (long)b * 65536;
#pragma unroll
    for (int i = 0; i < 4; i++) {
        float sc = si[rowt + i];
        *(float4*)(Ob + (long)(m0 + rowt + i) * 64 + colt) =
            make_float4(acc[i][0]*sc, acc[i][1]*sc, acc[i][2]*sc, acc[i][3]*sc);
    }
}

// ---------------------------------------------------------------------------
// Keys cubic (a=-0.5), bicubic downsample (8-tap AA), upsample operator algebra
// ---------------------------------------------------------------------------
__device__ __forceinline__ float keys_cubic(float x)
{
    x = fabsf(x);
    if (x < 1.f) return ((1.5f * x - 2.5f) * x) * x + 1.f;
    if (x < 2.f) return ((-0.5f * x + 2.5f) * x - 4.f) * x + 2.f;
    return 0.f;
}

__global__ void downsample_k(const float* __restrict__ x, float* __restrict__ y)
{
    int idx = blockIdx.x * 256 + threadIdx.x;
    if (idx >= 8 * 64 * 256) return;
    int ox = idx & 15;
    int oy = (idx >> 4) & 15;
    int bc = idx >> 8;

    int jy0 = 2 * oy - 3, jx0 = 2 * ox - 3;
    float wy[8], wx[8];
    float sy = 0.f, sx = 0.f;
#pragma unroll
    for (int t = 0; t < 8; t++) {
        float w = keys_cubic(fabsf(3.5f - t) * 0.5f);
        int jy = jy0 + t;
        wy[t] = (jy >= 0 && jy < 32) ? w : 0.f; sy += wy[t];
        int jx = jx0 + t;
        wx[t] = (jx >= 0 && jx < 32) ? w : 0.f; sx += wx[t];
    }
    float iy = 1.f / sy, ix = 1.f / sx;
#pragma unroll
    for (int t = 0; t < 8; t++) { wy[t] *= iy; wx[t] *= ix; }

    const float* src = x + (long)bc * 1024;
    float acc = 0.f;
#pragma unroll
    for (int t = 0; t < 8; t++) {
        int jy = min(max(jy0 + t, 0), 31);
        float r = 0.f;
#pragma unroll
        for (int u = 0; u < 8; u++) {
            int jx = min(max(jx0 + u, 0), 31);
            r += wx[u] * src[jy * 32 + jx];
        }
        acc += wy[t] * r;
    }
    y[idx] = acc;
}

// Z[b][c][j] = sum_I x[b][c][I] * U[I][j]    (adjoint of 4x upsample), Z [8,64,256]
__global__ void upadj_k(const float* __restrict__ x, float* __restrict__ Z)
{
    int idx = blockIdx.x * 256 + threadIdx.x;
    if (idx >= 8 * 64 * 256) return;
    int j = idx & 255;
    int c = (idx >> 8) & 63;
    int b = idx >> 14;
    const float* xr = x + (long)b * 65536 + (long)c * 1024;

    float acc = 0.f;
    int Ilo = max(0, 4 * j - 8), Ihi = min(1023, 4 * j + 10);
    for (int I = Ilo; I <= Ihi; I++) {
        float sf = (I + 0.5f) * 0.25f - 0.5f;
        float fl = floorf(sf);
        float f  = sf - fl;
        int base = (int)fl - 1;
        int tt = j - base;
        if (tt < 0 || tt > 3) continue;
        float tot = 0.f, wsel = 0.f;
#pragma unroll
        for (int t = 0; t < 4; t++) {
            float w = keys_cubic(f + 1.f - t);
            int jj = base + t;
            if (jj < 0 || jj >= 256) w = 0.f;
            tot += w;
            if (t == tt) wsel = w;
        }
        acc += xr[I] * (wsel / tot);
    }
    Z[idx] = acc;
}

// Wout[b][I][c] = sum_t w_t(I) * Y[b][base+t][c]   (apply U), Y [8,256,64] -> W [8,1024,64]
__global__ void upapply_k(const float* __restrict__ Y, float* __restrict__ Wout)
{
    int idx = blockIdx.x * 256 + threadIdx.x;
    if (idx >= 8 * 1024 * 64) return;
    int c = idx & 63;
    int I = (idx >> 6) & 1023;
    int b = idx >> 16;

    float sf = (I + 0.5f) * 0.25f - 0.5f;
    float fl = floorf(sf);
    float f  = sf - fl;
    int base = (int)fl - 1;
    float w[4], tot = 0.f;
#pragma unroll
    for (int t = 0; t < 4; t++) {
        float ww = keys_cubic(f + 1.f - t);
        int jj = base + t;
        if (jj < 0 || jj >= 256) ww = 0.f;
        w[t] = ww; tot += ww;
    }
    float inv = 1.f / tot;
    const float* Yb = Y + (long)b * 16384;
    float acc = 0.f;
#pragma unroll
    for (int t = 0; t < 4; t++) {
        if (w[t] != 0.f) acc += w[t] * Yb[(base + t) * 64 + c];
    }
    Wout[idx] = acc * inv;
}

// ---------------------------------------------------------------------------
// BN stats: [B][C][HW] layout and transposed [B][HW][C] layout
// ---------------------------------------------------------------------------
__global__ void bn_stats_k(const float* __restrict__ T, float* __restrict__ mv)
{
    int c = blockIdx.x;
    int t = threadIdx.x;
    float s = 0.f, s2 = 0.f;
    for (int i = t; i < 8192; i += 256) {
        float v = T[(long)(i >> 10) * 65536 + c * 1024 + (i & 1023)];
        s += v; s2 += v * v;
    }
    __shared__ float sh1[8], sh2[8];
#pragma unroll
    for (int o = 16; o; o >>= 1) {
        s  += __shfl_xor_sync(0xffffffffu, s, o);
        s2 += __shfl_xor_sync(0xffffffffu, s2, o);
    }
    if ((t & 31) == 0) { sh1[t >> 5] = s; sh2[t >> 5] = s2; }
    __syncthreads();
    if (t == 0) {
        float ts = 0.f, ts2 = 0.f;
#pragma unroll
        for (int w = 0; w < 8; w++) { ts += sh1[w]; ts2 += sh2[w]; }
        float mean = ts * (1.f / 8192.f);
        float var  = ts2 * (1.f / 8192.f) - mean * mean;
        mv[c] = mean;
        mv[64 + c] = fmaxf(var, 0.f);
    }
}

__global__ void bn_stats_t_k(const float* __restrict__ T, float* __restrict__ mv)
{
    int c = blockIdx.x;
    int t = threadIdx.x;
    float s = 0.f, s2 = 0.f;
    for (int i = t; i < 8192; i += 256) {
        float v = T[(long)(i >> 10) * 65536 + (i & 1023) * 64 + c];
        s += v; s2 += v * v;
    }
    __shared__ float sh1[8], sh2[8];
#pragma unroll
    for (int o = 16; o; o >>= 1) {
        s  += __shfl_xor_sync(0xffffffffu, s, o);
        s2 += __shfl_xor_sync(0xffffffffu, s2, o);
    }
    if ((t & 31) == 0) { sh1[t >> 5] = s; sh2[t >> 5] = s2; }
    __syncthreads();
    if (t == 0) {
        float ts = 0.f, ts2 = 0.f;
#pragma unroll
        for (int w = 0; w < 8; w++) { ts += sh1[w]; ts2 += sh2[w]; }
        float mean = ts * (1.f / 8192.f);
        float var  = ts2 * (1.f / 8192.f) - mean * mean;
        mv[c] = mean;
        mv[64 + c] = fmaxf(var, 0.f);
    }
}

// ---------------------------------------------------------------------------
// Finalize: ch_o [B][C][HW]; hw_o transposed [B][HW][C]
// ---------------------------------------------------------------------------
__global__ void finalize_k(const float* __restrict__ x1, const float* __restrict__ x2,
                           const float* __restrict__ ch1o, const float* __restrict__ ch2o,
                           const float* __restrict__ hw1t, const float* __restrict__ hw2t,
                           const float* __restrict__ mv,
                           const float* __restrict__ gamma, const float* __restrict__ beta,
                           float* __restrict__ out)
{
    int idx = blockIdx.x * 256 + threadIdx.x;
    if (idx >= 524288) return;
    int c = (idx >> 10) & 63;
    long hwi = ((long)(idx >> 16)) * 65536 + (long)(idx & 1023) * 64 + c;
    float g = gamma[c], be = beta[c];

    float xa = x1[idx], xb = x2[idx];

    float v, r;
    v = (ch1o[idx] - mv[c])       * rsqrtf(mv[64 + c]  + 1e-5f) * g + be + xa;
    r = fmaxf(v, 0.f);
    v = (hw1t[hwi] - mv[256 + c]) * rsqrtf(mv[320 + c] + 1e-5f) * g + be + xa;
    out[idx] = 0.5f * (r + fmaxf(v, 0.f));

    v = (ch2o[idx] - mv[128 + c]) * rsqrtf(mv[192 + c] + 1e-5f) * g + be + xb;
    r = fmaxf(v, 0.f);
    v = (hw2t[hwi] - mv[384 + c]) * rsqrtf(mv[448 + c] + 1e-5f) * g + be + xb;
    out[524288 + idx] = 0.5f * (r + fmaxf(v, 0.f));
}

// ===========================================================================
extern "C" void kernel_launch(void* const* d_in, const int* in_sizes, int n_in,
                              void* d_out, int out_size)
{
    const float* x1     = (const float*)d_in[0];   // [8,64,1024]
    const float* x2     = (const float*)d_in[1];
    const float* w_down = (const float*)d_in[2];   // [32,64]
    const float* b_down = (const float*)d_in[3];   // [32]
    const float* w_up   = (const float*)d_in[4];   // [64,32]
    const float* b_up   = (const float*)d_in[5];   // [64]
    const float* gamma  = (const float*)d_in[6];   // [64]
    const float* beta   = (const float*)d_in[7];   // [64]
    float* out = (float*)d_out;

    float* base = nullptr;
    cudaGetSymbolAddress((void**)&base, g_buf);

    float* LB = base;                      // [8,1024,1024]
    float* S  = base + 8ll * 1024 * 1024;
    float* XD1   = S; S += 262144;   // [8,32,1024]
    float* XD2   = S; S += 262144;
    float* X1C   = S; S += 32768;    // [8,64,64]
    float* X2C   = S; S += 32768;
    float* G12   = S; S += 32768;
    float* X1CD  = S; S += 8192;     // [8,32,32]
    float* X2CD  = S; S += 8192;
    float* LC    = S; S += 32768;
    float* AC12  = S; S += 32768;
    float* AC21  = S; S += 32768;
    float* LCD   = S; S += 8192;
    float* ACD12 = S; S += 8192;
    float* ACD21 = S; S += 8192;
    float* TT    = S; S += 16384;    // [8,64,32]
    float* U1T   = S; S += 32768;
    float* U2T   = S; S += 32768;
    float* CH1   = S; S += 32768;
    float* CH2   = S; S += 32768;
    float* CH1O  = S; S += 524288;   // [8,64,1024]
    float* CH2O  = S; S += 524288;
    float* XDN1  = S; S += 131072;   // [8,64,256]
    float* XDN2  = S; S += 131072;
    float* GD    = S; S += 32768;
    float* PD    = S; S += 131072;   // [8,64,256]
    float* LFD   = S; S += 524288;   // [8,256,256]
    float* AFD12 = S; S += 524288;
    float* AFD21 = S; S += 524288;
    float* Z1    = S; S += 131072;   // [8,64,256]
    float* Z2    = S; S += 131072;
    float* Y1    = S; S += 131072;   // [8,256,64]
    float* Y2    = S; S += 131072;
    float* W1    = S; S += 524288;   // [8,1024,64]
    float* W2    = S; S += 524288;
    float* HW1OT = S; S += 524288;   // [8,1024,64]
    float* HW2OT = S; S += 524288;
    float* PP    = S; S += 524288;   // [8,64,1024]
    float* RSM   = S; S += 8192;
    float* RSI   = S; S += 8192;
    float* CSM   = S; S += 8192;
    float* CSI   = S; S += 8192;
    float* PART  = S; S += 262144;   // split-K partials (reused sequentially)
    float* MV    = S; S += 512;

    // ===================== channel path =====================
    gram_k<<<dim3(8,8),256>>>(x1, x1, PART, 64, 64, 1024, 128, 65536, 65536);
    gram_reduce_k<<<128,256>>>(PART, X1C, 64, 64, 8);
    gram_k<<<dim3(8,8),256>>>(x2, x2, PART, 64, 64, 1024, 128, 65536, 65536);
    gram_reduce_k<<<128,256>>>(PART, X2C, 64, 64, 8);
    launch_gemm64(false,false, w_down, x1, XD1, b_down, 32, 1024, 64, 0, 65536, 32768, 8);
    launch_gemm64(false,false, w_down, x2, XD2, b_down, 32, 1024, 64, 0, 65536, 32768, 8);
    gram_k<<<dim3(8,8),256>>>(XD1, XD1, PART, 32, 32, 1024, 128, 32768, 32768);
    gram_reduce_k<<<32,256>>>(PART, X1CD, 32, 32, 8);
    gram_k<<<dim3(8,8),256>>>(XD2, XD2, PART, 32, 32, 1024, 128, 32768, 32768);
    gram_reduce_k<<<32,256>>>(PART, X2CD, 32, 32, 8);
    launch_gemm64(false,true, X1C, X2C, LC, nullptr, 64, 64, 64, 4096, 4096, 4096, 8);
    row_softmax_k<<<512,256>>>(LC, AC12, 64);
    launch_gemm64(false,true, X2C, X1C, LC, nullptr, 64, 64, 64, 4096, 4096, 4096, 8);
    row_softmax_k<<<512,256>>>(LC, AC21, 64);
    launch_gemm64(false,true, X1CD, X2CD, LCD, nullptr, 32, 32, 32, 1024, 1024, 1024, 8);
    row_softmax_k<<<256,256>>>(LCD, ACD12, 32);
    launch_gemm64(false,true, X2CD, X1CD, LCD, nullptr, 32, 32, 32, 1024, 1024, 1024, 8);
    row_softmax_k<<<256,256>>>(LCD, ACD21, 32);
    launch_gemm64(false,false, w_up, ACD12, TT, b_up, 64, 32, 32, 0, 1024, 2048, 8);
    launch_gemm64(false,true,  w_up, TT, U1T, b_up, 64, 64, 32, 0, 2048, 4096, 8);
    launch_gemm64(false,false, w_up, ACD21, TT, b_up, 64, 32, 32, 0, 1024, 2048, 8);
    launch_gemm64(false,true,  w_up, TT, U2T, b_up, 64, 64, 32, 0, 2048, 4096, 8);
    launch_gemm64(false,true, AC12, U1T, CH1, nullptr, 64, 64, 64, 4096, 4096, 4096, 8);
    launch_gemm64(false,true, AC21, U2T, CH2, nullptr, 64, 64, 64, 4096, 4096, 4096, 8);
    launch_gemm64(false,false, CH1, x1, CH1O, nullptr, 64, 1024, 64, 4096, 65536, 65536, 8);
    launch_gemm64(false,false, CH2, x2, CH2O, nullptr, 64, 1024, 64, 4096, 65536, 65536, 8);

    // ===================== feature path =====================
    // L = x1^T (x1 x2^T) x2
    gram_k<<<dim3(8,8),256>>>(x1, x2, PART, 64, 64, 1024, 128, 65536, 65536);
    gram_reduce_k<<<128,256>>>(PART, G12, 64, 64, 8);
    launch_gemm64(false,false, G12, x2, PP, nullptr, 64, 1024, 64, 4096, 65536, 65536, 8);
    launch_gemm64(true, false, x1, PP, LB, nullptr, 1024, 1024, 64, 65536, 65536, 1048576, 8);
    row_stats_k<<<8192,256>>>(LB, RSM, RSI);
    col_stats_k<<<dim3(16,8),256>>>(LB, CSM, CSI);

    // downsampled attention maps via same factorization
    downsample_k<<<512,256>>>(x1, XDN1);
    downsample_k<<<512,256>>>(x2, XDN2);
    gram_k<<<dim3(2,8),256>>>(XDN1, XDN2, PART, 64, 64, 256, 128, 16384, 16384);
    gram_reduce_k<<<128,256>>>(PART, GD, 64, 64, 2);
    launch_gemm64(false,false, GD, XDN2, PD, nullptr, 64, 256, 64, 4096, 16384, 16384, 8);
    launch_gemm64(true, false, XDN1, PD, LFD, nullptr, 256, 256, 64, 16384, 16384, 65536, 8);
    row_softmax_k<<<2048,256>>>(LFD, AFD12, 256);
    gram_k<<<dim3(2,8),256>>>(XDN2, XDN1, PART, 64, 64, 256, 128, 16384, 16384);
    gram_reduce_k<<<128,256>>>(PART, GD, 64, 64, 2);
    launch_gemm64(false,false, GD, XDN1, PD, nullptr, 64, 256, 64, 4096, 16384, 16384, 8);
    launch_gemm64(true, false, XDN2, PD, LFD, nullptr, 256, 256, 64, 16384, 16384, 65536, 8);
    row_softmax_k<<<2048,256>>>(LFD, AFD21, 256);

    // W = U (AFD (xU)^T):  Z = xU ; Y = AFD Z^T ; W = U Y
    upadj_k<<<512,256>>>(x1, Z1);
    upadj_k<<<512,256>>>(x2, Z2);
    launch_gemm64(false,true, AFD12, Z1, Y1, nullptr, 256, 64, 256, 65536, 16384, 16384, 8);
    launch_gemm64(false,true, AFD21, Z2, Y2, nullptr, 256, 64, 256, 65536, 16384, 16384, 8);
    upapply_k<<<2048,256>>>(Y1, W1);
    upapply_k<<<2048,256>>>(Y2, W2);

    // fused softmax(L) @ W
    av_row_k<<<dim3(16,8),256>>>(LB, W1, RSM, RSI, HW1OT);
    av_col_k<<<dim3(16,8),256>>>(LB, W2, CSM, CSI, HW2OT);

    // ===================== BN + residual + relu + average =====================
    bn_stats_k<<<64,256>>>(CH1O, MV);
    bn_stats_k<<<64,256>>>(CH2O, MV + 128);
    bn_stats_t_k<<<64,256>>>(HW1OT, MV + 256);
    bn_stats_t_k<<<64,256>>>(HW2OT, MV + 384);
    finalize_k<<<2048,256>>>(x1, x2, CH1O, CH2O, HW1OT, HW2OT, MV, gamma, beta, out);
}

// round 8
// speedup vs baseline: 7.2207x; 1.1481x over previous
#include <cuda_runtime.h>
#include <math.h>

// ---------------------------------------------------------------------------
// B=8, C=64, HW=1024, D=32.
// L = x1^T (x1 x2^T) x2 ; LFD21 = LFD12^T ; X?CD from W·X?C·W^T identity;
// channel path fully fused; HW outputs via fused softmax·W GEMMs.
// ---------------------------------------------------------------------------
__device__ float g_buf[17ll * 1024 * 1024];

// ===========================================================================
// gemm64: C[b](MxN) = opA(A[b]) * opB(B[b]); tile 64x64, KT=16, 256 thr, 4x4.
//  TA=0: A [M][K] ; TA=1: A [K][M] (stride M)
//  TB=0: B [K][N] ; TB=1: B [N][K] (C = A B^T)
// ===========================================================================
template <bool TA, bool TB>
__global__ void __launch_bounds__(256)
gemm64_kernel(const float* __restrict__ A, const float* __restrict__ B,
              float* __restrict__ C, int M, int N, int K, long sA, long sB, long sC)
{
    __shared__ float As[16][68];
    __shared__ float Bs[16][68];
    const int tid = threadIdx.x;
    const int m0 = blockIdx.y * 64, n0 = blockIdx.x * 64;
    const float* Ab = A + (long)blockIdx.z * sA;
    const float* Bb = B + (long)blockIdx.z * sB;
    float* Cb = C + (long)blockIdx.z * sC;
    const int rowt = (tid >> 4) * 4, colt = (tid & 15) * 4;
    float acc[4][4] = {};

    for (int k0 = 0; k0 < K; k0 += 16) {
        float4 av = {0,0,0,0}, bv = {0,0,0,0};
        if (!TA) {
            int r = tid >> 2, c = (tid & 3) * 4;
            if (m0 + r < M) av = *(const float4*)(Ab + (long)(m0 + r) * K + k0 + c);
            As[c+0][r]=av.x; As[c+1][r]=av.y; As[c+2][r]=av.z; As[c+3][r]=av.w;
        } else {
            int kr = tid >> 4, mc = (tid & 15) * 4;
            if (m0 + mc < M) av = *(const float4*)(Ab + (long)(k0 + kr) * M + m0 + mc);
            *(float4*)&As[kr][mc] = av;
        }
        if (!TB) {
            int kr = tid >> 4, nc = (tid & 15) * 4;
            if (n0 + nc < N) bv = *(const float4*)(Bb + (long)(k0 + kr) * N + n0 + nc);
            *(float4*)&Bs[kr][nc] = bv;
        } else {
            int r = tid >> 2, c = (tid & 3) * 4;
            if (n0 + r < N) bv = *(const float4*)(Bb + (long)(n0 + r) * K + k0 + c);
            Bs[c+0][r]=bv.x; Bs[c+1][r]=bv.y; Bs[c+2][r]=bv.z; Bs[c+3][r]=bv.w;
        }
        __syncthreads();
#pragma unroll
        for (int kk = 0; kk < 16; kk++) {
            float4 a = *(const float4*)&As[kk][rowt];
            float4 b = *(const float4*)&Bs[kk][colt];
            float ra[4] = {a.x,a.y,a.z,a.w}, rb[4] = {b.x,b.y,b.z,b.w};
#pragma unroll
            for (int i = 0; i < 4; i++)
#pragma unroll
                for (int j = 0; j < 4; j++) acc[i][j] += ra[i] * rb[j];
        }
        __syncthreads();
    }
    if (n0 + colt < N) {
#pragma unroll
        for (int i = 0; i < 4; i++) {
            int m = m0 + rowt + i;
            if (m < M)
                *(float4*)(Cb + (long)m * N + n0 + colt) =
                    make_float4(acc[i][0], acc[i][1], acc[i][2], acc[i][3]);
        }
    }
}

static void launch_gemm64(bool ta, bool tb,
                          const float* A, const float* B, float* C,
                          int M, int N, int K, long sA, long sB, long sC, int batch)
{
    dim3 grid((N + 63) / 64, (M + 63) / 64, batch);
    if (!ta && !tb)      gemm64_kernel<false,false><<<grid,256>>>(A,B,C,M,N,K,sA,sB,sC);
    else if (!ta && tb)  gemm64_kernel<false,true ><<<grid,256>>>(A,B,C,M,N,K,sA,sB,sC);
    else if (ta && !tb)  gemm64_kernel<true ,false><<<grid,256>>>(A,B,C,M,N,K,sA,sB,sC);
    else                 gemm64_kernel<true ,true ><<<grid,256>>>(A,B,C,M,N,K,sA,sB,sC);
}

// ===========================================================================
// gramA: 3 pairs {x1x1, x2x2, x1x2} x 8 batches x 8 k-splits of K=1024.
// P[(pz*8+split)] 64x64 tiles. grid (8, 24).
// ===========================================================================
__global__ void __launch_bounds__(256)
gramA_k(const float* __restrict__ x1, const float* __restrict__ x2, float* __restrict__ P)
{
    __shared__ float Xs[16][68], Ys[16][68];
    const int tid = threadIdx.x;
    const int pz = blockIdx.y, pair = pz >> 3, b = pz & 7;
    const float* Xb = ((pair == 1) ? x2 : x1) + (long)b * 65536;
    const float* Yb = ((pair == 0) ? x1 : x2) + (long)b * 65536;
    const int kbase = blockIdx.x * 128;
    const int rowt = (tid >> 4) * 4, colt = (tid & 15) * 4;
    const int r = tid >> 2, c = (tid & 3) * 4;
    float acc[4][4] = {};

    for (int k0 = kbase; k0 < kbase + 128; k0 += 16) {
        float4 xv = *(const float4*)(Xb + (long)r * 1024 + k0 + c);
        float4 yv = *(const float4*)(Yb + (long)r * 1024 + k0 + c);
        Xs[c+0][r]=xv.x; Xs[c+1][r]=xv.y; Xs[c+2][r]=xv.z; Xs[c+3][r]=xv.w;
        Ys[c+0][r]=yv.x; Ys[c+1][r]=yv.y; Ys[c+2][r]=yv.z; Ys[c+3][r]=yv.w;
        __syncthreads();
#pragma unroll
        for (int kk = 0; kk < 16; kk++) {
            float4 a = *(const float4*)&Xs[kk][rowt];
            float4 bq = *(const float4*)&Ys[kk][colt];
            float ra[4]={a.x,a.y,a.z,a.w}, rb[4]={bq.x,bq.y,bq.z,bq.w};
#pragma unroll
            for (int i = 0; i < 4; i++)
#pragma unroll
                for (int j = 0; j < 4; j++) acc[i][j] += ra[i] * rb[j];
        }
        __syncthreads();
    }
    float* Pp = P + ((long)pz * 8 + blockIdx.x) * 4096;
#pragma unroll
    for (int i = 0; i < 4; i++)
        *(float4*)(Pp + (rowt + i) * 64 + colt) =
            make_float4(acc[i][0], acc[i][1], acc[i][2], acc[i][3]);
}

// O (contiguous X1C,X2C,G12 = [3][8][4096]) = sum over 8 splits
__global__ void reduceA_k(const float* __restrict__ P, float* __restrict__ O)
{
    int idx = blockIdx.x * 256 + threadIdx.x;   // < 98304
    int pz = idx >> 12, e = idx & 4095;
    float s = 0.f;
#pragma unroll
    for (int k = 0; k < 8; k++) s += P[((long)pz * 8 + k) * 4096 + e];
    O[idx] = s;
}

// Generic split-K gram (used for GD): grid (nsplit, batch), M=N=64
__global__ void __launch_bounds__(256)
gram_k(const float* __restrict__ X, const float* __restrict__ Y,
       float* __restrict__ P, int K, int klen, long sX, long sY)
{
    __shared__ float Xs[16][68], Ys[16][68];
    const int tid = threadIdx.x;
    const float* Xb = X + (long)blockIdx.y * sX;
    const float* Yb = Y + (long)blockIdx.y * sY;
    const int kbase = blockIdx.x * klen;
    const int rowt = (tid >> 4) * 4, colt = (tid & 15) * 4;
    const int r = tid >> 2, c = (tid & 3) * 4;
    float acc[4][4] = {};

    for (int k0 = kbase; k0 < kbase + klen; k0 += 16) {
        float4 xv = *(const float4*)(Xb + (long)r * K + k0 + c);
        float4 yv = *(const float4*)(Yb + (long)r * K + k0 + c);
        Xs[c+0][r]=xv.x; Xs[c+1][r]=xv.y; Xs[c+2][r]=xv.z; Xs[c+3][r]=xv.w;
        Ys[c+0][r]=yv.x; Ys[c+1][r]=yv.y; Ys[c+2][r]=yv.z; Ys[c+3][r]=yv.w;
        __syncthreads();
#pragma unroll
        for (int kk = 0; kk < 16; kk++) {
            float4 a = *(const float4*)&Xs[kk][rowt];
            float4 bq = *(const float4*)&Ys[kk][colt];
            float ra[4]={a.x,a.y,a.z,a.w}, rb[4]={bq.x,bq.y,bq.z,bq.w};
#pragma unroll
            for (int i = 0; i < 4; i++)
#pragma unroll
                for (int j = 0; j < 4; j++) acc[i][j] += ra[i] * rb[j];
        }
        __syncthreads();
    }
    float* Pp = P + ((long)blockIdx.y * gridDim.x + blockIdx.x) * 4096;
#pragma unroll
    for (int i = 0; i < 4; i++)
        *(float4*)(Pp + (rowt + i) * 64 + colt) =
            make_float4(acc[i][0], acc[i][1], acc[i][2], acc[i][3]);
}

__global__ void gram_reduce_k(const float* __restrict__ P, float* __restrict__ C, int nsplit)
{
    int idx = blockIdx.x * 256 + threadIdx.x;   // 8*4096
    if (idx >= 32768) return;
    int b = idx >> 12, e = idx & 4095;
    float s = 0.f;
    for (int k = 0; k < nsplit; k++) s += P[((long)b * nsplit + k) * 4096 + e];
    C[idx] = s;
}

// ---------------------------------------------------------------------------
// Row sums: r[which][b][c] = sum_p x[b][c][p]; grid 16 (which*8+b), 256 thr
// ---------------------------------------------------------------------------
__global__ void rowsum_k(const float* __restrict__ x1, const float* __restrict__ x2,
                         float* __restrict__ r)
{
    int which = blockIdx.x >> 3, b = blockIdx.x & 7;
    const float* xb = (which ? x2 : x1) + (long)b * 65536;
    int w = threadIdx.x >> 5, lane = threadIdx.x & 31;
    for (int rr = w * 8; rr < w * 8 + 8; rr++) {
        float s = 0.f;
        for (int p = lane; p < 1024; p += 32) s += xb[rr * 1024 + p];
#pragma unroll
        for (int o = 16; o; o >>= 1) s += __shfl_xor_sync(0xffffffffu, s, o);
        if (lane == 0) r[which * 512 + b * 64 + rr] = s;
    }
}

// ===========================================================================
// Fused channel path: one block per batch. Everything in smem.
// ===========================================================================
__global__ void __launch_bounds__(256)
chan_fused_k(const float* __restrict__ X1C_g, const float* __restrict__ X2C_g,
             const float* __restrict__ rsum,
             const float* __restrict__ w_down, const float* __restrict__ b_down,
             const float* __restrict__ w_up, const float* __restrict__ b_up,
             float* __restrict__ CH1_g, float* __restrict__ CH2_g)
{
    extern __shared__ float sm[];
    float* A   = sm;              // 64*65  X1C -> U1T
    float* Bf  = A   + 4160;      // 64*65  X2C -> U2T
    float* LC  = Bf  + 4160;      // 64*65  LC -> E12
    float* E2  = LC  + 4160;      // 64*65
    float* Wd  = E2  + 4160;      // 32*64
    float* Wu  = Wd  + 2048;      // 64*32
    float* Mb  = Wu  + 2048;      // 32*64
    float* C1d = Mb  + 2048;      // 32*33
    float* C2d = C1d + 1056;
    float* LCD = C2d + 1056;
    float* A12d= LCD + 1056;
    float* A21d= A12d+ 1056;
    float* TT  = A21d+ 1056;      // 64*33
    float* bd  = TT  + 2112;      // 32
    float* bu  = bd  + 32;        // 64
    float* u1  = bu  + 64;        // 32
    float* u2  = u1  + 32;        // 32
    float* st  = u2  + 32;        // 256: rm, rsInv, cm, csInv

    const int b = blockIdx.x, t = threadIdx.x;

    for (int i = t; i < 4096; i += 256) {
        A [(i >> 6) * 65 + (i & 63)] = X1C_g[b * 4096 + i];
        Bf[(i >> 6) * 65 + (i & 63)] = X2C_g[b * 4096 + i];
    }
    for (int i = t; i < 2048; i += 256) { Wd[i] = w_down[i]; Wu[i] = w_up[i]; }
    if (t < 32) bd[t] = b_down[t];
    if (t < 64) bu[t] = b_up[t];
    __syncthreads();

    // u = Wd * rowsum
    if (t < 64) {
        int d = t & 31, which = t >> 5;
        const float* r = rsum + which * 512 + b * 64;
        float s = 0.f;
        for (int c = 0; c < 64; c++) s += Wd[d * 64 + c] * r[c];
        (which ? u2 : u1)[d] = s;
    }
    __syncthreads();

    // X1CD = Wd X1C Wd^T + u1 bd^T + bd u1^T + 1024 bd bd^T
    for (int o = t; o < 2048; o += 256) {
        int d = o >> 6, c = o & 63;
        float s = 0.f;
        for (int k = 0; k < 64; k++) s += Wd[d * 64 + k] * A[k * 65 + c];
        Mb[o] = s;
    }
    __syncthreads();
    for (int o = t; o < 1024; o += 256) {
        int d = o >> 5, e = o & 31;
        float s = 0.f;
        for (int c = 0; c < 64; c++) s += Mb[d * 64 + c] * Wd[e * 64 + c];
        C1d[d * 33 + e] = s + bd[d]*u1[e] + bd[e]*u1[d] + 1024.f*bd[d]*bd[e];
    }
    __syncthreads();
    // X2CD
    for (int o = t; o < 2048; o += 256) {
        int d = o >> 6, c = o & 63;
        float s = 0.f;
        for (int k = 0; k < 64; k++) s += Wd[d * 64 + k] * Bf[k * 65 + c];
        Mb[o] = s;
    }
    __syncthreads();
    for (int o = t; o < 1024; o += 256) {
        int d = o >> 5, e = o & 31;
        float s = 0.f;
        for (int c = 0; c < 64; c++) s += Mb[d * 64 + c] * Wd[e * 64 + c];
        C2d[d * 33 + e] = s + bd[d]*u2[e] + bd[e]*u2[d] + 1024.f*bd[d]*bd[e];
    }
    __syncthreads();

    // LC = X1C * X2C ; LCD = C1d * C2d
    for (int o = t; o < 4096; o += 256) {
        int i = o >> 6, j = o & 63;
        float s = 0.f;
        for (int k = 0; k < 64; k++) s += A[i * 65 + k] * Bf[k * 65 + j];
        LC[i * 65 + j] = s;
    }
    for (int o = t; o < 1024; o += 256) {
        int i = o >> 5, j = o & 31;
        float s = 0.f;
        for (int k = 0; k < 32; k++) s += C1d[i * 33 + k] * C2d[k * 33 + j];
        LCD[i * 33 + j] = s;
    }
    __syncthreads();

    // stats + small softmaxes
    if (t < 64) {                   // LC row stats
        float m = -3.4e38f;
        for (int j = 0; j < 64; j++) m = fmaxf(m, LC[t * 65 + j]);
        float s = 0.f;
        for (int j = 0; j < 64; j++) s += __expf(LC[t * 65 + j] - m);
        st[t] = m; st[64 + t] = 1.f / s;
    } else if (t < 128) {           // LC col stats
        int i = t - 64;
        float m = -3.4e38f;
        for (int j = 0; j < 64; j++) m = fmaxf(m, LC[j * 65 + i]);
        float s = 0.f;
        for (int j = 0; j < 64; j++) s += __expf(LC[j * 65 + i] - m);
        st[128 + i] = m; st[192 + i] = 1.f / s;
    } else if (t < 160) {           // LCD row softmax -> A12d
        int i = t - 128;
        float m = -3.4e38f;
        for (int j = 0; j < 32; j++) m = fmaxf(m, LCD[i * 33 + j]);
        float s = 0.f;
        for (int j = 0; j < 32; j++) s += __expf(LCD[i * 33 + j] - m);
        float inv = 1.f / s;
        for (int j = 0; j < 32; j++) A12d[i * 33 + j] = __expf(LCD[i * 33 + j] - m) * inv;
    } else if (t < 192) {           // LCD col softmax -> A21d (row i of LCD^T)
        int i = t - 160;
        float m = -3.4e38f;
        for (int j = 0; j < 32; j++) m = fmaxf(m, LCD[j * 33 + i]);
        float s = 0.f;
        for (int j = 0; j < 32; j++) s += __expf(LCD[j * 33 + i] - m);
        float inv = 1.f / s;
        for (int j = 0; j < 32; j++) A21d[i * 33 + j] = __expf(LCD[j * 33 + i] - m) * inv;
    }
    __syncthreads();

    // E2[i][j] = exp(LC[j][i] - cm_i)  (attn(x2c,x1c) row i unnormalized)
    for (int o = t; o < 4096; o += 256) {
        int i = o >> 6, j = o & 63;
        E2[i * 65 + j] = __expf(LC[j * 65 + i] - st[128 + i]);
    }
    __syncthreads();
    // E12 in place
    for (int o = t; o < 4096; o += 256) {
        int i = o >> 6, j = o & 63;
        LC[i * 65 + j] = __expf(LC[i * 65 + j] - st[i]);
    }
    __syncthreads();

    // dir1 ConvUp: TT = Wu*A12d + bu ; U1T -> A
    for (int o = t; o < 2048; o += 256) {
        int m = o >> 5, j = o & 31;
        float s = bu[m];
        for (int d = 0; d < 32; d++) s += Wu[m * 32 + d] * A12d[d * 33 + j];
        TT[m * 33 + j] = s;
    }
    __syncthreads();
    for (int o = t; o < 4096; o += 256) {
        int m = o >> 6, i = o & 63;
        float s = bu[m];
        for (int k = 0; k < 32; k++) s += Wu[m * 32 + k] * TT[i * 33 + k];
        A[m * 65 + i] = s;            // U1T[m][i]
    }
    __syncthreads();
    // dir2 ConvUp: TT = Wu*A21d + bu ; U2T -> Bf
    for (int o = t; o < 2048; o += 256) {
        int m = o >> 5, j = o & 31;
        float s = bu[m];
        for (int d = 0; d < 32; d++) s += Wu[m * 32 + d] * A21d[d * 33 + j];
        TT[m * 33 + j] = s;
    }
    __syncthreads();
    for (int o = t; o < 4096; o += 256) {
        int m = o >> 6, i = o & 63;
        float s = bu[m];
        for (int k = 0; k < 32; k++) s += Wu[m * 32 + k] * TT[i * 33 + k];
        Bf[m * 65 + i] = s;           // U2T[m][i]
    }
    __syncthreads();

    // CH1[i][k] = rsInv_i * sum_j E12[i][j] * U1T[k][j]
    // CH2[i][k] = csInv_i * sum_j E2 [i][j] * U2T[k][j]
    for (int o = t; o < 4096; o += 256) {
        int i = o >> 6, k = o & 63;
        float s1 = 0.f, s2 = 0.f;
        for (int j = 0; j < 64; j++) {
            s1 += LC[i * 65 + j] * A [k * 65 + j];
            s2 += E2[i * 65 + j] * Bf[k * 65 + j];
        }
        CH1_g[b * 4096 + i * 64 + k] = s1 * st[64 + i];
        CH2_g[b * 4096 + i * 64 + k] = s2 * st[192 + i];
    }
}

// ---------------------------------------------------------------------------
// Row softmax (materializing, for AFD12), width N
// ---------------------------------------------------------------------------
__global__ void row_softmax_k(const float* __restrict__ L, float* __restrict__ A, int N)
{
    long row = blockIdx.x;
    const float* p = L + row * (long)N;
    float* q = A + row * (long)N;
    int t = threadIdx.x;
    __shared__ float sh[8];

    float m = -3.4e38f;
    for (int i = t; i < N; i += 256) m = fmaxf(m, p[i]);
#pragma unroll
    for (int o = 16; o; o >>= 1) m = fmaxf(m, __shfl_xor_sync(0xffffffffu, m, o));
    if ((t & 31) == 0) sh[t >> 5] = m;
    __syncthreads();
    float mm = sh[0];
#pragma unroll
    for (int w = 1; w < 8; w++) mm = fmaxf(mm, sh[w]);
    __syncthreads();

    float s = 0.f;
    for (int i = t; i < N; i += 256) s += __expf(p[i] - mm);
#pragma unroll
    for (int o = 16; o; o >>= 1) s += __shfl_xor_sync(0xffffffffu, s, o);
    if ((t & 31) == 0) sh[t >> 5] = s;
    __syncthreads();
    float ss = 0.f;
#pragma unroll
    for (int w = 0; w < 8; w++) ss += sh[w];
    float inv = 1.f / ss;

    for (int i = t; i < N; i += 256) q[i] = __expf(p[i] - mm) * inv;
}

// Column softmax of L [batch][N][N] written TRANSPOSED: AT[k][i] = colsoftmax col i at row k
__global__ void colsoftT_k(const float* __restrict__ L, float* __restrict__ AT, int N)
{
    int cc = threadIdx.x & 63;
    int kg = threadIdx.x >> 6;
    int i  = blockIdx.x * 64 + cc;
    const float* Lb = L  + (long)blockIdx.y * N * N;
    float*       Ab = AT + (long)blockIdx.y * N * N;
    __shared__ float red[4][64];

    float m = -3.4e38f;
    for (int k = kg; k < N; k += 4) m = fmaxf(m, Lb[k * N + i]);
    red[kg][cc] = m;
    __syncthreads();
    m = fmaxf(fmaxf(red[0][cc], red[1][cc]), fmaxf(red[2][cc], red[3][cc]));
    __syncthreads();

    float s = 0.f;
    for (int k = kg; k < N; k += 4) s += __expf(Lb[k * N + i] - m);
    red[kg][cc] = s;
    __syncthreads();
    s = red[0][cc] + red[1][cc] + red[2][cc] + red[3][cc];
    float inv = 1.f / s;

    for (int k = kg; k < N; k += 4)
        Ab[k * N + i] = __expf(Lb[k * N + i] - m) * inv;
}

// ---------------------------------------------------------------------------
// LB stats: row (max, 1/sum) and col (max, 1/sum)
// ---------------------------------------------------------------------------
__global__ void row_stats_k(const float* __restrict__ L,
                            float* __restrict__ Mo, float* __restrict__ Io)
{
    long row = blockIdx.x;
    const float* p = L + row * 1024;
    int t = threadIdx.x;
    __shared__ float sh[8];

    float m = -3.4e38f;
    for (int i = t; i < 1024; i += 256) m = fmaxf(m, p[i]);
#pragma unroll
    for (int o = 16; o; o >>= 1) m = fmaxf(m, __shfl_xor_sync(0xffffffffu, m, o));
    if ((t & 31) == 0) sh[t >> 5] = m;
    __syncthreads();
    float mm = sh[0];
#pragma unroll
    for (int w = 1; w < 8; w++) mm = fmaxf(mm, sh[w]);
    __syncthreads();

    float s = 0.f;
    for (int i = t; i < 1024; i += 256) s += __expf(p[i] - mm);
#pragma unroll
    for (int o = 16; o; o >>= 1) s += __shfl_xor_sync(0xffffffffu, s, o);
    if ((t & 31) == 0) sh[t >> 5] = s;
    __syncthreads();
    if (t == 0) {
        float ss = 0.f;
#pragma unroll
        for (int w = 0; w < 8; w++) ss += sh[w];
        Mo[row] = mm;
        Io[row] = 1.f / ss;
    }
}

__global__ void col_stats_k(const float* __restrict__ L,
                            float* __restrict__ Mo, float* __restrict__ Io)
{
    int cc = threadIdx.x & 63;
    int kg = threadIdx.x >> 6;
    int i  = blockIdx.x * 64 + cc;
    const float* Lb = L + (long)blockIdx.y * 1048576;
    __shared__ float red[4][64];

    float m = -3.4e38f;
    for (int k = kg; k < 1024; k += 4) m = fmaxf(m, Lb[(k << 10) + i]);
    red[kg][cc] = m;
    __syncthreads();
    m = fmaxf(fmaxf(red[0][cc], red[1][cc]), fmaxf(red[2][cc], red[3][cc]));
    __syncthreads();

    float s = 0.f;
    for (int k = kg; k < 1024; k += 4) s += __expf(Lb[(k << 10) + i] - m);
    red[kg][cc] = s;
    __syncthreads();
    if (kg == 0) {
        float ss = red[0][cc] + red[1][cc] + red[2][cc] + red[3][cc];
        Mo[blockIdx.y * 1024 + i] = m;
        Io[blockIdx.y * 1024 + i] = 1.f / ss;
    }
}

// ===========================================================================
// Fused softmax(L)·W. L [8][1024][1024], W [8][1024][64], O [8][1024][64].
// ===========================================================================
__global__ void __launch_bounds__(256)
av_row_k(const float* __restrict__ L, const float* __restrict__ W,
         const float* __restrict__ Ms, const float* __restrict__ Is,
         float* __restrict__ O)
{
    __shared__ float Ls[16][68], Ws[16][68];
    __shared__ float smx[64], sin[64];
    const int tid = threadIdx.x;
    const int b = blockIdx.y, m0 = blockIdx.x * 64;
    if (tid < 64) { smx[tid] = Ms[b * 1024 + m0 + tid]; sin[tid] = Is[b * 1024 + m0 + tid]; }
    __syncthreads();
    const float* Lb = L + (long)b * 1048576;
    const float* Wb = W + (long)b * 65536;
    const int rowt = (tid >> 4) * 4, colt = (tid & 15) * 4;
    const int r = tid >> 2, c = (tid & 3) * 4;
    const int kr = tid >> 4, nc = (tid & 15) * 4;
    float acc[4][4] = {};

    for (int k0 = 0; k0 < 1024; k0 += 16) {
        float4 v = *(const float4*)(Lb + (long)(m0 + r) * 1024 + k0 + c);
        float mr = smx[r];
        Ls[c+0][r] = __expf(v.x - mr);
        Ls[c+1][r] = __expf(v.y - mr);
        Ls[c+2][r] = __expf(v.z - mr);
        Ls[c+3][r] = __expf(v.w - mr);
        *(float4*)&Ws[kr][nc] = *(const float4*)(Wb + (long)(k0 + kr) * 64 + nc);
        __syncthreads();
#pragma unroll
        for (int kk = 0; kk < 16; kk++) {
            float4 a = *(const float4*)&Ls[kk][rowt];
            float4 w = *(const float4*)&Ws[kk][colt];
            float ra[4]={a.x,a.y,a.z,a.w}, rb[4]={w.x,w.y,w.z,w.w};
#pragma unroll
            for (int i = 0; i < 4; i++)
#pragma unroll
                for (int j = 0; j < 4; j++) acc[i][j] += ra[i] * rb[j];
        }
        __syncthreads();
    }
    float* Ob = O + (long)b * 65536;
#pragma unroll
    for (int i = 0; i < 4; i++) {
        float sc = sin[rowt + i];
        *(float4*)(Ob + (long)(m0 + rowt + i) * 64 + colt) =
            make_float4(acc[i][0]*sc, acc[i][1]*sc, acc[i][2]*sc, acc[i][3]*sc);
    }
}

__global__ void __launch_bounds__(256)
av_col_k(const float* __restrict__ L, const float* __restrict__ W,
         const float* __restrict__ Ms, const float* __restrict__ Is,
         float* __restrict__ O)
{
    __shared__ float Ls[16][68], Ws[16][68];
    __shared__ float smx[64], sin[64];
    const int tid = threadIdx.x;
    const int b = blockIdx.y, m0 = blockIdx.x * 64;
    if (tid < 64) { smx[tid] = Ms[b * 1024 + m0 + tid]; sin[tid] = Is[b * 1024 + m0 + tid]; }
    __syncthreads();
    const float* Lb = L + (long)b * 1048576;
    const float* Wb = W + (long)b * 65536;
    const int rowt = (tid >> 4) * 4, colt = (tid & 15) * 4;
    const int kr = tid >> 4, mc = (tid & 15) * 4;
    float acc[4][4] = {};

    for (int k0 = 0; k0 < 1024; k0 += 16) {
        float4 v = *(const float4*)(Lb + (long)(k0 + kr) * 1024 + m0 + mc);
        float4 e = make_float4(__expf(v.x - smx[mc+0]), __expf(v.y - smx[mc+1]),
                               __expf(v.z - smx[mc+2]), __expf(v.w - smx[mc+3]));
        *(float4*)&Ls[kr][mc] = e;
        *(float4*)&Ws[kr][mc] = *(const float4*)(Wb + (long)(k0 + kr) * 64 + mc);
        __syncthreads();
#pragma unroll
        for (int kk = 0; kk < 16; kk++) {
            float4 a = *(const float4*)&Ls[kk][rowt];
            float4 w = *(const float4*)&Ws[kk][colt];
            float ra[4]={a.x,a.y,a.z,a.w}, rb[4]={w.x,w.y,w.z,w.w};
#pragma unroll
            for (int i = 0; i < 4; i++)
#pragma unroll
                for (int j = 0; j < 4; j++) acc[i][j] += ra[i] * rb[j];
        }
        __syncthreads();
    }
    float* Ob = O + (long)b * 65536;
#pragma unroll
    for (int i = 0; i < 4; i++) {
        float sc = sin[rowt + i];
        *(float4*)(Ob + (long)(m0 + rowt + i) * 64 + colt) =
            make_float4(acc[i][0]*sc, acc[i][1]*sc, acc[i][2]*sc, acc[i][3]*sc);
    }
}

// ---------------------------------------------------------------------------
// Keys cubic (a=-0.5) + resampling (paired kernels)
// ---------------------------------------------------------------------------
__device__ __forceinline__ float keys_cubic(float x)
{
    x = fabsf(x);
    if (x < 1.f) return ((1.5f * x - 2.5f) * x) * x + 1.f;
    if (x < 2.f) return ((-0.5f * x + 2.5f) * x - 4.f) * x + 2.f;
    return 0.f;
}

__global__ void downsample2_k(const float* __restrict__ x1, const float* __restrict__ x2,
                              float* __restrict__ y1, float* __restrict__ y2)
{
    int gidx = blockIdx.x * 256 + threadIdx.x;
    if (gidx >= 262144) return;
    const float* x = gidx < 131072 ? x1 : x2;
    float* y = gidx < 131072 ? y1 : y2;
    int idx = gidx & 131071;
    int ox = idx & 15;
    int oy = (idx >> 4) & 15;
    int bc = idx >> 8;

    int jy0 = 2 * oy - 3, jx0 = 2 * ox - 3;
    float wy[8], wx[8];
    float sy = 0.f, sx = 0.f;
#pragma unroll
    for (int t = 0; t < 8; t++) {
        float w = keys_cubic(fabsf(3.5f - t) * 0.5f);
        int jy = jy0 + t;
        wy[t] = (jy >= 0 && jy < 32) ? w : 0.f; sy += wy[t];
        int jx = jx0 + t;
        wx[t] = (jx >= 0 && jx < 32) ? w : 0.f; sx += wx[t];
    }
    float iy = 1.f / sy, ix = 1.f / sx;
#pragma unroll
    for (int t = 0; t < 8; t++) { wy[t] *= iy; wx[t] *= ix; }

    const float* src = x + (long)bc * 1024;
    float acc = 0.f;
#pragma unroll
    for (int t = 0; t < 8; t++) {
        int jy = min(max(jy0 + t, 0), 31);
        float r = 0.f;
#pragma unroll
        for (int u = 0; u < 8; u++) {
            int jx = min(max(jx0 + u, 0), 31);
            r += wx[u] * src[jy * 32 + jx];
        }
        acc += wy[t] * r;
    }
    y[idx] = acc;
}

// Z[b][c][j] = sum_I x[b][c][I] U[I][j]  (adjoint of 4x 1-D upsample)
__global__ void upadj2_k(const float* __restrict__ x1, const float* __restrict__ x2,
                         float* __restrict__ Z1, float* __restrict__ Z2)
{
    int gidx = blockIdx.x * 256 + threadIdx.x;
    if (gidx >= 262144) return;
    const float* x = gidx < 131072 ? x1 : x2;
    float* Z = gidx < 131072 ? Z1 : Z2;
    int idx = gidx & 131071;
    int j = idx & 255;
    int c = (idx >> 8) & 63;
    int b = idx >> 14;
    const float* xr = x + (long)b * 65536 + (long)c * 1024;

    float acc = 0.f;
    int Ilo = max(0, 4 * j - 8), Ihi = min(1023, 4 * j + 10);
    for (int I = Ilo; I <= Ihi; I++) {
        float sf = (I + 0.5f) * 0.25f - 0.5f;
        float fl = floorf(sf);
        float f  = sf - fl;
        int base = (int)fl - 1;
        int tt = j - base;
        if (tt < 0 || tt > 3) continue;
        float tot = 0.f, wsel = 0.f;
#pragma unroll
        for (int t = 0; t < 4; t++) {
            float w = keys_cubic(f + 1.f - t);
            int jj = base + t;
            if (jj < 0 || jj >= 256) w = 0.f;
            tot += w;
            if (t == tt) wsel = w;
        }
        acc += xr[I] * (wsel / tot);
    }
    Z[idx] = acc;
}

// W[b][I][c] = sum_t w_t(I) Y[b][base+t][c]
__global__ void upapply2_k(const float* __restrict__ Y1, const float* __restrict__ Y2,
                           float* __restrict__ W1, float* __restrict__ W2)
{
    int gidx = blockIdx.x * 256 + threadIdx.x;
    if (gidx >= 1048576) return;
    const float* Y = gidx < 524288 ? Y1 : Y2;
    float* Wo = gidx < 524288 ? W1 : W2;
    int idx = gidx & 524287;
    int c = idx & 63;
    int I = (idx >> 6) & 1023;
    int b = idx >> 16;

    float sf = (I + 0.5f) * 0.25f - 0.5f;
    float fl = floorf(sf);
    float f  = sf - fl;
    int base = (int)fl - 1;
    float w[4], tot = 0.f;
#pragma unroll
    for (int t = 0; t < 4; t++) {
        float ww = keys_cubic(f + 1.f - t);
        int jj = base + t;
        if (jj < 0 || jj >= 256) ww = 0.f;
        w[t] = ww; tot += ww;
    }
    float inv = 1.f / tot;
    const float* Yb = Y + (long)b * 16384;
    float acc = 0.f;
#pragma unroll
    for (int t = 0; t < 4; t++)
        if (w[t] != 0.f) acc += w[t] * Yb[(base + t) * 64 + c];
    Wo[idx] = acc * inv;
}

// ---------------------------------------------------------------------------
// BN stats for all four tensors in one launch (grid 256)
// ---------------------------------------------------------------------------
__global__ void bn_all_k(const float* __restrict__ CH1O, const float* __restrict__ CH2O,
                         const float* __restrict__ HW1OT, const float* __restrict__ HW2OT,
                         float* __restrict__ mv)
{
    int which = blockIdx.x >> 6, c = blockIdx.x & 63;
    const float* T = which == 0 ? CH1O : which == 1 ? CH2O : which == 2 ? HW1OT : HW2OT;
    bool tr = which >= 2;
    int t = threadIdx.x;
    float s = 0.f, s2 = 0.f;
    for (int i = t; i < 8192; i += 256) {
        float v = tr ? T[(long)(i >> 10) * 65536 + (long)(i & 1023) * 64 + c]
                     : T[(long)(i >> 10) * 65536 + c * 1024 + (i & 1023)];
        s += v; s2 += v * v;
    }
    __shared__ float sh1[8], sh2[8];
#pragma unroll
    for (int o = 16; o; o >>= 1) {
        s  += __shfl_xor_sync(0xffffffffu, s, o);
        s2 += __shfl_xor_sync(0xffffffffu, s2, o);
    }
    if ((t & 31) == 0) { sh1[t >> 5] = s; sh2[t >> 5] = s2; }
    __syncthreads();
    if (t == 0) {
        float ts = 0.f, ts2 = 0.f;
#pragma unroll
        for (int w = 0; w < 8; w++) { ts += sh1[w]; ts2 += sh2[w]; }
        float mean = ts * (1.f / 8192.f);
        float var  = ts2 * (1.f / 8192.f) - mean * mean;
        mv[which * 128 + c] = mean;
        mv[which * 128 + 64 + c] = fmaxf(var, 0.f);
    }
}

// ---------------------------------------------------------------------------
// Finalize: ch_o [B][C][HW]; hw_o transposed [B][HW][C]
// ---------------------------------------------------------------------------
__global__ void finalize_k(const float* __restrict__ x1, const float* __restrict__ x2,
                           const float* __restrict__ ch1o, const float* __restrict__ ch2o,
                           const float* __restrict__ hw1t, const float* __restrict__ hw2t,
                           const float* __restrict__ mv,
                           const float* __restrict__ gamma, const float* __restrict__ beta,
                           float* __restrict__ out)
{
    int idx = blockIdx.x * 256 + threadIdx.x;
    if (idx >= 524288) return;
    int c = (idx >> 10) & 63;
    long hwi = ((long)(idx >> 16)) * 65536 + (long)(idx & 1023) * 64 + c;
    float g = gamma[c], be = beta[c];

    float xa = x1[idx], xb = x2[idx];

    float v, r;
    v = (ch1o[idx] - mv[c])       * rsqrtf(mv[64 + c]  + 1e-5f) * g + be + xa;
    r = fmaxf(v, 0.f);
    v = (hw1t[hwi] - mv[256 + c]) * rsqrtf(mv[320 + c] + 1e-5f) * g + be + xa;
    out[idx] = 0.5f * (r + fmaxf(v, 0.f));

    v = (ch2o[idx] - mv[128 + c]) * rsqrtf(mv[192 + c] + 1e-5f) * g + be + xb;
    r = fmaxf(v, 0.f);
    v = (hw2t[hwi] - mv[384 + c]) * rsqrtf(mv[448 + c] + 1e-5f) * g + be + xb;
    out[524288 + idx] = 0.5f * (r + fmaxf(v, 0.f));
}

// ===========================================================================
extern "C" void kernel_launch(void* const* d_in, const int* in_sizes, int n_in,
                              void* d_out, int out_size)
{
    const float* x1     = (const float*)d_in[0];
    const float* x2     = (const float*)d_in[1];
    const float* w_down = (const float*)d_in[2];
    const float* b_down = (const float*)d_in[3];
    const float* w_up   = (const float*)d_in[4];
    const float* b_up   = (const float*)d_in[5];
    const float* gamma  = (const float*)d_in[6];
    const float* beta   = (const float*)d_in[7];
    float* out = (float*)d_out;

    float* base = nullptr;
    cudaGetSymbolAddress((void**)&base, g_buf);

    float* LB = base;                      // [8,1024,1024]
    float* S  = base + 8ll * 1024 * 1024;
    float* X1C   = S; S += 32768;    // [8,64,64]  (X1C,X2C,G12 contiguous)
    float* X2C   = S; S += 32768;
    float* G12   = S; S += 32768;
    float* GD    = S; S += 32768;
    float* CH1   = S; S += 32768;
    float* CH2   = S; S += 32768;
    float* CH1O  = S; S += 524288;   // [8,64,1024]
    float* CH2O  = S; S += 524288;
    float* XDN1  = S; S += 131072;   // [8,64,256]
    float* XDN2  = S; S += 131072;
    float* PD    = S; S += 131072;   // [8,64,256]
    float* LFD   = S; S += 524288;   // [8,256,256]
    float* AFD12 = S; S += 524288;
    float* AFD21T= S; S += 524288;   // col-softmax stored transposed
    float* Z1    = S; S += 131072;   // [8,64,256]
    float* Z2    = S; S += 131072;
    float* Y1    = S; S += 131072;   // [8,256,64]
    float* Y2    = S; S += 131072;
    float* W1    = S; S += 524288;   // [8,1024,64]
    float* W2    = S; S += 524288;
    float* HW1OT = S; S += 524288;
    float* HW2OT = S; S += 524288;
    float* PP    = S; S += 524288;   // [8,64,1024]
    float* RSM   = S; S += 8192;
    float* RSI   = S; S += 8192;
    float* CSM   = S; S += 8192;
    float* CSI   = S; S += 8192;
    float* R12   = S; S += 1024;     // rowsums [2][8][64]
    float* PART  = S; S += 786432;   // 192 x 4096 split-K partials
    float* MV    = S; S += 512;

    const int CHAN_SMEM = 30592 * 4;
    cudaFuncSetAttribute(chan_fused_k, cudaFuncAttributeMaxDynamicSharedMemorySize, CHAN_SMEM);

    // ---- grams + rowsums ----
    rowsum_k<<<16, 256>>>(x1, x2, R12);
    gramA_k<<<dim3(8, 24), 256>>>(x1, x2, PART);
    reduceA_k<<<384, 256>>>(PART, X1C);           // fills X1C, X2C, G12

    // ---- fused channel path ----
    chan_fused_k<<<8, 256, CHAN_SMEM>>>(X1C, X2C, R12, w_down, b_down, w_up, b_up, CH1, CH2);
    launch_gemm64(false, false, CH1, x1, CH1O, 64, 1024, 64, 4096, 65536, 65536, 8);
    launch_gemm64(false, false, CH2, x2, CH2O, 64, 1024, 64, 4096, 65536, 65536, 8);

    // ---- big logits via rank-64 factorization ----
    launch_gemm64(false, false, G12, x2, PP, 64, 1024, 64, 4096, 65536, 65536, 8);
    launch_gemm64(true,  false, x1, PP, LB, 1024, 1024, 64, 65536, 65536, 1048576, 8);
    row_stats_k<<<8192, 256>>>(LB, RSM, RSI);
    col_stats_k<<<dim3(16, 8), 256>>>(LB, CSM, CSI);

    // ---- downsampled attention (one direction; other is transpose) ----
    downsample2_k<<<1024, 256>>>(x1, x2, XDN1, XDN2);
    gram_k<<<dim3(2, 8), 256>>>(XDN1, XDN2, PART, 256, 128, 16384, 16384);
    gram_reduce_k<<<128, 256>>>(PART, GD, 2);
    launch_gemm64(false, false, GD, XDN2, PD, 64, 256, 64, 4096, 16384, 16384, 8);
    launch_gemm64(true,  false, XDN1, PD, LFD, 256, 256, 64, 16384, 16384, 65536, 8);
    row_softmax_k<<<2048, 256>>>(LFD, AFD12, 256);
    colsoftT_k<<<dim3(4, 8), 256>>>(LFD, AFD21T, 256);

    // ---- W = U (AFD (xU)^T) ----
    upadj2_k<<<1024, 256>>>(x1, x2, Z1, Z2);
    launch_gemm64(false, true, AFD12,  Z1, Y1, 256, 64, 256, 65536, 16384, 16384, 8);
    launch_gemm64(true,  true, AFD21T, Z2, Y2, 256, 64, 256, 65536, 16384, 16384, 8);
    upapply2_k<<<4096, 256>>>(Y1, Y2, W1, W2);

    // ---- fused softmax(L) @ W ----
    av_row_k<<<dim3(16, 8), 256>>>(LB, W1, RSM, RSI, HW1OT);
    av_col_k<<<dim3(16, 8), 256>>>(LB, W2, CSM, CSI, HW2OT);

    // ---- BN + residual + relu + average ----
    bn_all_k<<<256, 256>>>(CH1O, CH2O, HW1OT, HW2OT, MV);
    finalize_k<<<2048, 256>>>(x1, x2, CH1O, CH2O, HW1OT, HW2OT, MV, gamma, beta, out);
}

// round 10
// speedup vs baseline: 7.7394x; 1.0718x over previous
#include <cuda_runtime.h>
#include <math.h>

// ---------------------------------------------------------------------------
// B=8, C=64, HW=1024, D=32.
// L = x1^T (x1 x2^T) x2 ; LFD21 = LFD12^T ; X?CD via W·X?C·W^T identity;
// channel path fused (register-microtiled); HW outputs via fused softmax·W.
// ---------------------------------------------------------------------------
__device__ float g_buf[17ll * 1024 * 1024];

// ===========================================================================
// gemm64: C[b](MxN) = opA(A[b]) * opB(B[b]); tile 64x64, KT=16, 256 thr, 4x4.
// ===========================================================================
template <bool TA, bool TB>
__global__ void __launch_bounds__(256)
gemm64_kernel(const float* __restrict__ A, const float* __restrict__ B,
              float* __restrict__ C, int M, int N, int K, long sA, long sB, long sC)
{
    __shared__ float As[16][68];
    __shared__ float Bs[16][68];
    const int tid = threadIdx.x;
    const int m0 = blockIdx.y * 64, n0 = blockIdx.x * 64;
    const float* Ab = A + (long)blockIdx.z * sA;
    const float* Bb = B + (long)blockIdx.z * sB;
    float* Cb = C + (long)blockIdx.z * sC;
    const int rowt = (tid >> 4) * 4, colt = (tid & 15) * 4;
    float acc[4][4] = {};

    for (int k0 = 0; k0 < K; k0 += 16) {
        float4 av = {0,0,0,0}, bv = {0,0,0,0};
        if (!TA) {
            int r = tid >> 2, c = (tid & 3) * 4;
            if (m0 + r < M) av = *(const float4*)(Ab + (long)(m0 + r) * K + k0 + c);
            As[c+0][r]=av.x; As[c+1][r]=av.y; As[c+2][r]=av.z; As[c+3][r]=av.w;
        } else {
            int kr = tid >> 4, mc = (tid & 15) * 4;
            if (m0 + mc < M) av = *(const float4*)(Ab + (long)(k0 + kr) * M + m0 + mc);
            *(float4*)&As[kr][mc] = av;
        }
        if (!TB) {
            int kr = tid >> 4, nc = (tid & 15) * 4;
            if (n0 + nc < N) bv = *(const float4*)(Bb + (long)(k0 + kr) * N + n0 + nc);
            *(float4*)&Bs[kr][nc] = bv;
        } else {
            int r = tid >> 2, c = (tid & 3) * 4;
            if (n0 + r < N) bv = *(const float4*)(Bb + (long)(n0 + r) * K + k0 + c);
            Bs[c+0][r]=bv.x; Bs[c+1][r]=bv.y; Bs[c+2][r]=bv.z; Bs[c+3][r]=bv.w;
        }
        __syncthreads();
#pragma unroll
        for (int kk = 0; kk < 16; kk++) {
            float4 a = *(const float4*)&As[kk][rowt];
            float4 b = *(const float4*)&Bs[kk][colt];
            float ra[4] = {a.x,a.y,a.z,a.w}, rb[4] = {b.x,b.y,b.z,b.w};
#pragma unroll
            for (int i = 0; i < 4; i++)
#pragma unroll
                for (int j = 0; j < 4; j++) acc[i][j] += ra[i] * rb[j];
        }
        __syncthreads();
    }
    if (n0 + colt < N) {
#pragma unroll
        for (int i = 0; i < 4; i++) {
            int m = m0 + rowt + i;
            if (m < M)
                *(float4*)(Cb + (long)m * N + n0 + colt) =
                    make_float4(acc[i][0], acc[i][1], acc[i][2], acc[i][3]);
        }
    }
}

static void launch_gemm64(bool ta, bool tb,
                          const float* A, const float* B, float* C,
                          int M, int N, int K, long sA, long sB, long sC, int batch)
{
    dim3 grid((N + 63) / 64, (M + 63) / 64, batch);
    if (!ta && !tb)      gemm64_kernel<false,false><<<grid,256>>>(A,B,C,M,N,K,sA,sB,sC);
    else if (!ta && tb)  gemm64_kernel<false,true ><<<grid,256>>>(A,B,C,M,N,K,sA,sB,sC);
    else if (ta && !tb)  gemm64_kernel<true ,false><<<grid,256>>>(A,B,C,M,N,K,sA,sB,sC);
    else                 gemm64_kernel<true ,true ><<<grid,256>>>(A,B,C,M,N,K,sA,sB,sC);
}

// ===========================================================================
// trio_k: three M=64,N=1024,K=64 NN GEMMs in one launch.
//   z/8==0: CH1@x1 -> CH1O ; ==1: CH2@x2 -> CH2O ; ==2: G12@x2 -> PP
// grid (16, 24)
// ===========================================================================
__global__ void __launch_bounds__(256)
trio_k(const float* __restrict__ CH1, const float* __restrict__ CH2,
       const float* __restrict__ G12,
       const float* __restrict__ x1, const float* __restrict__ x2,
       float* __restrict__ CH1O, float* __restrict__ CH2O, float* __restrict__ PP)
{
    __shared__ float As[16][68];
    __shared__ float Bs[16][68];
    const int tid = threadIdx.x;
    const int z = blockIdx.y, pair = z >> 3, b = z & 7;
    const int n0 = blockIdx.x * 64;
    const float* Ab = (pair == 0 ? CH1 : pair == 1 ? CH2 : G12) + (long)b * 4096;
    const float* Bb = (pair == 0 ? x1 : x2) + (long)b * 65536;
    float* Cb = (pair == 0 ? CH1O : pair == 1 ? CH2O : PP) + (long)b * 65536;
    const int rowt = (tid >> 4) * 4, colt = (tid & 15) * 4;
    float acc[4][4] = {};

    for (int k0 = 0; k0 < 64; k0 += 16) {
        {
            int r = tid >> 2, c = (tid & 3) * 4;
            float4 av = *(const float4*)(Ab + r * 64 + k0 + c);
            As[c+0][r]=av.x; As[c+1][r]=av.y; As[c+2][r]=av.z; As[c+3][r]=av.w;
        }
        {
            int kr = tid >> 4, nc = (tid & 15) * 4;
            float4 bv = *(const float4*)(Bb + (long)(k0 + kr) * 1024 + n0 + nc);
            *(float4*)&Bs[kr][nc] = bv;
        }
        __syncthreads();
#pragma unroll
        for (int kk = 0; kk < 16; kk++) {
            float4 a = *(const float4*)&As[kk][rowt];
            float4 bq = *(const float4*)&Bs[kk][colt];
            float ra[4] = {a.x,a.y,a.z,a.w}, rb[4] = {bq.x,bq.y,bq.z,bq.w};
#pragma unroll
            for (int i = 0; i < 4; i++)
#pragma unroll
                for (int j = 0; j < 4; j++) acc[i][j] += ra[i] * rb[j];
        }
        __syncthreads();
    }
#pragma unroll
    for (int i = 0; i < 4; i++)
        *(float4*)(Cb + (long)(rowt + i) * 1024 + n0 + colt) =
            make_float4(acc[i][0], acc[i][1], acc[i][2], acc[i][3]);
}

// ===========================================================================
// gramA: 3 pairs {x1x1, x2x2, x1x2} x 8 batches x 8 k-splits. grid (8, 24).
// ===========================================================================
__global__ void __launch_bounds__(256)
gramA_k(const float* __restrict__ x1, const float* __restrict__ x2, float* __restrict__ P)
{
    __shared__ float Xs[16][68], Ys[16][68];
    const int tid = threadIdx.x;
    const int pz = blockIdx.y, pair = pz >> 3, b = pz & 7;
    const float* Xb = ((pair == 1) ? x2 : x1) + (long)b * 65536;
    const float* Yb = ((pair == 0) ? x1 : x2) + (long)b * 65536;
    const int kbase = blockIdx.x * 128;
    const int rowt = (tid >> 4) * 4, colt = (tid & 15) * 4;
    const int r = tid >> 2, c = (tid & 3) * 4;
    float acc[4][4] = {};

    for (int k0 = kbase; k0 < kbase + 128; k0 += 16) {
        float4 xv = *(const float4*)(Xb + (long)r * 1024 + k0 + c);
        float4 yv = *(const float4*)(Yb + (long)r * 1024 + k0 + c);
        Xs[c+0][r]=xv.x; Xs[c+1][r]=xv.y; Xs[c+2][r]=xv.z; Xs[c+3][r]=xv.w;
        Ys[c+0][r]=yv.x; Ys[c+1][r]=yv.y; Ys[c+2][r]=yv.z; Ys[c+3][r]=yv.w;
        __syncthreads();
#pragma unroll
        for (int kk = 0; kk < 16; kk++) {
            float4 a = *(const float4*)&Xs[kk][rowt];
            float4 bq = *(const float4*)&Ys[kk][colt];
            float ra[4]={a.x,a.y,a.z,a.w}, rb[4]={bq.x,bq.y,bq.z,bq.w};
#pragma unroll
            for (int i = 0; i < 4; i++)
#pragma unroll
                for (int j = 0; j < 4; j++) acc[i][j] += ra[i] * rb[j];
        }
        __syncthreads();
    }
    float* Pp = P + ((long)pz * 8 + blockIdx.x) * 4096;
#pragma unroll
    for (int i = 0; i < 4; i++)
        *(float4*)(Pp + (rowt + i) * 64 + colt) =
            make_float4(acc[i][0], acc[i][1], acc[i][2], acc[i][3]);
}

__global__ void reduceA_k(const float* __restrict__ P, float* __restrict__ O)
{
    int idx = blockIdx.x * 256 + threadIdx.x;   // < 98304
    int pz = idx >> 12, e = idx & 4095;
    float s = 0.f;
#pragma unroll
    for (int k = 0; k < 8; k++) s += P[((long)pz * 8 + k) * 4096 + e];
    O[idx] = s;
}

// Generic split-K gram (GD): grid (nsplit, batch), M=N=64
__global__ void __launch_bounds__(256)
gram_k(const float* __restrict__ X, const float* __restrict__ Y,
       float* __restrict__ P, int K, int klen, long sX, long sY)
{
    __shared__ float Xs[16][68], Ys[16][68];
    const int tid = threadIdx.x;
    const float* Xb = X + (long)blockIdx.y * sX;
    const float* Yb = Y + (long)blockIdx.y * sY;
    const int kbase = blockIdx.x * klen;
    const int rowt = (tid >> 4) * 4, colt = (tid & 15) * 4;
    const int r = tid >> 2, c = (tid & 3) * 4;
    float acc[4][4] = {};

    for (int k0 = kbase; k0 < kbase + klen; k0 += 16) {
        float4 xv = *(const float4*)(Xb + (long)r * K + k0 + c);
        float4 yv = *(const float4*)(Yb + (long)r * K + k0 + c);
        Xs[c+0][r]=xv.x; Xs[c+1][r]=xv.y; Xs[c+2][r]=xv.z; Xs[c+3][r]=xv.w;
        Ys[c+0][r]=yv.x; Ys[c+1][r]=yv.y; Ys[c+2][r]=yv.z; Ys[c+3][r]=yv.w;
        __syncthreads();
#pragma unroll
        for (int kk = 0; kk < 16; kk++) {
            float4 a = *(const float4*)&Xs[kk][rowt];
            float4 bq = *(const float4*)&Ys[kk][colt];
            float ra[4]={a.x,a.y,a.z,a.w}, rb[4]={bq.x,bq.y,bq.z,bq.w};
#pragma unroll
            for (int i = 0; i < 4; i++)
#pragma unroll
                for (int j = 0; j < 4; j++) acc[i][j] += ra[i] * rb[j];
        }
        __syncthreads();
    }
    float* Pp = P + ((long)blockIdx.y * gridDim.x + blockIdx.x) * 4096;
#pragma unroll
    for (int i = 0; i < 4; i++)
        *(float4*)(Pp + (rowt + i) * 64 + colt) =
            make_float4(acc[i][0], acc[i][1], acc[i][2], acc[i][3]);
}

__global__ void gram_reduce_k(const float* __restrict__ P, float* __restrict__ C, int nsplit)
{
    int idx = blockIdx.x * 256 + threadIdx.x;
    if (idx >= 32768) return;
    int b = idx >> 12, e = idx & 4095;
    float s = 0.f;
    for (int k = 0; k < nsplit; k++) s += P[((long)b * nsplit + k) * 4096 + e];
    C[idx] = s;
}

// ---------------------------------------------------------------------------
// Row sums of x1/x2 per (batch, channel)
// ---------------------------------------------------------------------------
__global__ void rowsum_k(const float* __restrict__ x1, const float* __restrict__ x2,
                         float* __restrict__ r)
{
    int which = blockIdx.x >> 3, b = blockIdx.x & 7;
    const float* xb = (which ? x2 : x1) + (long)b * 65536;
    int w = threadIdx.x >> 5, lane = threadIdx.x & 31;
    for (int rr = w * 8; rr < w * 8 + 8; rr++) {
        float s = 0.f;
        for (int p = lane; p < 1024; p += 32) s += xb[rr * 1024 + p];
#pragma unroll
        for (int o = 16; o; o >>= 1) s += __shfl_xor_sync(0xffffffffu, s, o);
        if (lane == 0) r[which * 512 + b * 64 + rr] = s;
    }
}

// ===========================================================================
// smm: in-smem matmul with 256 threads, per-thread (M/16)x(N/16) microtile.
//   C[M][N](ldc) = A[M][K](lda) * op(B)  [+ bias[m]]  [* rscale[m] at store]
//   BT=false: B[K][N](ldb) ; BT=true: B[N][K](ldb)
// ===========================================================================
template<int M, int N, int K, bool BT>
__device__ __forceinline__ void smm(const float* __restrict__ A, int lda,
                                    const float* __restrict__ B, int ldb,
                                    float* __restrict__ C, int ldc,
                                    const float* __restrict__ bias,
                                    const float* __restrict__ rscale, int t)
{
    constexpr int RM = M / 16, RN = N / 16;
    const int r0 = (t >> 4) * RM, c0 = (t & 15) * RN;
    float acc[RM][RN];
#pragma unroll
    for (int i = 0; i < RM; i++) {
        float bv = bias ? bias[r0 + i] : 0.f;
#pragma unroll
        for (int j = 0; j < RN; j++) acc[i][j] = bv;
    }
#pragma unroll 4
    for (int k = 0; k < K; k++) {
        float a[RM], b[RN];
#pragma unroll
        for (int i = 0; i < RM; i++) a[i] = A[(r0 + i) * lda + k];
#pragma unroll
        for (int j = 0; j < RN; j++) b[j] = BT ? B[(c0 + j) * ldb + k] : B[k * ldb + c0 + j];
#pragma unroll
        for (int i = 0; i < RM; i++)
#pragma unroll
            for (int j = 0; j < RN; j++) acc[i][j] += a[i] * b[j];
    }
#pragma unroll
    for (int i = 0; i < RM; i++) {
        float sc = rscale ? rscale[r0 + i] : 1.f;
#pragma unroll
        for (int j = 0; j < RN; j++) C[(r0 + i) * ldc + c0 + j] = acc[i][j] * sc;
    }
}

// ===========================================================================
// Fused channel path: one block per batch, register-microtiled stages.
// ===========================================================================
__global__ void __launch_bounds__(256)
chan_fused_k(const float* __restrict__ X1C_g, const float* __restrict__ X2C_g,
             const float* __restrict__ rsum,
             const float* __restrict__ w_down, const float* __restrict__ b_down,
             const float* __restrict__ w_up, const float* __restrict__ b_up,
             float* __restrict__ CH1_g, float* __restrict__ CH2_g)
{
    extern __shared__ float sm[];
    float* A   = sm;              // 64x68  X1C -> U1T
    float* Bf  = A   + 4352;      // 64x68  X2C -> U2T
    float* LC  = Bf  + 4352;      // 64x68  LC -> E12
    float* E2  = LC  + 4352;      // 64x68
    float* Wd  = E2  + 4352;      // 32x64
    float* Wu  = Wd  + 2048;      // 64x32
    float* Mb  = Wu  + 2048;      // 32x68
    float* C1d = Mb  + 2176;      // 32x36
    float* C2d = C1d + 1152;
    float* LCD = C2d + 1152;
    float* A12d= LCD + 1152;
    float* A21d= A12d+ 1152;
    float* TT  = A21d+ 1152;      // 64x36
    float* bd  = TT  + 2304;      // 32
    float* bu  = bd  + 32;        // 64
    float* u1  = bu  + 64;        // 32
    float* u2  = u1  + 32;        // 32
    float* st  = u2  + 32;        // 256

    const int b = blockIdx.x, t = threadIdx.x;

    for (int i = t; i < 4096; i += 256) {
        A [(i >> 6) * 68 + (i & 63)] = X1C_g[b * 4096 + i];
        Bf[(i >> 6) * 68 + (i & 63)] = X2C_g[b * 4096 + i];
    }
    for (int i = t; i < 2048; i += 256) { Wd[i] = w_down[i]; Wu[i] = w_up[i]; }
    if (t < 32) bd[t] = b_down[t];
    if (t < 64) bu[t] = b_up[t];
    __syncthreads();

    // u = Wd * rowsum
    if (t < 64) {
        int d = t & 31, which = t >> 5;
        const float* r = rsum + which * 512 + b * 64;
        float s = 0.f;
        for (int c = 0; c < 64; c++) s += Wd[d * 64 + c] * r[c];
        (which ? u2 : u1)[d] = s;
    }
    __syncthreads();

    // C1d = Wd X1C Wd^T (+rank-1 terms)
    smm<32, 64, 64, false>(Wd, 64, A, 68, Mb, 68, nullptr, nullptr, t);
    __syncthreads();
    smm<32, 32, 64, true >(Mb, 68, Wd, 64, C1d, 36, nullptr, nullptr, t);
    __syncthreads();
    for (int o = t; o < 1024; o += 256) {
        int d = o >> 5, e = o & 31;
        C1d[d * 36 + e] += bd[d]*u1[e] + bd[e]*u1[d] + 1024.f*bd[d]*bd[e];
    }
    __syncthreads();
    // C2d
    smm<32, 64, 64, false>(Wd, 64, Bf, 68, Mb, 68, nullptr, nullptr, t);
    __syncthreads();
    smm<32, 32, 64, true >(Mb, 68, Wd, 64, C2d, 36, nullptr, nullptr, t);
    __syncthreads();
    for (int o = t; o < 1024; o += 256) {
        int d = o >> 5, e = o & 31;
        C2d[d * 36 + e] += bd[d]*u2[e] + bd[e]*u2[d] + 1024.f*bd[d]*bd[e];
    }
    __syncthreads();

    // LC = X1C X2C ; LCD = C1d C2d
    smm<64, 64, 64, false>(A, 68, Bf, 68, LC, 68, nullptr, nullptr, t);
    smm<32, 32, 32, false>(C1d, 36, C2d, 36, LCD, 36, nullptr, nullptr, t);
    __syncthreads();

    // stats + small softmaxes
    if (t < 64) {                   // LC row stats
        float m = -3.4e38f;
        for (int j = 0; j < 64; j++) m = fmaxf(m, LC[t * 68 + j]);
        float s = 0.f;
        for (int j = 0; j < 64; j++) s += __expf(LC[t * 68 + j] - m);
        st[t] = m; st[64 + t] = 1.f / s;
    } else if (t < 128) {           // LC col stats
        int i = t - 64;
        float m = -3.4e38f;
        for (int j = 0; j < 64; j++) m = fmaxf(m, LC[j * 68 + i]);
        float s = 0.f;
        for (int j = 0; j < 64; j++) s += __expf(LC[j * 68 + i] - m);
        st[128 + i] = m; st[192 + i] = 1.f / s;
    } else if (t < 160) {           // LCD row softmax -> A12d
        int i = t - 128;
        float m = -3.4e38f;
        for (int j = 0; j < 32; j++) m = fmaxf(m, LCD[i * 36 + j]);
        float s = 0.f;
        for (int j = 0; j < 32; j++) s += __expf(LCD[i * 36 + j] - m);
        float inv = 1.f / s;
        for (int j = 0; j < 32; j++) A12d[i * 36 + j] = __expf(LCD[i * 36 + j] - m) * inv;
    } else if (t < 192) {           // LCD col softmax -> A21d
        int i = t - 160;
        float m = -3.4e38f;
        for (int j = 0; j < 32; j++) m = fmaxf(m, LCD[j * 36 + i]);
        float s = 0.f;
        for (int j = 0; j < 32; j++) s += __expf(LCD[j * 36 + i] - m);
        float inv = 1.f / s;
        for (int j = 0; j < 32; j++) A21d[i * 36 + j] = __expf(LCD[j * 36 + i] - m) * inv;
    }
    __syncthreads();

    // E2[i][j] = exp(LC[j][i] - cm_i), then E12 in place
    for (int o = t; o < 4096; o += 256) {
        int i = o >> 6, j = o & 63;
        E2[i * 68 + j] = __expf(LC[j * 68 + i] - st[128 + i]);
    }
    __syncthreads();
    for (int o = t; o < 4096; o += 256) {
        int i = o >> 6, j = o & 63;
        LC[i * 68 + j] = __expf(LC[i * 68 + j] - st[i]);
    }
    __syncthreads();

    // ConvUp dir1: TT = Wu A12d + bu ; U1T[m][i] = bu[m] + sum_k Wu[m][k] TT[i][k]
    smm<64, 32, 32, false>(Wu, 32, A12d, 36, TT, 36, bu, nullptr, t);
    __syncthreads();
    smm<64, 64, 32, true >(Wu, 32, TT, 36, A, 68, bu, nullptr, t);
    __syncthreads();
    // ConvUp dir2
    smm<64, 32, 32, false>(Wu, 32, A21d, 36, TT, 36, bu, nullptr, t);
    __syncthreads();
    smm<64, 64, 32, true >(Wu, 32, TT, 36, Bf, 68, bu, nullptr, t);
    __syncthreads();

    // CH1 = diag(rsInv) E12 U1T^T ; CH2 = diag(csInv) E2 U2T^T  (to global)
    smm<64, 64, 64, true>(LC, 68, A, 68, CH1_g + b * 4096, 64, nullptr, st + 64, t);
    smm<64, 64, 64, true>(E2, 68, Bf, 68, CH2_g + b * 4096, 64, nullptr, st + 192, t);
}

// ---------------------------------------------------------------------------
// Row softmax (materializing), width N
// ---------------------------------------------------------------------------
__global__ void row_softmax_k(const float* __restrict__ L, float* __restrict__ A, int N)
{
    long row = blockIdx.x;
    const float* p = L + row * (long)N;
    float* q = A + row * (long)N;
    int t = threadIdx.x;
    __shared__ float sh[8];

    float m = -3.4e38f;
    for (int i = t; i < N; i += 256) m = fmaxf(m, p[i]);
#pragma unroll
    for (int o = 16; o; o >>= 1) m = fmaxf(m, __shfl_xor_sync(0xffffffffu, m, o));
    if ((t & 31) == 0) sh[t >> 5] = m;
    __syncthreads();
    float mm = sh[0];
#pragma unroll
    for (int w = 1; w < 8; w++) mm = fmaxf(mm, sh[w]);
    __syncthreads();

    float s = 0.f;
    for (int i = t; i < N; i += 256) s += __expf(p[i] - mm);
#pragma unroll
    for (int o = 16; o; o >>= 1) s += __shfl_xor_sync(0xffffffffu, s, o);
    if ((t & 31) == 0) sh[t >> 5] = s;
    __syncthreads();
    float ss = 0.f;
#pragma unroll
    for (int w = 0; w < 8; w++) ss += sh[w];
    float inv = 1.f / ss;

    for (int i = t; i < N; i += 256) q[i] = __expf(p[i] - mm) * inv;
}

// Column softmax written TRANSPOSED
__global__ void colsoftT_k(const float* __restrict__ L, float* __restrict__ AT, int N)
{
    int cc = threadIdx.x & 63;
    int kg = threadIdx.x >> 6;
    int i  = blockIdx.x * 64 + cc;
    const float* Lb = L  + (long)blockIdx.y * N * N;
    float*       Ab = AT + (long)blockIdx.y * N * N;
    __shared__ float red[4][64];

    float m = -3.4e38f;
    for (int k = kg; k < N; k += 4) m = fmaxf(m, Lb[k * N + i]);
    red[kg][cc] = m;
    __syncthreads();
    m = fmaxf(fmaxf(red[0][cc], red[1][cc]), fmaxf(red[2][cc], red[3][cc]));
    __syncthreads();

    float s = 0.f;
    for (int k = kg; k < N; k += 4) s += __expf(Lb[k * N + i] - m);
    red[kg][cc] = s;
    __syncthreads();
    s = red[0][cc] + red[1][cc] + red[2][cc] + red[3][cc];
    float inv = 1.f / s;

    for (int k = kg; k < N; k += 4)
        Ab[k * N + i] = __expf(Lb[k * N + i] - m) * inv;
}

// ---------------------------------------------------------------------------
// LB stats
// ---------------------------------------------------------------------------
__global__ void row_stats_k(const float* __restrict__ L,
                            float* __restrict__ Mo, float* __restrict__ Io)
{
    long row = blockIdx.x;
    const float* p = L + row * 1024;
    int t = threadIdx.x;
    __shared__ float sh[8];

    float m = -3.4e38f;
    for (int i = t; i < 1024; i += 256) m = fmaxf(m, p[i]);
#pragma unroll
    for (int o = 16; o; o >>= 1) m = fmaxf(m, __shfl_xor_sync(0xffffffffu, m, o));
    if ((t & 31) == 0) sh[t >> 5] = m;
    __syncthreads();
    float mm = sh[0];
#pragma unroll
    for (int w = 1; w < 8; w++) mm = fmaxf(mm, sh[w]);
    __syncthreads();

    float s = 0.f;
    for (int i = t; i < 1024; i += 256) s += __expf(p[i] - mm);
#pragma unroll
    for (int o = 16; o; o >>= 1) s += __shfl_xor_sync(0xffffffffu, s, o);
    if ((t & 31) == 0) sh[t >> 5] = s;
    __syncthreads();
    if (t == 0) {
        float ss = 0.f;
#pragma unroll
        for (int w = 0; w < 8; w++) ss += sh[w];
        Mo[row] = mm;
        Io[row] = 1.f / ss;
    }
}

__global__ void col_stats_k(const float* __restrict__ L,
                            float* __restrict__ Mo, float* __restrict__ Io)
{
    int cc = threadIdx.x & 63;
    int kg = threadIdx.x >> 6;
    int i  = blockIdx.x * 64 + cc;
    const float* Lb = L + (long)blockIdx.y * 1048576;
    __shared__ float red[4][64];

    float m = -3.4e38f;
    for (int k = kg; k < 1024; k += 4) m = fmaxf(m, Lb[(k << 10) + i]);
    red[kg][cc] = m;
    __syncthreads();
    m = fmaxf(fmaxf(red[0][cc], red[1][cc]), fmaxf(red[2][cc], red[3][cc]));
    __syncthreads();

    float s = 0.f;
    for (int k = kg; k < 1024; k += 4) s += __expf(Lb[(k << 10) + i] - m);
    red[kg][cc] = s;
    __syncthreads();
    if (kg == 0) {
        float ss = red[0][cc] + red[1][cc] + red[2][cc] + red[3][cc];
        Mo[blockIdx.y * 1024 + i] = m;
        Io[blockIdx.y * 1024 + i] = 1.f / ss;
    }
}

// ===========================================================================
// Fused softmax(L)·W
// ===========================================================================
__global__ void __launch_bounds__(256)
av_row_k(const float* __restrict__ L, const float* __restrict__ W,
         const float* __restrict__ Ms, const float* __restrict__ Is,
         float* __restrict__ O)
{
    __shared__ float Ls[16][68], Ws[16][68];
    __shared__ float smx[64], sin[64];
    const int tid = threadIdx.x;
    const int b = blockIdx.y, m0 = blockIdx.x * 64;
    if (tid < 64) { smx[tid] = Ms[b * 1024 + m0 + tid]; sin[tid] = Is[b * 1024 + m0 + tid]; }
    __syncthreads();
    const float* Lb = L + (long)b * 1048576;
    const float* Wb = W + (long)b * 65536;
    const int rowt = (tid >> 4) * 4, colt = (tid & 15) * 4;
    const int r = tid >> 2, c = (tid & 3) * 4;
    const int kr = tid >> 4, nc = (tid & 15) * 4;
    float acc[4][4] = {};

    for (int k0 = 0; k0 < 1024; k0 += 16) {
        float4 v = *(const float4*)(Lb + (long)(m0 + r) * 1024 + k0 + c);
        float mr = smx[r];
        Ls[c+0][r] = __expf(v.x - mr);
        Ls[c+1][r] = __expf(v.y - mr);
        Ls[c+2][r] = __expf(v.z - mr);
        Ls[c+3][r] = __expf(v.w - mr);
        *(float4*)&Ws[kr][nc] = *(const float4*)(Wb + (long)(k0 + kr) * 64 + nc);
        __syncthreads();
#pragma unroll
        for (int kk = 0; kk < 16; kk++) {
            float4 a = *(const float4*)&Ls[kk][rowt];
            float4 w = *(const float4*)&Ws[kk][colt];
            float ra[4]={a.x,a.y,a.z,a.w}, rb[4]={w.x,w.y,w.z,w.w};
#pragma unroll
            for (int i = 0; i < 4; i++)
#pragma unroll
                for (int j = 0; j < 4; j++) acc[i][j] += ra[i] * rb[j];
        }
        __syncthreads();
    }
    float* Ob = O + (long)b * 65536;
#pragma unroll
    for (int i = 0; i < 4; i++) {
        float sc = sin[rowt + i];
        *(float4*)(Ob + (long)(m0 + rowt + i) * 64 + colt) =
            make_float4(acc[i][0]*sc, acc[i][1]*sc, acc[i][2]*sc, acc[i][3]*sc);
    }
}

__global__ void __launch_bounds__(256)
av_col_k(const float* __restrict__ L, const float* __restrict__ W,
         const float* __restrict__ Ms, const float* __restrict__ Is,
         float* __restrict__ O)
{
    __shared__ float Ls[16][68], Ws[16][68];
    __shared__ float smx[64], sin[64];
    const int tid = threadIdx.x;
    const int b = blockIdx.y, m0 = blockIdx.x * 64;
    if (tid < 64) { smx[tid] = Ms[b * 1024 + m0 + tid]; sin[tid] = Is[b * 1024 + m0 + tid]; }
    __syncthreads();
    const float* Lb = L + (long)b * 1048576;
    const float* Wb = W + (long)b * 65536;
    const int rowt = (tid >> 4) * 4, colt = (tid & 15) * 4;
    const int kr = tid >> 4, mc = (tid & 15) * 4;
    float acc[4][4] = {};

    for (int k0 = 0; k0 < 1024; k0 += 16) {
        float4 v = *(const float4*)(Lb + (long)(k0 + kr) * 1024 + m0 + mc);
        float4 e = make_float4(__expf(v.x - smx[mc+0]), __expf(v.y - smx[mc+1]),
                               __expf(v.z - smx[mc+2]), __expf(v.w - smx[mc+3]));
        *(float4*)&Ls[kr][mc] = e;
        *(float4*)&Ws[kr][mc] = *(const float4*)(Wb + (long)(k0 + kr) * 64 + mc);
        __syncthreads();
#pragma unroll
        for (int kk = 0; kk < 16; kk++) {
            float4 a = *(const float4*)&Ls[kk][rowt];
            float4 w = *(const float4*)&Ws[kk][colt];
            float ra[4]={a.x,a.y,a.z,a.w}, rb[4]={w.x,w.y,w.z,w.w};
#pragma unroll
            for (int i = 0; i < 4; i++)
#pragma unroll
                for (int j = 0; j < 4; j++) acc[i][j] += ra[i] * rb[j];
        }
        __syncthreads();
    }
    float* Ob = O + (long)b * 65536;
#pragma unroll
    for (int i = 0; i < 4; i++) {
        float sc = sin[rowt + i];
        *(float4*)(Ob + (long)(m0 + rowt + i) * 64 + colt) =
            make_float4(acc[i][0]*sc, acc[i][1]*sc, acc[i][2]*sc, acc[i][3]*sc);
    }
}

// ---------------------------------------------------------------------------
// Keys cubic + merged resampling (downsample both + upsample-adjoint both)
// ---------------------------------------------------------------------------
__device__ __forceinline__ float keys_cubic(float x)
{
    x = fabsf(x);
    if (x < 1.f) return ((1.5f * x - 2.5f) * x) * x + 1.f;
    if (x < 2.f) return ((-0.5f * x + 2.5f) * x - 4.f) * x + 2.f;
    return 0.f;
}

__global__ void resample_k(const float* __restrict__ x1, const float* __restrict__ x2,
                           float* __restrict__ y1, float* __restrict__ y2,
                           float* __restrict__ Z1, float* __restrict__ Z2)
{
    int gidx = blockIdx.x * 256 + threadIdx.x;
    if (gidx < 262144) {
        // 2-D bicubic downsample (8-tap AA, edge-renormalized)
        const float* x = gidx < 131072 ? x1 : x2;
        float* y = gidx < 131072 ? y1 : y2;
        int idx = gidx & 131071;
        int ox = idx & 15;
        int oy = (idx >> 4) & 15;
        int bc = idx >> 8;

        int jy0 = 2 * oy - 3, jx0 = 2 * ox - 3;
        float wy[8], wx[8];
        float sy = 0.f, sx = 0.f;
#pragma unroll
        for (int t = 0; t < 8; t++) {
            float w = keys_cubic(fabsf(3.5f - t) * 0.5f);
            int jy = jy0 + t;
            wy[t] = (jy >= 0 && jy < 32) ? w : 0.f; sy += wy[t];
            int jx = jx0 + t;
            wx[t] = (jx >= 0 && jx < 32) ? w : 0.f; sx += wx[t];
        }
        float iy = 1.f / sy, ix = 1.f / sx;
#pragma unroll
        for (int t = 0; t < 8; t++) { wy[t] *= iy; wx[t] *= ix; }

        const float* src = x + (long)bc * 1024;
        float acc = 0.f;
#pragma unroll
        for (int t = 0; t < 8; t++) {
            int jy = min(max(jy0 + t, 0), 31);
            float r = 0.f;
#pragma unroll
            for (int u = 0; u < 8; u++) {
                int jx = min(max(jx0 + u, 0), 31);
                r += wx[u] * src[jy * 32 + jx];
            }
            acc += wy[t] * r;
        }
        y[idx] = acc;
    } else if (gidx < 524288) {
        // upsample adjoint: Z[b][c][j] = sum_I x[b][c][I] U[I][j]
        int g2 = gidx - 262144;
        const float* x = g2 < 131072 ? x1 : x2;
        float* Z = g2 < 131072 ? Z1 : Z2;
        int idx = g2 & 131071;
        int j = idx & 255;
        int c = (idx >> 8) & 63;
        int b = idx >> 14;
        const float* xr = x + (long)b * 65536 + (long)c * 1024;

        float acc = 0.f;
        int Ilo = max(0, 4 * j - 8), Ihi = min(1023, 4 * j + 10);
        for (int I = Ilo; I <= Ihi; I++) {
            float sf = (I + 0.5f) * 0.25f - 0.5f;
            float fl = floorf(sf);
            float f  = sf - fl;
            int base = (int)fl - 1;
            int tt = j - base;
            if (tt < 0 || tt > 3) continue;
            float tot = 0.f, wsel = 0.f;
#pragma unroll
            for (int t = 0; t < 4; t++) {
                float w = keys_cubic(f + 1.f - t);
                int jj = base + t;
                if (jj < 0 || jj >= 256) w = 0.f;
                tot += w;
                if (t == tt) wsel = w;
            }
            acc += xr[I] * (wsel / tot);
        }
        Z[idx] = acc;
    }
}

// W[b][I][c] = sum_t w_t(I) Y[b][base+t][c]
__global__ void upapply2_k(const float* __restrict__ Y1, const float* __restrict__ Y2,
                           float* __restrict__ W1, float* __restrict__ W2)
{
    int gidx = blockIdx.x * 256 + threadIdx.x;
    if (gidx >= 1048576) return;
    const float* Y = gidx < 524288 ? Y1 : Y2;
    float* Wo = gidx < 524288 ? W1 : W2;
    int idx = gidx & 524287;
    int c = idx & 63;
    int I = (idx >> 6) & 1023;
    int b = idx >> 16;

    float sf = (I + 0.5f) * 0.25f - 0.5f;
    float fl = floorf(sf);
    float f  = sf - fl;
    int base = (int)fl - 1;
    float w[4], tot = 0.f;
#pragma unroll
    for (int t = 0; t < 4; t++) {
        float ww = keys_cubic(f + 1.f - t);
        int jj = base + t;
        if (jj < 0 || jj >= 256) ww = 0.f;
        w[t] = ww; tot += ww;
    }
    float inv = 1.f / tot;
    const float* Yb = Y + (long)b * 16384;
    float acc = 0.f;
#pragma unroll
    for (int t = 0; t < 4; t++)
        if (w[t] != 0.f) acc += w[t] * Yb[(base + t) * 64 + c];
    Wo[idx] = acc * inv;
}

// ---------------------------------------------------------------------------
// BN stats for all four tensors (grid 256)
// ---------------------------------------------------------------------------
__global__ void bn_all_k(const float* __restrict__ CH1O, const float* __restrict__ CH2O,
                         const float* __restrict__ HW1OT, const float* __restrict__ HW2OT,
                         float* __restrict__ mv)
{
    int which = blockIdx.x >> 6, c = blockIdx.x & 63;
    const float* T = which == 0 ? CH1O : which == 1 ? CH2O : which == 2 ? HW1OT : HW2OT;
    bool tr = which >= 2;
    int t = threadIdx.x;
    float s = 0.f, s2 = 0.f;
    for (int i = t; i < 8192; i += 256) {
        float v = tr ? T[(long)(i >> 10) * 65536 + (long)(i & 1023) * 64 + c]
                     : T[(long)(i >> 10) * 65536 + c * 1024 + (i & 1023)];
        s += v; s2 += v * v;
    }
    __shared__ float sh1[8], sh2[8];
#pragma unroll
    for (int o = 16; o; o >>= 1) {
        s  += __shfl_xor_sync(0xffffffffu, s, o);
        s2 += __shfl_xor_sync(0xffffffffu, s2, o);
    }
    if ((t & 31) == 0) { sh1[t >> 5] = s; sh2[t >> 5] = s2; }
    __syncthreads();
    if (t == 0) {
        float ts = 0.f, ts2 = 0.f;
#pragma unroll
        for (int w = 0; w < 8; w++) { ts += sh1[w]; ts2 += sh2[w]; }
        float mean = ts * (1.f / 8192.f);
        float var  = ts2 * (1.f / 8192.f) - mean * mean;
        mv[which * 128 + c] = mean;
        mv[which * 128 + 64 + c] = fmaxf(var, 0.f);
    }
}

// ---------------------------------------------------------------------------
// Finalize
// ---------------------------------------------------------------------------
__global__ void finalize_k(const float* __restrict__ x1, const float* __restrict__ x2,
                           const float* __restrict__ ch1o, const float* __restrict__ ch2o,
                           const float* __restrict__ hw1t, const float* __restrict__ hw2t,
                           const float* __restrict__ mv,
                           const float* __restrict__ gamma, const float* __restrict__ beta,
                           float* __restrict__ out)
{
    int idx = blockIdx.x * 256 + threadIdx.x;
    if (idx >= 524288) return;
    int c = (idx >> 10) & 63;
    long hwi = ((long)(idx >> 16)) * 65536 + (long)(idx & 1023) * 64 + c;
    float g = gamma[c], be = beta[c];

    float xa = x1[idx], xb = x2[idx];

    float v, r;
    v = (ch1o[idx] - mv[c])       * rsqrtf(mv[64 + c]  + 1e-5f) * g + be + xa;
    r = fmaxf(v, 0.f);
    v = (hw1t[hwi] - mv[256 + c]) * rsqrtf(mv[320 + c] + 1e-5f) * g + be + xa;
    out[idx] = 0.5f * (r + fmaxf(v, 0.f));

    v = (ch2o[idx] - mv[128 + c]) * rsqrtf(mv[192 + c] + 1e-5f) * g + be + xb;
    r = fmaxf(v, 0.f);
    v = (hw2t[hwi] - mv[384 + c]) * rsqrtf(mv[448 + c] + 1e-5f) * g + be + xb;
    out[524288 + idx] = 0.5f * (r + fmaxf(v, 0.f));
}

// ===========================================================================
extern "C" void kernel_launch(void* const* d_in, const int* in_sizes, int n_in,
                              void* d_out, int out_size)
{
    const float* x1     = (const float*)d_in[0];
    const float* x2     = (const float*)d_in[1];
    const float* w_down = (const float*)d_in[2];
    const float* b_down = (const float*)d_in[3];
    const float* w_up   = (const float*)d_in[4];
    const float* b_up   = (const float*)d_in[5];
    const float* gamma  = (const float*)d_in[6];
    const float* beta   = (const float*)d_in[7];
    float* out = (float*)d_out;

    float* base = nullptr;
    cudaGetSymbolAddress((void**)&base, g_buf);

    float* LB = base;                      // [8,1024,1024]
    float* S  = base + 8ll * 1024 * 1024;
    float* X1C   = S; S += 32768;    // (X1C,X2C,G12 contiguous for reduceA)
    float* X2C   = S; S += 32768;
    float* G12   = S; S += 32768;
    float* GD    = S; S += 32768;
    float* CH1   = S; S += 32768;
    float* CH2   = S; S += 32768;
    float* CH1O  = S; S += 524288;
    float* CH2O  = S; S += 524288;
    float* XDN1  = S; S += 131072;
    float* XDN2  = S; S += 131072;
    float* PD    = S; S += 131072;
    float* LFD   = S; S += 524288;
    float* AFD12 = S; S += 524288;
    float* AFD21T= S; S += 524288;
    float* Z1    = S; S += 131072;
    float* Z2    = S; S += 131072;
    float* Y1    = S; S += 131072;
    float* Y2    = S; S += 131072;
    float* W1    = S; S += 524288;
    float* W2    = S; S += 524288;
    float* HW1OT = S; S += 524288;
    float* HW2OT = S; S += 524288;
    float* PP    = S; S += 524288;
    float* RSM   = S; S += 8192;
    float* RSI   = S; S += 8192;
    float* CSM   = S; S += 8192;
    float* CSI   = S; S += 8192;
    float* R12   = S; S += 1024;
    float* PART  = S; S += 786432;
    float* MV    = S; S += 512;

    const int CHAN_SMEM = 32160 * 4;
    cudaFuncSetAttribute(chan_fused_k, cudaFuncAttributeMaxDynamicSharedMemorySize, CHAN_SMEM);

    // ---- grams + rowsums ----
    rowsum_k<<<16, 256>>>(x1, x2, R12);
    gramA_k<<<dim3(8, 24), 256>>>(x1, x2, PART);
    reduceA_k<<<384, 256>>>(PART, X1C);           // X1C, X2C, G12

    // ---- fused channel path ----
    chan_fused_k<<<8, 256, CHAN_SMEM>>>(X1C, X2C, R12, w_down, b_down, w_up, b_up, CH1, CH2);
    // CH1O = CH1@x1, CH2O = CH2@x2, PP = G12@x2 in one launch
    trio_k<<<dim3(16, 24), 256>>>(CH1, CH2, G12, x1, x2, CH1O, CH2O, PP);

    // ---- big logits ----
    launch_gemm64(true, false, x1, PP, LB, 1024, 1024, 64, 65536, 65536, 1048576, 8);
    row_stats_k<<<8192, 256>>>(LB, RSM, RSI);
    col_stats_k<<<dim3(16, 8), 256>>>(LB, CSM, CSI);

    // ---- downsampled attention (one direction; other is transpose) ----
    resample_k<<<2048, 256>>>(x1, x2, XDN1, XDN2, Z1, Z2);
    gram_k<<<dim3(2, 8), 256>>>(XDN1, XDN2, PART, 256, 128, 16384, 16384);
    gram_reduce_k<<<128, 256>>>(PART, GD, 2);
    launch_gemm64(false, false, GD, XDN2, PD, 64, 256, 64, 4096, 16384, 16384, 8);
    launch_gemm64(true,  false, XDN1, PD, LFD, 256, 256, 64, 16384, 16384, 65536, 8);
    row_softmax_k<<<2048, 256>>>(LFD, AFD12, 256);
    colsoftT_k<<<dim3(4, 8), 256>>>(LFD, AFD21T, 256);

    // ---- W = U (AFD (xU)^T) ----
    launch_gemm64(false, true, AFD12,  Z1, Y1, 256, 64, 256, 65536, 16384, 16384, 8);
    launch_gemm64(true,  true, AFD21T, Z2, Y2, 256, 64, 256, 65536, 16384, 16384, 8);
    upapply2_k<<<4096, 256>>>(Y1, Y2, W1, W2);

    // ---- fused softmax(L) @ W ----
    av_row_k<<<dim3(16, 8), 256>>>(LB, W1, RSM, RSI, HW1OT);
    av_col_k<<<dim3(16, 8), 256>>>(LB, W2, CSM, CSI, HW2OT);

    // ---- BN + residual + relu + average ----
    bn_all_k<<<256, 256>>>(CH1O, CH2O, HW1OT, HW2OT, MV);
    finalize_k<<<2048, 256>>>(x1, x2, CH1O, CH2O, HW1OT, HW2OT, MV, gamma, beta, out);
}

// round 11
// speedup vs baseline: 9.0555x; 1.1700x over previous
#include <cuda_runtime.h>
#include <math.h>

// ---------------------------------------------------------------------------
// B=8, C=64, HW=1024, D=32.
// L = x1^T (x1 x2^T) x2 ; LFD21 = LFD12^T ; X?CD via W·X?C·W^T identity;
// channel path fused (warp-split); row/col maxes folded into LB epilogue;
// HW outputs via fused softmax·W with threshold-skipped exp and inline sums.
// ---------------------------------------------------------------------------
__device__ float g_buf[17ll * 1024 * 1024];

// ---- order-preserving float <-> unsigned encoding for atomicMax ----
__device__ __forceinline__ unsigned fenc(float f)
{
    unsigned b = __float_as_uint(f);
    return (b & 0x80000000u) ? ~b : (b | 0x80000000u);
}
__device__ __forceinline__ float fdec(unsigned u)
{
    return (u & 0x80000000u) ? __uint_as_float(u & 0x7FFFFFFFu)
                             : __uint_as_float(~u);
}

// ===========================================================================
// gemm64: C[b](MxN) = opA(A[b]) * opB(B[b]); tile 64x64, KT=16, 256 thr, 4x4.
// ===========================================================================
template <bool TA, bool TB>
__global__ void __launch_bounds__(256)
gemm64_kernel(const float* __restrict__ A, const float* __restrict__ B,
              float* __restrict__ C, int M, int N, int K, long sA, long sB, long sC)
{
    __shared__ float As[16][68];
    __shared__ float Bs[16][68];
    const int tid = threadIdx.x;
    const int m0 = blockIdx.y * 64, n0 = blockIdx.x * 64;
    const float* Ab = A + (long)blockIdx.z * sA;
    const float* Bb = B + (long)blockIdx.z * sB;
    float* Cb = C + (long)blockIdx.z * sC;
    const int rowt = (tid >> 4) * 4, colt = (tid & 15) * 4;
    float acc[4][4] = {};

    for (int k0 = 0; k0 < K; k0 += 16) {
        float4 av = {0,0,0,0}, bv = {0,0,0,0};
        if (!TA) {
            int r = tid >> 2, c = (tid & 3) * 4;
            if (m0 + r < M) av = *(const float4*)(Ab + (long)(m0 + r) * K + k0 + c);
            As[c+0][r]=av.x; As[c+1][r]=av.y; As[c+2][r]=av.z; As[c+3][r]=av.w;
        } else {
            int kr = tid >> 4, mc = (tid & 15) * 4;
            if (m0 + mc < M) av = *(const float4*)(Ab + (long)(k0 + kr) * M + m0 + mc);
            *(float4*)&As[kr][mc] = av;
        }
        if (!TB) {
            int kr = tid >> 4, nc = (tid & 15) * 4;
            if (n0 + nc < N) bv = *(const float4*)(Bb + (long)(k0 + kr) * N + n0 + nc);
            *(float4*)&Bs[kr][nc] = bv;
        } else {
            int r = tid >> 2, c = (tid & 3) * 4;
            if (n0 + r < N) bv = *(const float4*)(Bb + (long)(n0 + r) * K + k0 + c);
            Bs[c+0][r]=bv.x; Bs[c+1][r]=bv.y; Bs[c+2][r]=bv.z; Bs[c+3][r]=bv.w;
        }
        __syncthreads();
#pragma unroll
        for (int kk = 0; kk < 16; kk++) {
            float4 a = *(const float4*)&As[kk][rowt];
            float4 b = *(const float4*)&Bs[kk][colt];
            float ra[4] = {a.x,a.y,a.z,a.w}, rb[4] = {b.x,b.y,b.z,b.w};
#pragma unroll
            for (int i = 0; i < 4; i++)
#pragma unroll
                for (int j = 0; j < 4; j++) acc[i][j] += ra[i] * rb[j];
        }
        __syncthreads();
    }
    if (n0 + colt < N) {
#pragma unroll
        for (int i = 0; i < 4; i++) {
            int m = m0 + rowt + i;
            if (m < M)
                *(float4*)(Cb + (long)m * N + n0 + colt) =
                    make_float4(acc[i][0], acc[i][1], acc[i][2], acc[i][3]);
        }
    }
}

static void launch_gemm64(bool ta, bool tb,
                          const float* A, const float* B, float* C,
                          int M, int N, int K, long sA, long sB, long sC, int batch)
{
    dim3 grid((N + 63) / 64, (M + 63) / 64, batch);
    if (!ta && !tb)      gemm64_kernel<false,false><<<grid,256>>>(A,B,C,M,N,K,sA,sB,sC);
    else if (!ta && tb)  gemm64_kernel<false,true ><<<grid,256>>>(A,B,C,M,N,K,sA,sB,sC);
    else if (ta && !tb)  gemm64_kernel<true ,false><<<grid,256>>>(A,B,C,M,N,K,sA,sB,sC);
    else                 gemm64_kernel<true ,true ><<<grid,256>>>(A,B,C,M,N,K,sA,sB,sC);
}

// ===========================================================================
// lbgemm: LB = x1^T @ PP  (M=N=1024, K=64), epilogue folds row/col maxes into
// encoded global atomicMax arrays. grid (16,16,8).
// ===========================================================================
__global__ void __launch_bounds__(256)
lbgemm_k(const float* __restrict__ X1, const float* __restrict__ PP,
         float* __restrict__ LB, unsigned* __restrict__ RSME, unsigned* __restrict__ CSME)
{
    __shared__ float As[16][68];
    __shared__ float Bs[16][68];
    __shared__ unsigned srow[64], scol[64];
    const int tid = threadIdx.x;
    const int m0 = blockIdx.y * 64, n0 = blockIdx.x * 64, b = blockIdx.z;
    const float* Ab = X1 + (long)b * 65536;   // [64][1024] k-major
    const float* Bb = PP + (long)b * 65536;   // [64][1024]
    float* Cb = LB + (long)b * 1048576;
    const int rowt = (tid >> 4) * 4, colt = (tid & 15) * 4;
    const int kr = tid >> 4, xc = (tid & 15) * 4;
    float acc[4][4] = {};

    if (tid < 64) { srow[tid] = 0u; scol[tid] = 0u; }

    for (int k0 = 0; k0 < 64; k0 += 16) {
        *(float4*)&As[kr][xc] = *(const float4*)(Ab + (long)(k0 + kr) * 1024 + m0 + xc);
        *(float4*)&Bs[kr][xc] = *(const float4*)(Bb + (long)(k0 + kr) * 1024 + n0 + xc);
        __syncthreads();
#pragma unroll
        for (int kk = 0; kk < 16; kk++) {
            float4 a = *(const float4*)&As[kk][rowt];
            float4 bq = *(const float4*)&Bs[kk][colt];
            float ra[4] = {a.x,a.y,a.z,a.w}, rb[4] = {bq.x,bq.y,bq.z,bq.w};
#pragma unroll
            for (int i = 0; i < 4; i++)
#pragma unroll
                for (int j = 0; j < 4; j++) acc[i][j] += ra[i] * rb[j];
        }
        __syncthreads();
    }

#pragma unroll
    for (int i = 0; i < 4; i++)
        *(float4*)(Cb + (long)(m0 + rowt + i) * 1024 + n0 + colt) =
            make_float4(acc[i][0], acc[i][1], acc[i][2], acc[i][3]);

    // per-thread row/col maxes -> smem atomics -> global encoded atomics
#pragma unroll
    for (int i = 0; i < 4; i++) {
        float rm = fmaxf(fmaxf(acc[i][0], acc[i][1]), fmaxf(acc[i][2], acc[i][3]));
        atomicMax(&srow[rowt + i], fenc(rm));
    }
#pragma unroll
    for (int j = 0; j < 4; j++) {
        float cm = fmaxf(fmaxf(acc[0][j], acc[1][j]), fmaxf(acc[2][j], acc[3][j]));
        atomicMax(&scol[colt + j], fenc(cm));
    }
    __syncthreads();
    if (tid < 64)       atomicMax(&RSME[b * 1024 + m0 + tid], srow[tid]);
    else if (tid < 128) atomicMax(&CSME[b * 1024 + n0 + (tid - 64)], scol[tid - 64]);
}

// ===========================================================================
// trio_k: three M=64,N=1024,K=64 NN GEMMs in one launch. grid (16, 24)
// ===========================================================================
__global__ void __launch_bounds__(256)
trio_k(const float* __restrict__ CH1, const float* __restrict__ CH2,
       const float* __restrict__ G12,
       const float* __restrict__ x1, const float* __restrict__ x2,
       float* __restrict__ CH1O, float* __restrict__ CH2O, float* __restrict__ PP)
{
    __shared__ float As[16][68];
    __shared__ float Bs[16][68];
    const int tid = threadIdx.x;
    const int z = blockIdx.y, pair = z >> 3, b = z & 7;
    const int n0 = blockIdx.x * 64;
    const float* Ab = (pair == 0 ? CH1 : pair == 1 ? CH2 : G12) + (long)b * 4096;
    const float* Bb = (pair == 0 ? x1 : x2) + (long)b * 65536;
    float* Cb = (pair == 0 ? CH1O : pair == 1 ? CH2O : PP) + (long)b * 65536;
    const int rowt = (tid >> 4) * 4, colt = (tid & 15) * 4;
    float acc[4][4] = {};

    for (int k0 = 0; k0 < 64; k0 += 16) {
        {
            int r = tid >> 2, c = (tid & 3) * 4;
            float4 av = *(const float4*)(Ab + r * 64 + k0 + c);
            As[c+0][r]=av.x; As[c+1][r]=av.y; As[c+2][r]=av.z; As[c+3][r]=av.w;
        }
        {
            int kr = tid >> 4, nc = (tid & 15) * 4;
            float4 bv = *(const float4*)(Bb + (long)(k0 + kr) * 1024 + n0 + nc);
            *(float4*)&Bs[kr][nc] = bv;
        }
        __syncthreads();
#pragma unroll
        for (int kk = 0; kk < 16; kk++) {
            float4 a = *(const float4*)&As[kk][rowt];
            float4 bq = *(const float4*)&Bs[kk][colt];
            float ra[4] = {a.x,a.y,a.z,a.w}, rb[4] = {bq.x,bq.y,bq.z,bq.w};
#pragma unroll
            for (int i = 0; i < 4; i++)
#pragma unroll
                for (int j = 0; j < 4; j++) acc[i][j] += ra[i] * rb[j];
        }
        __syncthreads();
    }
#pragma unroll
    for (int i = 0; i < 4; i++)
        *(float4*)(Cb + (long)(rowt + i) * 1024 + n0 + colt) =
            make_float4(acc[i][0], acc[i][1], acc[i][2], acc[i][3]);
}

// ===========================================================================
// gramA: 3 pairs {x1x1, x2x2, x1x2} x 8 batches x 8 k-splits. grid (8, 24).
// ===========================================================================
__global__ void __launch_bounds__(256)
gramA_k(const float* __restrict__ x1, const float* __restrict__ x2, float* __restrict__ P)
{
    __shared__ float Xs[16][68], Ys[16][68];
    const int tid = threadIdx.x;
    const int pz = blockIdx.y, pair = pz >> 3, b = pz & 7;
    const float* Xb = ((pair == 1) ? x2 : x1) + (long)b * 65536;
    const float* Yb = ((pair == 0) ? x1 : x2) + (long)b * 65536;
    const int kbase = blockIdx.x * 128;
    const int rowt = (tid >> 4) * 4, colt = (tid & 15) * 4;
    const int r = tid >> 2, c = (tid & 3) * 4;
    float acc[4][4] = {};

    for (int k0 = kbase; k0 < kbase + 128; k0 += 16) {
        float4 xv = *(const float4*)(Xb + (long)r * 1024 + k0 + c);
        float4 yv = *(const float4*)(Yb + (long)r * 1024 + k0 + c);
        Xs[c+0][r]=xv.x; Xs[c+1][r]=xv.y; Xs[c+2][r]=xv.z; Xs[c+3][r]=xv.w;
        Ys[c+0][r]=yv.x; Ys[c+1][r]=yv.y; Ys[c+2][r]=yv.z; Ys[c+3][r]=yv.w;
        __syncthreads();
#pragma unroll
        for (int kk = 0; kk < 16; kk++) {
            float4 a = *(const float4*)&Xs[kk][rowt];
            float4 bq = *(const float4*)&Ys[kk][colt];
            float ra[4]={a.x,a.y,a.z,a.w}, rb[4]={bq.x,bq.y,bq.z,bq.w};
#pragma unroll
            for (int i = 0; i < 4; i++)
#pragma unroll
                for (int j = 0; j < 4; j++) acc[i][j] += ra[i] * rb[j];
        }
        __syncthreads();
    }
    float* Pp = P + ((long)pz * 8 + blockIdx.x) * 4096;
#pragma unroll
    for (int i = 0; i < 4; i++)
        *(float4*)(Pp + (rowt + i) * 64 + colt) =
            make_float4(acc[i][0], acc[i][1], acc[i][2], acc[i][3]);
}

__global__ void reduceA_k(const float* __restrict__ P, float* __restrict__ O)
{
    int idx = blockIdx.x * 256 + threadIdx.x;   // < 98304
    int pz = idx >> 12, e = idx & 4095;
    float s = 0.f;
#pragma unroll
    for (int k = 0; k < 8; k++) s += P[((long)pz * 8 + k) * 4096 + e];
    O[idx] = s;
}

// Generic split-K gram (GD): grid (nsplit, batch), M=N=64
__global__ void __launch_bounds__(256)
gram_k(const float* __restrict__ X, const float* __restrict__ Y,
       float* __restrict__ P, int K, int klen, long sX, long sY)
{
    __shared__ float Xs[16][68], Ys[16][68];
    const int tid = threadIdx.x;
    const float* Xb = X + (long)blockIdx.y * sX;
    const float* Yb = Y + (long)blockIdx.y * sY;
    const int kbase = blockIdx.x * klen;
    const int rowt = (tid >> 4) * 4, colt = (tid & 15) * 4;
    const int r = tid >> 2, c = (tid & 3) * 4;
    float acc[4][4] = {};

    for (int k0 = kbase; k0 < kbase + klen; k0 += 16) {
        float4 xv = *(const float4*)(Xb + (long)r * K + k0 + c);
        float4 yv = *(const float4*)(Yb + (long)r * K + k0 + c);
        Xs[c+0][r]=xv.x; Xs[c+1][r]=xv.y; Xs[c+2][r]=xv.z; Xs[c+3][r]=xv.w;
        Ys[c+0][r]=yv.x; Ys[c+1][r]=yv.y; Ys[c+2][r]=yv.z; Ys[c+3][r]=yv.w;
        __syncthreads();
#pragma unroll
        for (int kk = 0; kk < 16; kk++) {
            float4 a = *(const float4*)&Xs[kk][rowt];
            float4 bq = *(const float4*)&Ys[kk][colt];
            float ra[4]={a.x,a.y,a.z,a.w}, rb[4]={bq.x,bq.y,bq.z,bq.w};
#pragma unroll
            for (int i = 0; i < 4; i++)
#pragma unroll
                for (int j = 0; j < 4; j++) acc[i][j] += ra[i] * rb[j];
        }
        __syncthreads();
    }
    float* Pp = P + ((long)blockIdx.y * gridDim.x + blockIdx.x) * 4096;
#pragma unroll
    for (int i = 0; i < 4; i++)
        *(float4*)(Pp + (rowt + i) * 64 + colt) =
            make_float4(acc[i][0], acc[i][1], acc[i][2], acc[i][3]);
}

__global__ void gram_reduce_k(const float* __restrict__ P, float* __restrict__ C, int nsplit)
{
    int idx = blockIdx.x * 256 + threadIdx.x;
    if (idx >= 32768) return;
    int b = idx >> 12, e = idx & 4095;
    float s = 0.f;
    for (int k = 0; k < nsplit; k++) s += P[((long)b * nsplit + k) * 4096 + e];
    C[idx] = s;
}

// ---------------------------------------------------------------------------
// Row sums of x1/x2 + zero the encoded max arrays (16384 words)
// ---------------------------------------------------------------------------
__global__ void rowsum_k(const float* __restrict__ x1, const float* __restrict__ x2,
                         float* __restrict__ r, unsigned* __restrict__ ME)
{
    int gid = blockIdx.x * 256 + threadIdx.x;
    for (int i = gid; i < 16384; i += 4096) ME[i] = 0u;

    int which = blockIdx.x >> 3, b = blockIdx.x & 7;
    const float* xb = (which ? x2 : x1) + (long)b * 65536;
    int w = threadIdx.x >> 5, lane = threadIdx.x & 31;
    for (int rr = w * 8; rr < w * 8 + 8; rr++) {
        float s = 0.f;
        for (int p = lane; p < 1024; p += 32) s += xb[rr * 1024 + p];
#pragma unroll
        for (int o = 16; o; o >>= 1) s += __shfl_xor_sync(0xffffffffu, s, o);
        if (lane == 0) r[which * 512 + b * 64 + rr] = s;
    }
}

// ===========================================================================
// smm / smm128: in-smem matmuls (256 / 128 threads)
// ===========================================================================
template<int M, int N, int K, bool BT>
__device__ __forceinline__ void smm(const float* __restrict__ A, int lda,
                                    const float* __restrict__ B, int ldb,
                                    float* __restrict__ C, int ldc,
                                    const float* __restrict__ bias,
                                    const float* __restrict__ rscale, int t)
{
    constexpr int RM = M / 16, RN = N / 16;
    const int r0 = (t >> 4) * RM, c0 = (t & 15) * RN;
    float acc[RM][RN];
#pragma unroll
    for (int i = 0; i < RM; i++) {
        float bv = bias ? bias[r0 + i] : 0.f;
#pragma unroll
        for (int j = 0; j < RN; j++) acc[i][j] = bv;
    }
#pragma unroll 4
    for (int k = 0; k < K; k++) {
        float a[RM], b[RN];
#pragma unroll
        for (int i = 0; i < RM; i++) a[i] = A[(r0 + i) * lda + k];
#pragma unroll
        for (int j = 0; j < RN; j++) b[j] = BT ? B[(c0 + j) * ldb + k] : B[k * ldb + c0 + j];
#pragma unroll
        for (int i = 0; i < RM; i++)
#pragma unroll
            for (int j = 0; j < RN; j++) acc[i][j] += a[i] * b[j];
    }
#pragma unroll
    for (int i = 0; i < RM; i++) {
        float sc = rscale ? rscale[r0 + i] : 1.f;
#pragma unroll
        for (int j = 0; j < RN; j++) C[(r0 + i) * ldc + c0 + j] = acc[i][j] * sc;
    }
}

template<int M, int N, int K, bool BT>
__device__ __forceinline__ void smm128(const float* __restrict__ A, int lda,
                                       const float* __restrict__ B, int ldb,
                                       float* __restrict__ C, int ldc,
                                       const float* __restrict__ bias,
                                       const float* __restrict__ rscale, int t)
{
    constexpr int RM = M / 8, RN = N / 16;
    const int r0 = (t >> 4) * RM, c0 = (t & 15) * RN;
    float acc[RM][RN];
#pragma unroll
    for (int i = 0; i < RM; i++) {
        float bv = bias ? bias[r0 + i] : 0.f;
#pragma unroll
        for (int j = 0; j < RN; j++) acc[i][j] = bv;
    }
#pragma unroll 4
    for (int k = 0; k < K; k++) {
        float a[RM], b[RN];
#pragma unroll
        for (int i = 0; i < RM; i++) a[i] = A[(r0 + i) * lda + k];
#pragma unroll
        for (int j = 0; j < RN; j++) b[j] = BT ? B[(c0 + j) * ldb + k] : B[k * ldb + c0 + j];
#pragma unroll
        for (int i = 0; i < RM; i++)
#pragma unroll
            for (int j = 0; j < RN; j++) acc[i][j] += a[i] * b[j];
    }
#pragma unroll
    for (int i = 0; i < RM; i++) {
        float sc = rscale ? rscale[r0 + i] : 1.f;
#pragma unroll
        for (int j = 0; j < RN; j++) C[(r0 + i) * ldc + c0 + j] = acc[i][j] * sc;
    }
}

// Cd = Mb(32x64,ld) * Wd^T + bd u^T + u bd^T + 1024 bd bd^T  (128 threads)
__device__ __forceinline__ void cd_stage(const float* __restrict__ Mb,
                                         const float* __restrict__ Wd,
                                         float* __restrict__ Cd,
                                         const float* __restrict__ bd,
                                         const float* __restrict__ u, int t)
{
    const int r0 = (t >> 4) * 4, c0 = (t & 15) * 2;
    float acc[4][2] = {};
#pragma unroll 4
    for (int k = 0; k < 64; k++) {
        float a[4], b[2];
#pragma unroll
        for (int i = 0; i < 4; i++) a[i] = Mb[(r0 + i) * 68 + k];
#pragma unroll
        for (int j = 0; j < 2; j++) b[j] = Wd[(c0 + j) * 64 + k];
#pragma unroll
        for (int i = 0; i < 4; i++)
#pragma unroll
            for (int j = 0; j < 2; j++) acc[i][j] += a[i] * b[j];
    }
#pragma unroll
    for (int i = 0; i < 4; i++) {
        int d = r0 + i;
#pragma unroll
        for (int j = 0; j < 2; j++) {
            int e = c0 + j;
            Cd[d * 36 + e] = acc[i][j] + bd[d]*u[e] + bd[e]*u[d] + 1024.f*bd[d]*bd[e];
        }
    }
}

// ===========================================================================
// Fused channel path (warp-split halves)
// ===========================================================================
__global__ void __launch_bounds__(256)
chan_fused_k(const float* __restrict__ X1C_g, const float* __restrict__ X2C_g,
             const float* __restrict__ rsum,
             const float* __restrict__ w_down, const float* __restrict__ b_down,
             const float* __restrict__ w_up, const float* __restrict__ b_up,
             float* __restrict__ CH1_g, float* __restrict__ CH2_g)
{
    extern __shared__ float sm[];
    float* A   = sm;              // 64x68  X1C -> U1T
    float* Bf  = A   + 4352;      // 64x68  X2C -> U2T
    float* LC  = Bf  + 4352;      // 64x68  LC -> E12
    float* E2  = LC  + 4352;      // 64x68
    float* Wd  = E2  + 4352;      // 32x64
    float* Wu  = Wd  + 2048;      // 64x32
    float* Mb1 = Wu  + 2048;      // 32x68
    float* Mb2 = Mb1 + 2176;      // 32x68
    float* C1d = Mb2 + 2176;      // 32x36
    float* C2d = C1d + 1152;
    float* LCD = C2d + 1152;
    float* A12d= LCD + 1152;
    float* A21d= A12d+ 1152;
    float* TT1 = A21d+ 1152;      // 64x36
    float* TT2 = TT1 + 2304;
    float* bd  = TT2 + 2304;      // 32
    float* bu  = bd  + 32;        // 64
    float* u1  = bu  + 64;        // 32
    float* u2  = u1  + 32;        // 32
    float* st  = u2  + 32;        // 256

    const int b = blockIdx.x, t = threadIdx.x;
    const bool h0 = t < 128;
    const int ht = h0 ? t : t - 128;

    for (int i = t; i < 4096; i += 256) {
        A [(i >> 6) * 68 + (i & 63)] = X1C_g[b * 4096 + i];
        Bf[(i >> 6) * 68 + (i & 63)] = X2C_g[b * 4096 + i];
    }
    for (int i = t; i < 2048; i += 256) { Wd[i] = w_down[i]; Wu[i] = w_up[i]; }
    if (t < 32) bd[t] = b_down[t];
    if (t < 64) bu[t] = b_up[t];
    __syncthreads();

    if (t < 64) {
        int d = t & 31, which = t >> 5;
        const float* r = rsum + which * 512 + b * 64;
        float s = 0.f;
        for (int c = 0; c < 64; c++) s += Wd[d * 64 + c] * r[c];
        (which ? u2 : u1)[d] = s;
    }
    __syncthreads();

    // Mb pair, then Cd pair (halves in parallel)
    if (h0) smm128<32, 64, 64, false>(Wd, 64, A, 68, Mb1, 68, nullptr, nullptr, ht);
    else    smm128<32, 64, 64, false>(Wd, 64, Bf, 68, Mb2, 68, nullptr, nullptr, ht);
    __syncthreads();
    if (h0) cd_stage(Mb1, Wd, C1d, bd, u1, ht);
    else    cd_stage(Mb2, Wd, C2d, bd, u2, ht);
    __syncthreads();

    // LC full block
    smm<64, 64, 64, false>(A, 68, Bf, 68, LC, 68, nullptr, nullptr, t);
    __syncthreads();

    // stats (t<128) || LCD (t>=128)
    if (t < 64) {
        float m = -3.4e38f;
        for (int j = 0; j < 64; j++) m = fmaxf(m, LC[t * 68 + j]);
        float s = 0.f;
        for (int j = 0; j < 64; j++) s += __expf(LC[t * 68 + j] - m);
        st[t] = m; st[64 + t] = 1.f / s;
    } else if (t < 128) {
        int i = t - 64;
        float m = -3.4e38f;
        for (int j = 0; j < 64; j++) m = fmaxf(m, LC[j * 68 + i]);
        float s = 0.f;
        for (int j = 0; j < 64; j++) s += __expf(LC[j * 68 + i] - m);
        st[128 + i] = m; st[192 + i] = 1.f / s;
    } else {
        smm128<32, 32, 32, false>(C1d, 36, C2d, 36, LCD, 36, nullptr, nullptr, ht);
    }
    __syncthreads();

    // E2/E12 (t<192) || LCD softmaxes (t>=192)
    if (t < 192) {
        for (int o = t; o < 4096; o += 192) {
            int i = o >> 6, j = o & 63;
            E2[i * 68 + j] = __expf(LC[j * 68 + i] - st[128 + i]);
        }
        for (int o = t; o < 4096; o += 192) {
            int i = o >> 6, j = o & 63;
            LC[i * 68 + j] = __expf(LC[i * 68 + j] - st[i]);
        }
    } else if (t < 224) {
        int i = t - 192;
        float m = -3.4e38f;
        for (int j = 0; j < 32; j++) m = fmaxf(m, LCD[i * 36 + j]);
        float s = 0.f;
        for (int j = 0; j < 32; j++) s += __expf(LCD[i * 36 + j] - m);
        float inv = 1.f / s;
        for (int j = 0; j < 32; j++) A12d[i * 36 + j] = __expf(LCD[i * 36 + j] - m) * inv;
    } else {
        int i = t - 224;
        float m = -3.4e38f;
        for (int j = 0; j < 32; j++) m = fmaxf(m, LCD[j * 36 + i]);
        float s = 0.f;
        for (int j = 0; j < 32; j++) s += __expf(LCD[j * 36 + i] - m);
        float inv = 1.f / s;
        for (int j = 0; j < 32; j++) A21d[i * 36 + j] = __expf(LCD[j * 36 + i] - m) * inv;
    }
    __syncthreads();

    // ConvUp pairs
    if (h0) smm128<64, 32, 32, false>(Wu, 32, A12d, 36, TT1, 36, bu, nullptr, ht);
    else    smm128<64, 32, 32, false>(Wu, 32, A21d, 36, TT2, 36, bu, nullptr, ht);
    __syncthreads();
    if (h0) smm128<64, 64, 32, true >(Wu, 32, TT1, 36, A, 68, bu, nullptr, ht);
    else    smm128<64, 64, 32, true >(Wu, 32, TT2, 36, Bf, 68, bu, nullptr, ht);
    __syncthreads();

    // CH pair (to global)
    if (h0) smm128<64, 64, 64, true>(LC, 68, A, 68, CH1_g + b * 4096, 64, nullptr, st + 64, ht);
    else    smm128<64, 64, 64, true>(E2, 68, Bf, 68, CH2_g + b * 4096, 64, nullptr, st + 192, ht);
}

// ---------------------------------------------------------------------------
// Row softmax (materializing), width N
// ---------------------------------------------------------------------------
__global__ void row_softmax_k(const float* __restrict__ L, float* __restrict__ A, int N)
{
    long row = blockIdx.x;
    const float* p = L + row * (long)N;
    float* q = A + row * (long)N;
    int t = threadIdx.x;
    __shared__ float sh[8];

    float m = -3.4e38f;
    for (int i = t; i < N; i += 256) m = fmaxf(m, p[i]);
#pragma unroll
    for (int o = 16; o; o >>= 1) m = fmaxf(m, __shfl_xor_sync(0xffffffffu, m, o));
    if ((t & 31) == 0) sh[t >> 5] = m;
    __syncthreads();
    float mm = sh[0];
#pragma unroll
    for (int w = 1; w < 8; w++) mm = fmaxf(mm, sh[w]);
    __syncthreads();

    float s = 0.f;
    for (int i = t; i < N; i += 256) s += __expf(p[i] - mm);
#pragma unroll
    for (int o = 16; o; o >>= 1) s += __shfl_xor_sync(0xffffffffu, s, o);
    if ((t & 31) == 0) sh[t >> 5] = s;
    __syncthreads();
    float ss = 0.f;
#pragma unroll
    for (int w = 0; w < 8; w++) ss += sh[w];
    float inv = 1.f / ss;

    for (int i = t; i < N; i += 256) q[i] = __expf(p[i] - mm) * inv;
}

// Column softmax written TRANSPOSED
__global__ void colsoftT_k(const float* __restrict__ L, float* __restrict__ AT, int N)
{
    int cc = threadIdx.x & 63;
    int kg = threadIdx.x >> 6;
    int i  = blockIdx.x * 64 + cc;
    const float* Lb = L  + (long)blockIdx.y * N * N;
    float*       Ab = AT + (long)blockIdx.y * N * N;
    __shared__ float red[4][64];

    float m = -3.4e38f;
    for (int k = kg; k < N; k += 4) m = fmaxf(m, Lb[k * N + i]);
    red[kg][cc] = m;
    __syncthreads();
    m = fmaxf(fmaxf(red[0][cc], red[1][cc]), fmaxf(red[2][cc], red[3][cc]));
    __syncthreads();

    float s = 0.f;
    for (int k = kg; k < N; k += 4) s += __expf(Lb[k * N + i] - m);
    red[kg][cc] = s;
    __syncthreads();
    s = red[0][cc] + red[1][cc] + red[2][cc] + red[3][cc];
    float inv = 1.f / s;

    for (int k = kg; k < N; k += 4)
        Ab[k * N + i] = __expf(Lb[k * N + i] - m) * inv;
}

// ===========================================================================
// Fused softmax(L)·W with threshold-skipped exp and inline sums.
// ===========================================================================
__global__ void __launch_bounds__(256)
av_row_k(const float* __restrict__ L, const float* __restrict__ W,
         const unsigned* __restrict__ RSME, float* __restrict__ O)
{
    __shared__ float Ls[16][68], Ws[16][68];
    __shared__ float smx[64], spart[256], sinv[64];
    const int tid = threadIdx.x;
    const int b = blockIdx.y, m0 = blockIdx.x * 64;
    if (tid < 64) smx[tid] = fdec(RSME[b * 1024 + m0 + tid]);
    __syncthreads();
    const float* Lb = L + (long)b * 1048576;
    const float* Wb = W + (long)b * 65536;
    const int rowt = (tid >> 4) * 4, colt = (tid & 15) * 4;
    const int r = tid >> 2, c = (tid & 3) * 4;
    const int kr = tid >> 4, nc = (tid & 15) * 4;
    float acc[4][4] = {};
    float psum = 0.f;
    const float mr = smx[r], thr = mr - 20.f;

    for (int k0 = 0; k0 < 1024; k0 += 16) {
        float4 v = *(const float4*)(Lb + (long)(m0 + r) * 1024 + k0 + c);
        float4 e = {0.f, 0.f, 0.f, 0.f};
        if (v.x > thr || v.y > thr || v.z > thr || v.w > thr) {
            e.x = __expf(v.x - mr); e.y = __expf(v.y - mr);
            e.z = __expf(v.z - mr); e.w = __expf(v.w - mr);
            psum += e.x + e.y + e.z + e.w;
        }
        Ls[c+0][r] = e.x; Ls[c+1][r] = e.y; Ls[c+2][r] = e.z; Ls[c+3][r] = e.w;
        *(float4*)&Ws[kr][nc] = *(const float4*)(Wb + (long)(k0 + kr) * 64 + nc);
        __syncthreads();
#pragma unroll
        for (int kk = 0; kk < 16; kk++) {
            float4 a = *(const float4*)&Ls[kk][rowt];
            float4 w = *(const float4*)&Ws[kk][colt];
            float ra[4]={a.x,a.y,a.z,a.w}, rb[4]={w.x,w.y,w.z,w.w};
#pragma unroll
            for (int i = 0; i < 4; i++)
#pragma unroll
                for (int j = 0; j < 4; j++) acc[i][j] += ra[i] * rb[j];
        }
        __syncthreads();
    }
    spart[tid] = psum;
    __syncthreads();
    if (tid < 64)
        sinv[tid] = 1.f / (spart[4*tid] + spart[4*tid+1] + spart[4*tid+2] + spart[4*tid+3]);
    __syncthreads();

    float* Ob = O + (long)b * 65536;
#pragma unroll
    for (int i = 0; i < 4; i++) {
        float sc = sinv[rowt + i];
        *(float4*)(Ob + (long)(m0 + rowt + i) * 64 + colt) =
            make_float4(acc[i][0]*sc, acc[i][1]*sc, acc[i][2]*sc, acc[i][3]*sc);
    }
}

__global__ void __launch_bounds__(256)
av_col_k(const float* __restrict__ L, const float* __restrict__ W,
         const unsigned* __restrict__ CSME, float* __restrict__ O)
{
    __shared__ float Ls[16][68], Ws[16][68];
    __shared__ float smx[64], scs[16][64], sinv[64];
    const int tid = threadIdx.x;
    const int b = blockIdx.y, m0 = blockIdx.x * 64;
    if (tid < 64) smx[tid] = fdec(CSME[b * 1024 + m0 + tid]);
    __syncthreads();
    const float* Lb = L + (long)b * 1048576;
    const float* Wb = W + (long)b * 65536;
    const int rowt = (tid >> 4) * 4, colt = (tid & 15) * 4;
    const int kr = tid >> 4, mc = (tid & 15) * 4;
    float acc[4][4] = {};
    float ps[4] = {0.f, 0.f, 0.f, 0.f};
    const float m0f = smx[mc], m1f = smx[mc+1], m2f = smx[mc+2], m3f = smx[mc+3];

    for (int k0 = 0; k0 < 1024; k0 += 16) {
        float4 v = *(const float4*)(Lb + (long)(k0 + kr) * 1024 + m0 + mc);
        float4 e = {0.f, 0.f, 0.f, 0.f};
        if (v.x > m0f - 20.f || v.y > m1f - 20.f || v.z > m2f - 20.f || v.w > m3f - 20.f) {
            e.x = (v.x > m0f - 20.f) ? __expf(v.x - m0f) : 0.f;
            e.y = (v.y > m1f - 20.f) ? __expf(v.y - m1f) : 0.f;
            e.z = (v.z > m2f - 20.f) ? __expf(v.z - m2f) : 0.f;
            e.w = (v.w > m3f - 20.f) ? __expf(v.w - m3f) : 0.f;
            ps[0] += e.x; ps[1] += e.y; ps[2] += e.z; ps[3] += e.w;
        }
        *(float4*)&Ls[kr][mc] = e;
        *(float4*)&Ws[kr][mc] = *(const float4*)(Wb + (long)(k0 + kr) * 64 + mc);
        __syncthreads();
#pragma unroll
        for (int kk = 0; kk < 16; kk++) {
            float4 a = *(const float4*)&Ls[kk][rowt];
            float4 w = *(const float4*)&Ws[kk][colt];
            float ra[4]={a.x,a.y,a.z,a.w}, rb[4]={w.x,w.y,w.z,w.w};
#pragma unroll
            for (int i = 0; i < 4; i++)
#pragma unroll
                for (int j = 0; j < 4; j++) acc[i][j] += ra[i] * rb[j];
        }
        __syncthreads();
    }
#pragma unroll
    for (int j = 0; j < 4; j++) scs[kr][mc + j] = ps[j];
    __syncthreads();
    if (tid < 64) {
        float s = 0.f;
#pragma unroll
        for (int k = 0; k < 16; k++) s += scs[k][tid];
        sinv[tid] = 1.f / s;
    }
    __syncthreads();

    float* Ob = O + (long)b * 65536;
#pragma unroll
    for (int i = 0; i < 4; i++) {
        float sc = sinv[rowt + i];
        *(float4*)(Ob + (long)(m0 + rowt + i) * 64 + colt) =
            make_float4(acc[i][0]*sc, acc[i][1]*sc, acc[i][2]*sc, acc[i][3]*sc);
    }
}

// ---------------------------------------------------------------------------
// Keys cubic + merged resampling
// ---------------------------------------------------------------------------
__device__ __forceinline__ float keys_cubic(float x)
{
    x = fabsf(x);
    if (x < 1.f) return ((1.5f * x - 2.5f) * x) * x + 1.f;
    if (x < 2.f) return ((-0.5f * x + 2.5f) * x - 4.f) * x + 2.f;
    return 0.f;
}

__global__ void resample_k(const float* __restrict__ x1, const float* __restrict__ x2,
                           float* __restrict__ y1, float* __restrict__ y2,
                           float* __restrict__ Z1, float* __restrict__ Z2)
{
    int gidx = blockIdx.x * 256 + threadIdx.x;
    if (gidx < 262144) {
        const float* x = gidx < 131072 ? x1 : x2;
        float* y = gidx < 131072 ? y1 : y2;
        int idx = gidx & 131071;
        int ox = idx & 15;
        int oy = (idx >> 4) & 15;
        int bc = idx >> 8;

        int jy0 = 2 * oy - 3, jx0 = 2 * ox - 3;
        float wy[8], wx[8];
        float sy = 0.f, sx = 0.f;
#pragma unroll
        for (int t = 0; t < 8; t++) {
            float w = keys_cubic(fabsf(3.5f - t) * 0.5f);
            int jy = jy0 + t;
            wy[t] = (jy >= 0 && jy < 32) ? w : 0.f; sy += wy[t];
            int jx = jx0 + t;
            wx[t] = (jx >= 0 && jx < 32) ? w : 0.f; sx += wx[t];
        }
        float iy = 1.f / sy, ix = 1.f / sx;
#pragma unroll
        for (int t = 0; t < 8; t++) { wy[t] *= iy; wx[t] *= ix; }

        const float* src = x + (long)bc * 1024;
        float acc = 0.f;
#pragma unroll
        for (int t = 0; t < 8; t++) {
            int jy = min(max(jy0 + t, 0), 31);
            float r = 0.f;
#pragma unroll
            for (int u = 0; u < 8; u++) {
                int jx = min(max(jx0 + u, 0), 31);
                r += wx[u] * src[jy * 32 + jx];
            }
            acc += wy[t] * r;
        }
        y[idx] = acc;
    } else if (gidx < 524288) {
        int g2 = gidx - 262144;
        const float* x = g2 < 131072 ? x1 : x2;
        float* Z = g2 < 131072 ? Z1 : Z2;
        int idx = g2 & 131071;
        int j = idx & 255;
        int c = (idx >> 8) & 63;
        int b = idx >> 14;
        const float* xr = x + (long)b * 65536 + (long)c * 1024;

        float acc = 0.f;
        int Ilo = max(0, 4 * j - 8), Ihi = min(1023, 4 * j + 10);
        for (int I = Ilo; I <= Ihi; I++) {
            float sf = (I + 0.5f) * 0.25f - 0.5f;
            float fl = floorf(sf);
            float f  = sf - fl;
            int base = (int)fl - 1;
            int tt = j - base;
            if (tt < 0 || tt > 3) continue;
            float tot = 0.f, wsel = 0.f;
#pragma unroll
            for (int t = 0; t < 4; t++) {
                float w = keys_cubic(f + 1.f - t);
                int jj = base + t;
                if (jj < 0 || jj >= 256) w = 0.f;
                tot += w;
                if (t == tt) wsel = w;
            }
            acc += xr[I] * (wsel / tot);
        }
        Z[idx] = acc;
    }
}

// W[b][I][c] = sum_t w_t(I) Y[b][base+t][c]
__global__ void upapply2_k(const float* __restrict__ Y1, const float* __restrict__ Y2,
                           float* __restrict__ W1, float* __restrict__ W2)
{
    int gidx = blockIdx.x * 256 + threadIdx.x;
    if (gidx >= 1048576) return;
    const float* Y = gidx < 524288 ? Y1 : Y2;
    float* Wo = gidx < 524288 ? W1 : W2;
    int idx = gidx & 524287;
    int c = idx & 63;
    int I = (idx >> 6) & 1023;
    int b = idx >> 16;

    float sf = (I + 0.5f) * 0.25f - 0.5f;
    float fl = floorf(sf);
    float f  = sf - fl;
    int base = (int)fl - 1;
    float w[4], tot = 0.f;
#pragma unroll
    for (int t = 0; t < 4; t++) {
        float ww = keys_cubic(f + 1.f - t);
        int jj = base + t;
        if (jj < 0 || jj >= 256) ww = 0.f;
        w[t] = ww; tot += ww;
    }
    float inv = 1.f / tot;
    const float* Yb = Y + (long)b * 16384;
    float acc = 0.f;
#pragma unroll
    for (int t = 0; t < 4; t++)
        if (w[t] != 0.f) acc += w[t] * Yb[(base + t) * 64 + c];
    Wo[idx] = acc * inv;
}

// ---------------------------------------------------------------------------
// BN stats for all four tensors (grid 256)
// ---------------------------------------------------------------------------
__global__ void bn_all_k(const float* __restrict__ CH1O, const float* __restrict__ CH2O,
                         const float* __restrict__ HW1OT, const float* __restrict__ HW2OT,
                         float* __restrict__ mv)
{
    int which = blockIdx.x >> 6, c = blockIdx.x & 63;
    const float* T = which == 0 ? CH1O : which == 1 ? CH2O : which == 2 ? HW1OT : HW2OT;
    bool tr = which >= 2;
    int t = threadIdx.x;
    float s = 0.f, s2 = 0.f;
    for (int i = t; i < 8192; i += 256) {
        float v = tr ? T[(long)(i >> 10) * 65536 + (long)(i & 1023) * 64 + c]
                     : T[(long)(i >> 10) * 65536 + c * 1024 + (i & 1023)];
        s += v; s2 += v * v;
    }
    __shared__ float sh1[8], sh2[8];
#pragma unroll
    for (int o = 16; o; o >>= 1) {
        s  += __shfl_xor_sync(0xffffffffu, s, o);
        s2 += __shfl_xor_sync(0xffffffffu, s2, o);
    }
    if ((t & 31) == 0) { sh1[t >> 5] = s; sh2[t >> 5] = s2; }
    __syncthreads();
    if (t == 0) {
        float ts = 0.f, ts2 = 0.f;
#pragma unroll
        for (int w = 0; w < 8; w++) { ts += sh1[w]; ts2 += sh2[w]; }
        float mean = ts * (1.f / 8192.f);
        float var  = ts2 * (1.f / 8192.f) - mean * mean;
        mv[which * 128 + c] = mean;
        mv[which * 128 + 64 + c] = fmaxf(var, 0.f);
    }
}

// ---------------------------------------------------------------------------
// Finalize
// ---------------------------------------------------------------------------
__global__ void finalize_k(const float* __restrict__ x1, const float* __restrict__ x2,
                           const float* __restrict__ ch1o, const float* __restrict__ ch2o,
                           const float* __restrict__ hw1t, const float* __restrict__ hw2t,
                           const float* __restrict__ mv,
                           const float* __restrict__ gamma, const float* __restrict__ beta,
                           float* __restrict__ out)
{
    int idx = blockIdx.x * 256 + threadIdx.x;
    if (idx >= 524288) return;
    int c = (idx >> 10) & 63;
    long hwi = ((long)(idx >> 16)) * 65536 + (long)(idx & 1023) * 64 + c;
    float g = gamma[c], be = beta[c];

    float xa = x1[idx], xb = x2[idx];

    float v, r;
    v = (ch1o[idx] - mv[c])       * rsqrtf(mv[64 + c]  + 1e-5f) * g + be + xa;
    r = fmaxf(v, 0.f);
    v = (hw1t[hwi] - mv[256 + c]) * rsqrtf(mv[320 + c] + 1e-5f) * g + be + xa;
    out[idx] = 0.5f * (r + fmaxf(v, 0.f));

    v = (ch2o[idx] - mv[128 + c]) * rsqrtf(mv[192 + c] + 1e-5f) * g + be + xb;
    r = fmaxf(v, 0.f);
    v = (hw2t[hwi] - mv[384 + c]) * rsqrtf(mv[448 + c] + 1e-5f) * g + be + xb;
    out[524288 + idx] = 0.5f * (r + fmaxf(v, 0.f));
}

// ===========================================================================
extern "C" void kernel_launch(void* const* d_in, const int* in_sizes, int n_in,
                              void* d_out, int out_size)
{
    const float* x1     = (const float*)d_in[0];
    const float* x2     = (const float*)d_in[1];
    const float* w_down = (const float*)d_in[2];
    const float* b_down = (const float*)d_in[3];
    const float* w_up   = (const float*)d_in[4];
    const float* b_up   = (const float*)d_in[5];
    const float* gamma  = (const float*)d_in[6];
    const float* beta   = (const float*)d_in[7];
    float* out = (float*)d_out;

    float* base = nullptr;
    cudaGetSymbolAddress((void**)&base, g_buf);

    float* LB = base;                      // [8,1024,1024]
    float* S  = base + 8ll * 1024 * 1024;
    float* X1C   = S; S += 32768;    // (X1C,X2C,G12 contiguous for reduceA)
    float* X2C   = S; S += 32768;
    float* G12   = S; S += 32768;
    float* GD    = S; S += 32768;
    float* CH1   = S; S += 32768;
    float* CH2   = S; S += 32768;
    float* CH1O  = S; S += 524288;
    float* CH2O  = S; S += 524288;
    float* XDN1  = S; S += 131072;
    float* XDN2  = S; S += 131072;
    float* PD    = S; S += 131072;
    float* LFD   = S; S += 524288;
    float* AFD12 = S; S += 524288;
    float* AFD21T= S; S += 524288;
    float* Z1    = S; S += 131072;
    float* Z2    = S; S += 131072;
    float* Y1    = S; S += 131072;
    float* Y2    = S; S += 131072;
    float* W1    = S; S += 524288;
    float* W2    = S; S += 524288;
    float* HW1OT = S; S += 524288;
    float* HW2OT = S; S += 524288;
    float* PP    = S; S += 524288;
    unsigned* RSME = (unsigned*)S; S += 8192;   // encoded row maxes (RSME+CSME contiguous)
    unsigned* CSME = (unsigned*)S; S += 8192;
    float* R12   = S; S += 1024;
    float* PART  = S; S += 786432;
    float* MV    = S; S += 512;

    const int CHAN_SMEM = 38720 * 4;
    cudaFuncSetAttribute(chan_fused_k, cudaFuncAttributeMaxDynamicSharedMemorySize, CHAN_SMEM);

    // ---- grams + rowsums (also zeros the encoded max arrays) ----
    rowsum_k<<<16, 256>>>(x1, x2, R12, RSME);
    gramA_k<<<dim3(8, 24), 256>>>(x1, x2, PART);
    reduceA_k<<<384, 256>>>(PART, X1C);           // X1C, X2C, G12

    // ---- fused channel path ----
    chan_fused_k<<<8, 256, CHAN_SMEM>>>(X1C, X2C, R12, w_down, b_down, w_up, b_up, CH1, CH2);
    trio_k<<<dim3(16, 24), 256>>>(CH1, CH2, G12, x1, x2, CH1O, CH2O, PP);

    // ---- big logits (row/col maxes folded into epilogue) ----
    lbgemm_k<<<dim3(16, 16, 8), 256>>>(x1, PP, LB, RSME, CSME);

    // ---- downsampled attention (one direction; other is transpose) ----
    resample_k<<<2048, 256>>>(x1, x2, XDN1, XDN2, Z1, Z2);
    gram_k<<<dim3(2, 8), 256>>>(XDN1, XDN2, PART, 256, 128, 16384, 16384);
    gram_reduce_k<<<128, 256>>>(PART, GD, 2);
    launch_gemm64(false, false, GD, XDN2, PD, 64, 256, 64, 4096, 16384, 16384, 8);
    launch_gemm64(true,  false, XDN1, PD, LFD, 256, 256, 64, 16384, 16384, 65536, 8);
    row_softmax_k<<<2048, 256>>>(LFD, AFD12, 256);
    colsoftT_k<<<dim3(4, 8), 256>>>(LFD, AFD21T, 256);

    // ---- W = U (AFD (xU)^T) ----
    launch_gemm64(false, true, AFD12,  Z1, Y1, 256, 64, 256, 65536, 16384, 16384, 8);
    launch_gemm64(true,  true, AFD21T, Z2, Y2, 256, 64, 256, 65536, 16384, 16384, 8);
    upapply2_k<<<4096, 256>>>(Y1, Y2, W1, W2);

    // ---- fused softmax(L) @ W ----
    av_row_k<<<dim3(16, 8), 256>>>(LB, W1, RSME, HW1OT);
    av_col_k<<<dim3(16, 8), 256>>>(LB, W2, CSME, HW2OT);

    // ---- BN + residual + relu + average ----
    bn_all_k<<<256, 256>>>(CH1O, CH2O, HW1OT, HW2OT, MV);
    finalize_k<<<2048, 256>>>(x1, x2, CH1O, CH2O, HW1OT, HW2OT, MV, gamma, beta, out);
}

// round 12
// speedup vs baseline: 9.9505x; 1.0988x over previous
#include <cuda_runtime.h>
#include <math.h>

// ---------------------------------------------------------------------------
// B=8, C=64, HW=1024, D=32.
// L = x1^T (x1 x2^T) x2 ; LFD21 = LFD12^T ; X?CD via W·X?C·W^T identity;
// channel path fused (warp-split); row/col maxes folded into LB epilogue;
// HW outputs via fused softmax·W with threshold-skipped exp, zero-tile skip,
// and inline sums.
// ---------------------------------------------------------------------------
__device__ float g_buf[17ll * 1024 * 1024];

// ---- order-preserving float <-> unsigned encoding for atomicMax ----
__device__ __forceinline__ unsigned fenc(float f)
{
    unsigned b = __float_as_uint(f);
    return (b & 0x80000000u) ? ~b : (b | 0x80000000u);
}
__device__ __forceinline__ float fdec(unsigned u)
{
    return (u & 0x80000000u) ? __uint_as_float(u & 0x7FFFFFFFu)
                             : __uint_as_float(~u);
}

// ===========================================================================
// gemm64: C[b](MxN) = opA(A[b]) * opB(B[b]); tile 64x64, KT=16, 256 thr, 4x4.
// ===========================================================================
template <bool TA, bool TB>
__global__ void __launch_bounds__(256)
gemm64_kernel(const float* __restrict__ A, const float* __restrict__ B,
              float* __restrict__ C, int M, int N, int K, long sA, long sB, long sC)
{
    __shared__ float As[16][68];
    __shared__ float Bs[16][68];
    const int tid = threadIdx.x;
    const int m0 = blockIdx.y * 64, n0 = blockIdx.x * 64;
    const float* Ab = A + (long)blockIdx.z * sA;
    const float* Bb = B + (long)blockIdx.z * sB;
    float* Cb = C + (long)blockIdx.z * sC;
    const int rowt = (tid >> 4) * 4, colt = (tid & 15) * 4;
    float acc[4][4] = {};

    for (int k0 = 0; k0 < K; k0 += 16) {
        float4 av = {0,0,0,0}, bv = {0,0,0,0};
        if (!TA) {
            int r = tid >> 2, c = (tid & 3) * 4;
            if (m0 + r < M) av = *(const float4*)(Ab + (long)(m0 + r) * K + k0 + c);
            As[c+0][r]=av.x; As[c+1][r]=av.y; As[c+2][r]=av.z; As[c+3][r]=av.w;
        } else {
            int kr = tid >> 4, mc = (tid & 15) * 4;
            if (m0 + mc < M) av = *(const float4*)(Ab + (long)(k0 + kr) * M + m0 + mc);
            *(float4*)&As[kr][mc] = av;
        }
        if (!TB) {
            int kr = tid >> 4, nc = (tid & 15) * 4;
            if (n0 + nc < N) bv = *(const float4*)(Bb + (long)(k0 + kr) * N + n0 + nc);
            *(float4*)&Bs[kr][nc] = bv;
        } else {
            int r = tid >> 2, c = (tid & 3) * 4;
            if (n0 + r < N) bv = *(const float4*)(Bb + (long)(n0 + r) * K + k0 + c);
            Bs[c+0][r]=bv.x; Bs[c+1][r]=bv.y; Bs[c+2][r]=bv.z; Bs[c+3][r]=bv.w;
        }
        __syncthreads();
#pragma unroll
        for (int kk = 0; kk < 16; kk++) {
            float4 a = *(const float4*)&As[kk][rowt];
            float4 b = *(const float4*)&Bs[kk][colt];
            float ra[4] = {a.x,a.y,a.z,a.w}, rb[4] = {b.x,b.y,b.z,b.w};
#pragma unroll
            for (int i = 0; i < 4; i++)
#pragma unroll
                for (int j = 0; j < 4; j++) acc[i][j] += ra[i] * rb[j];
        }
        __syncthreads();
    }
    if (n0 + colt < N) {
#pragma unroll
        for (int i = 0; i < 4; i++) {
            int m = m0 + rowt + i;
            if (m < M)
                *(float4*)(Cb + (long)m * N + n0 + colt) =
                    make_float4(acc[i][0], acc[i][1], acc[i][2], acc[i][3]);
        }
    }
}

static void launch_gemm64(bool ta, bool tb,
                          const float* A, const float* B, float* C,
                          int M, int N, int K, long sA, long sB, long sC, int batch)
{
    dim3 grid((N + 63) / 64, (M + 63) / 64, batch);
    if (!ta && !tb)      gemm64_kernel<false,false><<<grid,256>>>(A,B,C,M,N,K,sA,sB,sC);
    else if (!ta && tb)  gemm64_kernel<false,true ><<<grid,256>>>(A,B,C,M,N,K,sA,sB,sC);
    else if (ta && !tb)  gemm64_kernel<true ,false><<<grid,256>>>(A,B,C,M,N,K,sA,sB,sC);
    else                 gemm64_kernel<true ,true ><<<grid,256>>>(A,B,C,M,N,K,sA,sB,sC);
}

// ===========================================================================
// lbgemm: LB = x1^T @ PP  (M=N=1024, K=64), epilogue folds row/col maxes into
// encoded global atomicMax arrays. grid (16,16,8).
// ===========================================================================
__global__ void __launch_bounds__(256)
lbgemm_k(const float* __restrict__ X1, const float* __restrict__ PP,
         float* __restrict__ LB, unsigned* __restrict__ RSME, unsigned* __restrict__ CSME)
{
    __shared__ float As[16][68];
    __shared__ float Bs[16][68];
    __shared__ unsigned srow[64], scol[64];
    const int tid = threadIdx.x;
    const int m0 = blockIdx.y * 64, n0 = blockIdx.x * 64, b = blockIdx.z;
    const float* Ab = X1 + (long)b * 65536;
    const float* Bb = PP + (long)b * 65536;
    float* Cb = LB + (long)b * 1048576;
    const int rowt = (tid >> 4) * 4, colt = (tid & 15) * 4;
    const int kr = tid >> 4, xc = (tid & 15) * 4;
    float acc[4][4] = {};

    if (tid < 64) { srow[tid] = 0u; scol[tid] = 0u; }

    for (int k0 = 0; k0 < 64; k0 += 16) {
        *(float4*)&As[kr][xc] = *(const float4*)(Ab + (long)(k0 + kr) * 1024 + m0 + xc);
        *(float4*)&Bs[kr][xc] = *(const float4*)(Bb + (long)(k0 + kr) * 1024 + n0 + xc);
        __syncthreads();
#pragma unroll
        for (int kk = 0; kk < 16; kk++) {
            float4 a = *(const float4*)&As[kk][rowt];
            float4 bq = *(const float4*)&Bs[kk][colt];
            float ra[4] = {a.x,a.y,a.z,a.w}, rb[4] = {bq.x,bq.y,bq.z,bq.w};
#pragma unroll
            for (int i = 0; i < 4; i++)
#pragma unroll
                for (int j = 0; j < 4; j++) acc[i][j] += ra[i] * rb[j];
        }
        __syncthreads();
    }

#pragma unroll
    for (int i = 0; i < 4; i++)
        *(float4*)(Cb + (long)(m0 + rowt + i) * 1024 + n0 + colt) =
            make_float4(acc[i][0], acc[i][1], acc[i][2], acc[i][3]);

#pragma unroll
    for (int i = 0; i < 4; i++) {
        float rm = fmaxf(fmaxf(acc[i][0], acc[i][1]), fmaxf(acc[i][2], acc[i][3]));
        atomicMax(&srow[rowt + i], fenc(rm));
    }
#pragma unroll
    for (int j = 0; j < 4; j++) {
        float cm = fmaxf(fmaxf(acc[0][j], acc[1][j]), fmaxf(acc[2][j], acc[3][j]));
        atomicMax(&scol[colt + j], fenc(cm));
    }
    __syncthreads();
    if (tid < 64)       atomicMax(&RSME[b * 1024 + m0 + tid], srow[tid]);
    else if (tid < 128) atomicMax(&CSME[b * 1024 + n0 + (tid - 64)], scol[tid - 64]);
}

// ===========================================================================
// trio_k: three M=64,N=1024,K=64 NN GEMMs in one launch. grid (16, 24)
// ===========================================================================
__global__ void __launch_bounds__(256)
trio_k(const float* __restrict__ CH1, const float* __restrict__ CH2,
       const float* __restrict__ G12,
       const float* __restrict__ x1, const float* __restrict__ x2,
       float* __restrict__ CH1O, float* __restrict__ CH2O, float* __restrict__ PP)
{
    __shared__ float As[16][68];
    __shared__ float Bs[16][68];
    const int tid = threadIdx.x;
    const int z = blockIdx.y, pair = z >> 3, b = z & 7;
    const int n0 = blockIdx.x * 64;
    const float* Ab = (pair == 0 ? CH1 : pair == 1 ? CH2 : G12) + (long)b * 4096;
    const float* Bb = (pair == 0 ? x1 : x2) + (long)b * 65536;
    float* Cb = (pair == 0 ? CH1O : pair == 1 ? CH2O : PP) + (long)b * 65536;
    const int rowt = (tid >> 4) * 4, colt = (tid & 15) * 4;
    float acc[4][4] = {};

    for (int k0 = 0; k0 < 64; k0 += 16) {
        {
            int r = tid >> 2, c = (tid & 3) * 4;
            float4 av = *(const float4*)(Ab + r * 64 + k0 + c);
            As[c+0][r]=av.x; As[c+1][r]=av.y; As[c+2][r]=av.z; As[c+3][r]=av.w;
        }
        {
            int kr = tid >> 4, nc = (tid & 15) * 4;
            float4 bv = *(const float4*)(Bb + (long)(k0 + kr) * 1024 + n0 + nc);
            *(float4*)&Bs[kr][nc] = bv;
        }
        __syncthreads();
#pragma unroll
        for (int kk = 0; kk < 16; kk++) {
            float4 a = *(const float4*)&As[kk][rowt];
            float4 bq = *(const float4*)&Bs[kk][colt];
            float ra[4] = {a.x,a.y,a.z,a.w}, rb[4] = {bq.x,bq.y,bq.z,bq.w};
#pragma unroll
            for (int i = 0; i < 4; i++)
#pragma unroll
                for (int j = 0; j < 4; j++) acc[i][j] += ra[i] * rb[j];
        }
        __syncthreads();
    }
#pragma unroll
    for (int i = 0; i < 4; i++)
        *(float4*)(Cb + (long)(rowt + i) * 1024 + n0 + colt) =
            make_float4(acc[i][0], acc[i][1], acc[i][2], acc[i][3]);
}

// ===========================================================================
// gramA: 3 pairs {x1x1, x2x2, x1x2} x 8 batches x 8 k-splits. grid (8, 24).
// ===========================================================================
__global__ void __launch_bounds__(256)
gramA_k(const float* __restrict__ x1, const float* __restrict__ x2, float* __restrict__ P)
{
    __shared__ float Xs[16][68], Ys[16][68];
    const int tid = threadIdx.x;
    const int pz = blockIdx.y, pair = pz >> 3, b = pz & 7;
    const float* Xb = ((pair == 1) ? x2 : x1) + (long)b * 65536;
    const float* Yb = ((pair == 0) ? x1 : x2) + (long)b * 65536;
    const int kbase = blockIdx.x * 128;
    const int rowt = (tid >> 4) * 4, colt = (tid & 15) * 4;
    const int r = tid >> 2, c = (tid & 3) * 4;
    float acc[4][4] = {};

    for (int k0 = kbase; k0 < kbase + 128; k0 += 16) {
        float4 xv = *(const float4*)(Xb + (long)r * 1024 + k0 + c);
        float4 yv = *(const float4*)(Yb + (long)r * 1024 + k0 + c);
        Xs[c+0][r]=xv.x; Xs[c+1][r]=xv.y; Xs[c+2][r]=xv.z; Xs[c+3][r]=xv.w;
        Ys[c+0][r]=yv.x; Ys[c+1][r]=yv.y; Ys[c+2][r]=yv.z; Ys[c+3][r]=yv.w;
        __syncthreads();
#pragma unroll
        for (int kk = 0; kk < 16; kk++) {
            float4 a = *(const float4*)&Xs[kk][rowt];
            float4 bq = *(const float4*)&Ys[kk][colt];
            float ra[4]={a.x,a.y,a.z,a.w}, rb[4]={bq.x,bq.y,bq.z,bq.w};
#pragma unroll
            for (int i = 0; i < 4; i++)
#pragma unroll
                for (int j = 0; j < 4; j++) acc[i][j] += ra[i] * rb[j];
        }
        __syncthreads();
    }
    float* Pp = P + ((long)pz * 8 + blockIdx.x) * 4096;
#pragma unroll
    for (int i = 0; i < 4; i++)
        *(float4*)(Pp + (rowt + i) * 64 + colt) =
            make_float4(acc[i][0], acc[i][1], acc[i][2], acc[i][3]);
}

__global__ void reduceA_k(const float* __restrict__ P, float* __restrict__ O)
{
    int idx = blockIdx.x * 256 + threadIdx.x;   // < 98304
    int pz = idx >> 12, e = idx & 4095;
    float s = 0.f;
#pragma unroll
    for (int k = 0; k < 8; k++) s += P[((long)pz * 8 + k) * 4096 + e];
    O[idx] = s;
}

// Generic split-K gram (GD): grid (nsplit, batch), M=N=64
__global__ void __launch_bounds__(256)
gram_k(const float* __restrict__ X, const float* __restrict__ Y,
       float* __restrict__ P, int K, int klen, long sX, long sY)
{
    __shared__ float Xs[16][68], Ys[16][68];
    const int tid = threadIdx.x;
    const float* Xb = X + (long)blockIdx.y * sX;
    const float* Yb = Y + (long)blockIdx.y * sY;
    const int kbase = blockIdx.x * klen;
    const int rowt = (tid >> 4) * 4, colt = (tid & 15) * 4;
    const int r = tid >> 2, c = (tid & 3) * 4;
    float acc[4][4] = {};

    for (int k0 = kbase; k0 < kbase + klen; k0 += 16) {
        float4 xv = *(const float4*)(Xb + (long)r * K + k0 + c);
        float4 yv = *(const float4*)(Yb + (long)r * K + k0 + c);
        Xs[c+0][r]=xv.x; Xs[c+1][r]=xv.y; Xs[c+2][r]=xv.z; Xs[c+3][r]=xv.w;
        Ys[c+0][r]=yv.x; Ys[c+1][r]=yv.y; Ys[c+2][r]=yv.z; Ys[c+3][r]=yv.w;
        __syncthreads();
#pragma unroll
        for (int kk = 0; kk < 16; kk++) {
            float4 a = *(const float4*)&Xs[kk][rowt];
            float4 bq = *(const float4*)&Ys[kk][colt];
            float ra[4]={a.x,a.y,a.z,a.w}, rb[4]={bq.x,bq.y,bq.z,bq.w};
#pragma unroll
            for (int i = 0; i < 4; i++)
#pragma unroll
                for (int j = 0; j < 4; j++) acc[i][j] += ra[i] * rb[j];
        }
        __syncthreads();
    }
    float* Pp = P + ((long)blockIdx.y * gridDim.x + blockIdx.x) * 4096;
#pragma unroll
    for (int i = 0; i < 4; i++)
        *(float4*)(Pp + (rowt + i) * 64 + colt) =
            make_float4(acc[i][0], acc[i][1], acc[i][2], acc[i][3]);
}

__global__ void gram_reduce_k(const float* __restrict__ P, float* __restrict__ C, int nsplit)
{
    int idx = blockIdx.x * 256 + threadIdx.x;
    if (idx >= 32768) return;
    int b = idx >> 12, e = idx & 4095;
    float s = 0.f;
    for (int k = 0; k < nsplit; k++) s += P[((long)b * nsplit + k) * 4096 + e];
    C[idx] = s;
}

// ---------------------------------------------------------------------------
// Row sums of x1/x2 + zero the encoded max arrays (16384 words)
// ---------------------------------------------------------------------------
__global__ void rowsum_k(const float* __restrict__ x1, const float* __restrict__ x2,
                         float* __restrict__ r, unsigned* __restrict__ ME)
{
    int gid = blockIdx.x * 256 + threadIdx.x;
    for (int i = gid; i < 16384; i += 4096) ME[i] = 0u;

    int which = blockIdx.x >> 3, b = blockIdx.x & 7;
    const float* xb = (which ? x2 : x1) + (long)b * 65536;
    int w = threadIdx.x >> 5, lane = threadIdx.x & 31;
    for (int rr = w * 8; rr < w * 8 + 8; rr++) {
        float s = 0.f;
        for (int p = lane; p < 1024; p += 32) s += xb[rr * 1024 + p];
#pragma unroll
        for (int o = 16; o; o >>= 1) s += __shfl_xor_sync(0xffffffffu, s, o);
        if (lane == 0) r[which * 512 + b * 64 + rr] = s;
    }
}

// ===========================================================================
// smm / smm128: in-smem matmuls (256 / 128 threads)
// ===========================================================================
template<int M, int N, int K, bool BT>
__device__ __forceinline__ void smm(const float* __restrict__ A, int lda,
                                    const float* __restrict__ B, int ldb,
                                    float* __restrict__ C, int ldc,
                                    const float* __restrict__ bias,
                                    const float* __restrict__ rscale, int t)
{
    constexpr int RM = M / 16, RN = N / 16;
    const int r0 = (t >> 4) * RM, c0 = (t & 15) * RN;
    float acc[RM][RN];
#pragma unroll
    for (int i = 0; i < RM; i++) {
        float bv = bias ? bias[r0 + i] : 0.f;
#pragma unroll
        for (int j = 0; j < RN; j++) acc[i][j] = bv;
    }
#pragma unroll 4
    for (int k = 0; k < K; k++) {
        float a[RM], b[RN];
#pragma unroll
        for (int i = 0; i < RM; i++) a[i] = A[(r0 + i) * lda + k];
#pragma unroll
        for (int j = 0; j < RN; j++) b[j] = BT ? B[(c0 + j) * ldb + k] : B[k * ldb + c0 + j];
#pragma unroll
        for (int i = 0; i < RM; i++)
#pragma unroll
            for (int j = 0; j < RN; j++) acc[i][j] += a[i] * b[j];
    }
#pragma unroll
    for (int i = 0; i < RM; i++) {
        float sc = rscale ? rscale[r0 + i] : 1.f;
#pragma unroll
        for (int j = 0; j < RN; j++) C[(r0 + i) * ldc + c0 + j] = acc[i][j] * sc;
    }
}

template<int M, int N, int K, bool BT>
__device__ __forceinline__ void smm128(const float* __restrict__ A, int lda,
                                       const float* __restrict__ B, int ldb,
                                       float* __restrict__ C, int ldc,
                                       const float* __restrict__ bias,
                                       const float* __restrict__ rscale, int t)
{
    constexpr int RM = M / 8, RN = N / 16;
    const int r0 = (t >> 4) * RM, c0 = (t & 15) * RN;
    float acc[RM][RN];
#pragma unroll
    for (int i = 0; i < RM; i++) {
        float bv = bias ? bias[r0 + i] : 0.f;
#pragma unroll
        for (int j = 0; j < RN; j++) acc[i][j] = bv;
    }
#pragma unroll 4
    for (int k = 0; k < K; k++) {
        float a[RM], b[RN];
#pragma unroll
        for (int i = 0; i < RM; i++) a[i] = A[(r0 + i) * lda + k];
#pragma unroll
        for (int j = 0; j < RN; j++) b[j] = BT ? B[(c0 + j) * ldb + k] : B[k * ldb + c0 + j];
#pragma unroll
        for (int i = 0; i < RM; i++)
#pragma unroll
            for (int j = 0; j < RN; j++) acc[i][j] += a[i] * b[j];
    }
#pragma unroll
    for (int i = 0; i < RM; i++) {
        float sc = rscale ? rscale[r0 + i] : 1.f;
#pragma unroll
        for (int j = 0; j < RN; j++) C[(r0 + i) * ldc + c0 + j] = acc[i][j] * sc;
    }
}

// Cd = Mb(32x64,ld68) * Wd^T + bd u^T + u bd^T + 1024 bd bd^T  (128 threads)
__device__ __forceinline__ void cd_stage(const float* __restrict__ Mb,
                                         const float* __restrict__ Wd,
                                         float* __restrict__ Cd,
                                         const float* __restrict__ bd,
                                         const float* __restrict__ u, int t)
{
    const int r0 = (t >> 4) * 4, c0 = (t & 15) * 2;
    float acc[4][2] = {};
#pragma unroll 4
    for (int k = 0; k < 64; k++) {
        float a[4], b[2];
#pragma unroll
        for (int i = 0; i < 4; i++) a[i] = Mb[(r0 + i) * 68 + k];
#pragma unroll
        for (int j = 0; j < 2; j++) b[j] = Wd[(c0 + j) * 64 + k];
#pragma unroll
        for (int i = 0; i < 4; i++)
#pragma unroll
            for (int j = 0; j < 2; j++) acc[i][j] += a[i] * b[j];
    }
#pragma unroll
    for (int i = 0; i < 4; i++) {
        int d = r0 + i;
#pragma unroll
        for (int j = 0; j < 2; j++) {
            int e = c0 + j;
            Cd[d * 36 + e] = acc[i][j] + bd[d]*u[e] + bd[e]*u[d] + 1024.f*bd[d]*bd[e];
        }
    }
}

// ===========================================================================
// Fused channel path (warp-split halves)
// ===========================================================================
__global__ void __launch_bounds__(256)
chan_fused_k(const float* __restrict__ X1C_g, const float* __restrict__ X2C_g,
             const float* __restrict__ rsum,
             const float* __restrict__ w_down, const float* __restrict__ b_down,
             const float* __restrict__ w_up, const float* __restrict__ b_up,
             float* __restrict__ CH1_g, float* __restrict__ CH2_g)
{
    extern __shared__ float sm[];
    float* A   = sm;              // 64x68  X1C -> U1T
    float* Bf  = A   + 4352;      // 64x68  X2C -> U2T
    float* LC  = Bf  + 4352;      // 64x68  LC -> E12
    float* E2  = LC  + 4352;      // 64x68
    float* Wd  = E2  + 4352;      // 32x64
    float* Wu  = Wd  + 2048;      // 64x32
    float* Mb1 = Wu  + 2048;      // 32x68
    float* Mb2 = Mb1 + 2176;      // 32x68
    float* C1d = Mb2 + 2176;      // 32x36
    float* C2d = C1d + 1152;
    float* LCD = C2d + 1152;
    float* A12d= LCD + 1152;
    float* A21d= A12d+ 1152;
    float* TT1 = A21d+ 1152;      // 64x36
    float* TT2 = TT1 + 2304;
    float* bd  = TT2 + 2304;      // 32
    float* bu  = bd  + 32;        // 64
    float* u1  = bu  + 64;        // 32
    float* u2  = u1  + 32;        // 32
    float* st  = u2  + 32;        // 256

    const int b = blockIdx.x, t = threadIdx.x;
    const bool h0 = t < 128;
    const int ht = h0 ? t : t - 128;

    for (int i = t; i < 4096; i += 256) {
        A [(i >> 6) * 68 + (i & 63)] = X1C_g[b * 4096 + i];
        Bf[(i >> 6) * 68 + (i & 63)] = X2C_g[b * 4096 + i];
    }
    for (int i = t; i < 2048; i += 256) { Wd[i] = w_down[i]; Wu[i] = w_up[i]; }
    if (t < 32) bd[t] = b_down[t];
    if (t < 64) bu[t] = b_up[t];
    __syncthreads();

    if (t < 64) {
        int d = t & 31, which = t >> 5;
        const float* r = rsum + which * 512 + b * 64;
        float s = 0.f;
        for (int c = 0; c < 64; c++) s += Wd[d * 64 + c] * r[c];
        (which ? u2 : u1)[d] = s;
    }
    __syncthreads();

    if (h0) smm128<32, 64, 64, false>(Wd, 64, A, 68, Mb1, 68, nullptr, nullptr, ht);
    else    smm128<32, 64, 64, false>(Wd, 64, Bf, 68, Mb2, 68, nullptr, nullptr, ht);
    __syncthreads();
    if (h0) cd_stage(Mb1, Wd, C1d, bd, u1, ht);
    else    cd_stage(Mb2, Wd, C2d, bd, u2, ht);
    __syncthreads();

    smm<64, 64, 64, false>(A, 68, Bf, 68, LC, 68, nullptr, nullptr, t);
    __syncthreads();

    if (t < 64) {
        float m = -3.4e38f;
        for (int j = 0; j < 64; j++) m = fmaxf(m, LC[t * 68 + j]);
        float s = 0.f;
        for (int j = 0; j < 64; j++) s += __expf(LC[t * 68 + j] - m);
        st[t] = m; st[64 + t] = 1.f / s;
    } else if (t < 128) {
        int i = t - 64;
        float m = -3.4e38f;
        for (int j = 0; j < 64; j++) m = fmaxf(m, LC[j * 68 + i]);
        float s = 0.f;
        for (int j = 0; j < 64; j++) s += __expf(LC[j * 68 + i] - m);
        st[128 + i] = m; st[192 + i] = 1.f / s;
    } else {
        smm128<32, 32, 32, false>(C1d, 36, C2d, 36, LCD, 36, nullptr, nullptr, ht);
    }
    __syncthreads();

    if (t < 192) {
        for (int o = t; o < 4096; o += 192) {
            int i = o >> 6, j = o & 63;
            E2[i * 68 + j] = __expf(LC[j * 68 + i] - st[128 + i]);
        }
        for (int o = t; o < 4096; o += 192) {
            int i = o >> 6, j = o & 63;
            LC[i * 68 + j] = __expf(LC[i * 68 + j] - st[i]);
        }
    } else if (t < 224) {
        int i = t - 192;
        float m = -3.4e38f;
        for (int j = 0; j < 32; j++) m = fmaxf(m, LCD[i * 36 + j]);
        float s = 0.f;
        for (int j = 0; j < 32; j++) s += __expf(LCD[i * 36 + j] - m);
        float inv = 1.f / s;
        for (int j = 0; j < 32; j++) A12d[i * 36 + j] = __expf(LCD[i * 36 + j] - m) * inv;
    } else {
        int i = t - 224;
        float m = -3.4e38f;
        for (int j = 0; j < 32; j++) m = fmaxf(m, LCD[j * 36 + i]);
        float s = 0.f;
        for (int j = 0; j < 32; j++) s += __expf(LCD[j * 36 + i] - m);
        float inv = 1.f / s;
        for (int j = 0; j < 32; j++) A21d[i * 36 + j] = __expf(LCD[j * 36 + i] - m) * inv;
    }
    __syncthreads();

    if (h0) smm128<64, 32, 32, false>(Wu, 32, A12d, 36, TT1, 36, bu, nullptr, ht);
    else    smm128<64, 32, 32, false>(Wu, 32, A21d, 36, TT2, 36, bu, nullptr, ht);
    __syncthreads();
    if (h0) smm128<64, 64, 32, true >(Wu, 32, TT1, 36, A, 68, bu, nullptr, ht);
    else    smm128<64, 64, 32, true >(Wu, 32, TT2, 36, Bf, 68, bu, nullptr, ht);
    __syncthreads();

    if (h0) smm128<64, 64, 64, true>(LC, 68, A, 68, CH1_g + b * 4096, 64, nullptr, st + 64, ht);
    else    smm128<64, 64, 64, true>(E2, 68, Bf, 68, CH2_g + b * 4096, 64, nullptr, st + 192, ht);
}

// ===========================================================================
// Merged LFD softmaxes: blocks 0..2047 = row softmax (AFD12);
// blocks 2048..2079 = column softmax written transposed (AFD21T). N=256.
// ===========================================================================
__global__ void softLFD_k(const float* __restrict__ L,
                          float* __restrict__ AFD12, float* __restrict__ AFD21T)
{
    if (blockIdx.x < 2048) {
        long row = blockIdx.x;
        const float* p = L + row * 256;
        float* q = AFD12 + row * 256;
        int t = threadIdx.x;
        __shared__ float sh[8];

        float m = -3.4e38f;
        for (int i = t; i < 256; i += 256) m = fmaxf(m, p[i]);
#pragma unroll
        for (int o = 16; o; o >>= 1) m = fmaxf(m, __shfl_xor_sync(0xffffffffu, m, o));
        if ((t & 31) == 0) sh[t >> 5] = m;
        __syncthreads();
        float mm = sh[0];
#pragma unroll
        for (int w = 1; w < 8; w++) mm = fmaxf(mm, sh[w]);
        __syncthreads();

        float s = __expf(p[t] - mm);
        float sv = s;
#pragma unroll
        for (int o = 16; o; o >>= 1) s += __shfl_xor_sync(0xffffffffu, s, o);
        if ((t & 31) == 0) sh[t >> 5] = s;
        __syncthreads();
        float ss = 0.f;
#pragma unroll
        for (int w = 0; w < 8; w++) ss += sh[w];
        q[t] = sv / ss;
    } else {
        int blk = blockIdx.x - 2048;   // 0..31 : (4 col-tiles) x 8 batches
        int cc = threadIdx.x & 63;
        int kg = threadIdx.x >> 6;
        int bi = blk >> 2;             // batch
        int i  = (blk & 3) * 64 + cc;  // column
        const float* Lb = L      + (long)bi * 65536;
        float*       Ab = AFD21T + (long)bi * 65536;
        __shared__ float red[4][64];

        float m = -3.4e38f;
        for (int k = kg; k < 256; k += 4) m = fmaxf(m, Lb[k * 256 + i]);
        red[kg][cc] = m;
        __syncthreads();
        m = fmaxf(fmaxf(red[0][cc], red[1][cc]), fmaxf(red[2][cc], red[3][cc]));
        __syncthreads();

        float s = 0.f;
        for (int k = kg; k < 256; k += 4) s += __expf(Lb[k * 256 + i] - m);
        red[kg][cc] = s;
        __syncthreads();
        s = red[0][cc] + red[1][cc] + red[2][cc] + red[3][cc];
        float inv = 1.f / s;

        for (int k = kg; k < 256; k += 4)
            Ab[k * 256 + i] = __expf(Lb[k * 256 + i] - m) * inv;
    }
}

// ===========================================================================
// ypair: Y1 = AFD12 @ Z1^T ; Y2 = AFD21T^T @ Z2^T. grid (4, 8, 2). M=256,N=64,K=256.
// ===========================================================================
__global__ void __launch_bounds__(256)
ypair_k(const float* __restrict__ AFD12, const float* __restrict__ AFD21T,
        const float* __restrict__ Z1, const float* __restrict__ Z2,
        float* __restrict__ Y1, float* __restrict__ Y2)
{
    __shared__ float As[16][68];
    __shared__ float Bs[16][68];
    const int tid = threadIdx.x;
    const int m0 = blockIdx.x * 64, b = blockIdx.y, dir = blockIdx.z;
    const float* Ab = (dir ? AFD21T : AFD12) + (long)b * 65536;
    const float* Zb = (dir ? Z2 : Z1) + (long)b * 16384;
    float* Yb = (dir ? Y2 : Y1) + (long)b * 16384;
    const int rowt = (tid >> 4) * 4, colt = (tid & 15) * 4;
    float acc[4][4] = {};

    for (int k0 = 0; k0 < 256; k0 += 16) {
        if (dir == 0) {   // A [M][K]
            int r = tid >> 2, c = (tid & 3) * 4;
            float4 av = *(const float4*)(Ab + (long)(m0 + r) * 256 + k0 + c);
            As[c+0][r]=av.x; As[c+1][r]=av.y; As[c+2][r]=av.z; As[c+3][r]=av.w;
        } else {          // A [K][M]
            int kr = tid >> 4, mc = (tid & 15) * 4;
            *(float4*)&As[kr][mc] = *(const float4*)(Ab + (long)(k0 + kr) * 256 + m0 + mc);
        }
        {   // Z [N=64][K] -> Bs[k][n]
            int r = tid >> 2, c = (tid & 3) * 4;
            float4 bv = *(const float4*)(Zb + (long)r * 256 + k0 + c);
            Bs[c+0][r]=bv.x; Bs[c+1][r]=bv.y; Bs[c+2][r]=bv.z; Bs[c+3][r]=bv.w;
        }
        __syncthreads();
#pragma unroll
        for (int kk = 0; kk < 16; kk++) {
            float4 a = *(const float4*)&As[kk][rowt];
            float4 bq = *(const float4*)&Bs[kk][colt];
            float ra[4]={a.x,a.y,a.z,a.w}, rb[4]={bq.x,bq.y,bq.z,bq.w};
#pragma unroll
            for (int i = 0; i < 4; i++)
#pragma unroll
                for (int j = 0; j < 4; j++) acc[i][j] += ra[i] * rb[j];
        }
        __syncthreads();
    }
#pragma unroll
    for (int i = 0; i < 4; i++)
        *(float4*)(Yb + (long)(m0 + rowt + i) * 64 + colt) =
            make_float4(acc[i][0], acc[i][1], acc[i][2], acc[i][3]);
}

// ===========================================================================
// Fused softmax(L)·W with threshold-skipped exp, zero-tile skip, inline sums.
// ===========================================================================
__global__ void __launch_bounds__(256)
av_row_k(const float* __restrict__ L, const float* __restrict__ W,
         const unsigned* __restrict__ RSME, float* __restrict__ O)
{
    __shared__ float Ls[16][68], Ws[16][68];
    __shared__ float smx[64], spart[256], sinv[64];
    const int tid = threadIdx.x;
    const int b = blockIdx.y, m0 = blockIdx.x * 64;
    if (tid < 64) smx[tid] = fdec(RSME[b * 1024 + m0 + tid]);
    __syncthreads();
    const float* Lb = L + (long)b * 1048576;
    const float* Wb = W + (long)b * 65536;
    const int rowt = (tid >> 4) * 4, colt = (tid & 15) * 4;
    const int r = tid >> 2, c = (tid & 3) * 4;
    const int kr = tid >> 4, nc = (tid & 15) * 4;
    float acc[4][4] = {};
    float psum = 0.f;
    const float mr = smx[r], thr = mr - 20.f;

    for (int k0 = 0; k0 < 1024; k0 += 16) {
        float4 v = *(const float4*)(Lb + (long)(m0 + r) * 1024 + k0 + c);
        float4 e = {0.f, 0.f, 0.f, 0.f};
        int live = 0;
        if (v.x > thr || v.y > thr || v.z > thr || v.w > thr) {
            e.x = __expf(v.x - mr); e.y = __expf(v.y - mr);
            e.z = __expf(v.z - mr); e.w = __expf(v.w - mr);
            psum += e.x + e.y + e.z + e.w;
            live = 1;
        }
        Ls[c+0][r] = e.x; Ls[c+1][r] = e.y; Ls[c+2][r] = e.z; Ls[c+3][r] = e.w;
        *(float4*)&Ws[kr][nc] = *(const float4*)(Wb + (long)(k0 + kr) * 64 + nc);
        int any = __syncthreads_or(live);      // barrier + all-zero detect
        if (any) {
#pragma unroll
            for (int kk = 0; kk < 16; kk++) {
                float4 a = *(const float4*)&Ls[kk][rowt];
                float4 w = *(const float4*)&Ws[kk][colt];
                float ra[4]={a.x,a.y,a.z,a.w}, rb[4]={w.x,w.y,w.z,w.w};
#pragma unroll
                for (int i = 0; i < 4; i++)
#pragma unroll
                    for (int j = 0; j < 4; j++) acc[i][j] += ra[i] * rb[j];
            }
        }
        __syncthreads();
    }
    spart[tid] = psum;
    __syncthreads();
    if (tid < 64)
        sinv[tid] = 1.f / (spart[4*tid] + spart[4*tid+1] + spart[4*tid+2] + spart[4*tid+3]);
    __syncthreads();

    float* Ob = O + (long)b * 65536;
#pragma unroll
    for (int i = 0; i < 4; i++) {
        float sc = sinv[rowt + i];
        *(float4*)(Ob + (long)(m0 + rowt + i) * 64 + colt) =
            make_float4(acc[i][0]*sc, acc[i][1]*sc, acc[i][2]*sc, acc[i][3]*sc);
    }
}

__global__ void __launch_bounds__(256)
av_col_k(const float* __restrict__ L, const float* __restrict__ W,
         const unsigned* __restrict__ CSME, float* __restrict__ O)
{
    __shared__ float Ls[16][68], Ws[16][68];
    __shared__ float smx[64], scs[16][64], sinv[64];
    const int tid = threadIdx.x;
    const int b = blockIdx.y, m0 = blockIdx.x * 64;
    if (tid < 64) smx[tid] = fdec(CSME[b * 1024 + m0 + tid]);
    __syncthreads();
    const float* Lb = L + (long)b * 1048576;
    const float* Wb = W + (long)b * 65536;
    const int rowt = (tid >> 4) * 4, colt = (tid & 15) * 4;
    const int kr = tid >> 4, mc = (tid & 15) * 4;
    float acc[4][4] = {};
    float ps[4] = {0.f, 0.f, 0.f, 0.f};
    const float m0f = smx[mc], m1f = smx[mc+1], m2f = smx[mc+2], m3f = smx[mc+3];

    for (int k0 = 0; k0 < 1024; k0 += 16) {
        float4 v = *(const float4*)(Lb + (long)(k0 + kr) * 1024 + m0 + mc);
        float4 e = {0.f, 0.f, 0.f, 0.f};
        int live = 0;
        if (v.x > m0f - 20.f || v.y > m1f - 20.f || v.z > m2f - 20.f || v.w > m3f - 20.f) {
            e.x = (v.x > m0f - 20.f) ? __expf(v.x - m0f) : 0.f;
            e.y = (v.y > m1f - 20.f) ? __expf(v.y - m1f) : 0.f;
            e.z = (v.z > m2f - 20.f) ? __expf(v.z - m2f) : 0.f;
            e.w = (v.w > m3f - 20.f) ? __expf(v.w - m3f) : 0.f;
            ps[0] += e.x; ps[1] += e.y; ps[2] += e.z; ps[3] += e.w;
            live = 1;
        }
        *(float4*)&Ls[kr][mc] = e;
        *(float4*)&Ws[kr][mc] = *(const float4*)(Wb + (long)(k0 + kr) * 64 + mc);
        int any = __syncthreads_or(live);
        if (any) {
#pragma unroll
            for (int kk = 0; kk < 16; kk++) {
                float4 a = *(const float4*)&Ls[kk][rowt];
                float4 w = *(const float4*)&Ws[kk][colt];
                float ra[4]={a.x,a.y,a.z,a.w}, rb[4]={w.x,w.y,w.z,w.w};
#pragma unroll
                for (int i = 0; i < 4; i++)
#pragma unroll
                    for (int j = 0; j < 4; j++) acc[i][j] += ra[i] * rb[j];
            }
        }
        __syncthreads();
    }
#pragma unroll
    for (int j = 0; j < 4; j++) scs[kr][mc + j] = ps[j];
    __syncthreads();
    if (tid < 64) {
        float s = 0.f;
#pragma unroll
        for (int k = 0; k < 16; k++) s += scs[k][tid];
        sinv[tid] = 1.f / s;
    }
    __syncthreads();

    float* Ob = O + (long)b * 65536;
#pragma unroll
    for (int i = 0; i < 4; i++) {
        float sc = sinv[rowt + i];
        *(float4*)(Ob + (long)(m0 + rowt + i) * 64 + colt) =
            make_float4(acc[i][0]*sc, acc[i][1]*sc, acc[i][2]*sc, acc[i][3]*sc);
    }
}

// ---------------------------------------------------------------------------
// Keys cubic + merged resampling
// ---------------------------------------------------------------------------
__device__ __forceinline__ float keys_cubic(float x)
{
    x = fabsf(x);
    if (x < 1.f) return ((1.5f * x - 2.5f) * x) * x + 1.f;
    if (x < 2.f) return ((-0.5f * x + 2.5f) * x - 4.f) * x + 2.f;
    return 0.f;
}

__global__ void resample_k(const float* __restrict__ x1, const float* __restrict__ x2,
                           float* __restrict__ y1, float* __restrict__ y2,
                           float* __restrict__ Z1, float* __restrict__ Z2)
{
    int gidx = blockIdx.x * 256 + threadIdx.x;
    if (gidx < 262144) {
        const float* x = gidx < 131072 ? x1 : x2;
        float* y = gidx < 131072 ? y1 : y2;
        int idx = gidx & 131071;
        int ox = idx & 15;
        int oy = (idx >> 4) & 15;
        int bc = idx >> 8;

        int jy0 = 2 * oy - 3, jx0 = 2 * ox - 3;
        float wy[8], wx[8];
        float sy = 0.f, sx = 0.f;
#pragma unroll
        for (int t = 0; t < 8; t++) {
            float w = keys_cubic(fabsf(3.5f - t) * 0.5f);
            int jy = jy0 + t;
            wy[t] = (jy >= 0 && jy < 32) ? w : 0.f; sy += wy[t];
            int jx = jx0 + t;
            wx[t] = (jx >= 0 && jx < 32) ? w : 0.f; sx += wx[t];
        }
        float iy = 1.f / sy, ix = 1.f / sx;
#pragma unroll
        for (int t = 0; t < 8; t++) { wy[t] *= iy; wx[t] *= ix; }

        const float* src = x + (long)bc * 1024;
        float acc = 0.f;
#pragma unroll
        for (int t = 0; t < 8; t++) {
            int jy = min(max(jy0 + t, 0), 31);
            float r = 0.f;
#pragma unroll
            for (int u = 0; u < 8; u++) {
                int jx = min(max(jx0 + u, 0), 31);
                r += wx[u] * src[jy * 32 + jx];
            }
            acc += wy[t] * r;
        }
        y[idx] = acc;
    } else if (gidx < 524288) {
        int g2 = gidx - 262144;
        const float* x = g2 < 131072 ? x1 : x2;
        float* Z = g2 < 131072 ? Z1 : Z2;
        int idx = g2 & 131071;
        int j = idx & 255;
        int c = (idx >> 8) & 63;
        int b = idx >> 14;
        const float* xr = x + (long)b * 65536 + (long)c * 1024;

        float acc = 0.f;
        int Ilo = max(0, 4 * j - 8), Ihi = min(1023, 4 * j + 10);
        for (int I = Ilo; I <= Ihi; I++) {
            float sf = (I + 0.5f) * 0.25f - 0.5f;
            float fl = floorf(sf);
            float f  = sf - fl;
            int base = (int)fl - 1;
            int tt = j - base;
            if (tt < 0 || tt > 3) continue;
            float tot = 0.f, wsel = 0.f;
#pragma unroll
            for (int t = 0; t < 4; t++) {
                float w = keys_cubic(f + 1.f - t);
                int jj = base + t;
                if (jj < 0 || jj >= 256) w = 0.f;
                tot += w;
                if (t == tt) wsel = w;
            }
            acc += xr[I] * (wsel / tot);
        }
        Z[idx] = acc;
    }
}

// W[b][I][c] = sum_t w_t(I) Y[b][base+t][c]
__global__ void upapply2_k(const float* __restrict__ Y1, const float* __restrict__ Y2,
                           float* __restrict__ W1, float* __restrict__ W2)
{
    int gidx = blockIdx.x * 256 + threadIdx.x;
    if (gidx >= 1048576) return;
    const float* Y = gidx < 524288 ? Y1 : Y2;
    float* Wo = gidx < 524288 ? W1 : W2;
    int idx = gidx & 524287;
    int c = idx & 63;
    int I = (idx >> 6) & 1023;
    int b = idx >> 16;

    float sf = (I + 0.5f) * 0.25f - 0.5f;
    float fl = floorf(sf);
    float f  = sf - fl;
    int base = (int)fl - 1;
    float w[4], tot = 0.f;
#pragma unroll
    for (int t = 0; t < 4; t++) {
        float ww = keys_cubic(f + 1.f - t);
        int jj = base + t;
        if (jj < 0 || jj >= 256) ww = 0.f;
        w[t] = ww; tot += ww;
    }
    float inv = 1.f / tot;
    const float* Yb = Y + (long)b * 16384;
    float acc = 0.f;
#pragma unroll
    for (int t = 0; t < 4; t++)
        if (w[t] != 0.f) acc += w[t] * Yb[(base + t) * 64 + c];
    Wo[idx] = acc * inv;
}

// ---------------------------------------------------------------------------
// BN stats for all four tensors (grid 256)
// ---------------------------------------------------------------------------
__global__ void bn_all_k(const float* __restrict__ CH1O, const float* __restrict__ CH2O,
                         const float* __restrict__ HW1OT, const float* __restrict__ HW2OT,
                         float* __restrict__ mv)
{
    int which = blockIdx.x >> 6, c = blockIdx.x & 63;
    const float* T = which == 0 ? CH1O : which == 1 ? CH2O : which == 2 ? HW1OT : HW2OT;
    bool tr = which >= 2;
    int t = threadIdx.x;
    float s = 0.f, s2 = 0.f;
    for (int i = t; i < 8192; i += 256) {
        float v = tr ? T[(long)(i >> 10) * 65536 + (long)(i & 1023) * 64 + c]
                     : T[(long)(i >> 10) * 65536 + c * 1024 + (i & 1023)];
        s += v; s2 += v * v;
    }
    __shared__ float sh1[8], sh2[8];
#pragma unroll
    for (int o = 16; o; o >>= 1) {
        s  += __shfl_xor_sync(0xffffffffu, s, o);
        s2 += __shfl_xor_sync(0xffffffffu, s2, o);
    }
    if ((t & 31) == 0) { sh1[t >> 5] = s; sh2[t >> 5] = s2; }
    __syncthreads();
    if (t == 0) {
        float ts = 0.f, ts2 = 0.f;
#pragma unroll
        for (int w = 0; w < 8; w++) { ts += sh1[w]; ts2 += sh2[w]; }
        float mean = ts * (1.f / 8192.f);
        float var  = ts2 * (1.f / 8192.f) - mean * mean;
        mv[which * 128 + c] = mean;
        mv[which * 128 + 64 + c] = fmaxf(var, 0.f);
    }
}

// ---------------------------------------------------------------------------
// Finalize
// ---------------------------------------------------------------------------
__global__ void finalize_k(const float* __restrict__ x1, const float* __restrict__ x2,
                           const float* __restrict__ ch1o, const float* __restrict__ ch2o,
                           const float* __restrict__ hw1t, const float* __restrict__ hw2t,
                           const float* __restrict__ mv,
                           const float* __restrict__ gamma, const float* __restrict__ beta,
                           float* __restrict__ out)
{
    int idx = blockIdx.x * 256 + threadIdx.x;
    if (idx >= 524288) return;
    int c = (idx >> 10) & 63;
    long hwi = ((long)(idx >> 16)) * 65536 + (long)(idx & 1023) * 64 + c;
    float g = gamma[c], be = beta[c];

    float xa = x1[idx], xb = x2[idx];

    float v, r;
    v = (ch1o[idx] - mv[c])       * rsqrtf(mv[64 + c]  + 1e-5f) * g + be + xa;
    r = fmaxf(v, 0.f);
    v = (hw1t[hwi] - mv[256 + c]) * rsqrtf(mv[320 + c] + 1e-5f) * g + be + xa;
    out[idx] = 0.5f * (r + fmaxf(v, 0.f));

    v = (ch2o[idx] - mv[128 + c]) * rsqrtf(mv[192 + c] + 1e-5f) * g + be + xb;
    r = fmaxf(v, 0.f);
    v = (hw2t[hwi] - mv[384 + c]) * rsqrtf(mv[448 + c] + 1e-5f) * g + be + xb;
    out[524288 + idx] = 0.5f * (r + fmaxf(v, 0.f));
}

// ===========================================================================
extern "C" void kernel_launch(void* const* d_in, const int* in_sizes, int n_in,
                              void* d_out, int out_size)
{
    const float* x1     = (const float*)d_in[0];
    const float* x2     = (const float*)d_in[1];
    const float* w_down = (const float*)d_in[2];
    const float* b_down = (const float*)d_in[3];
    const float* w_up   = (const float*)d_in[4];
    const float* b_up   = (const float*)d_in[5];
    const float* gamma  = (const float*)d_in[6];
    const float* beta   = (const float*)d_in[7];
    float* out = (float*)d_out;

    float* base = nullptr;
    cudaGetSymbolAddress((void**)&base, g_buf);

    float* LB = base;                      // [8,1024,1024]
    float* S  = base + 8ll * 1024 * 1024;
    float* X1C   = S; S += 32768;    // (X1C,X2C,G12 contiguous for reduceA)
    float* X2C   = S; S += 32768;
    float* G12   = S; S += 32768;
    float* GD    = S; S += 32768;
    float* CH1   = S; S += 32768;
    float* CH2   = S; S += 32768;
    float* CH1O  = S; S += 524288;
    float* CH2O  = S; S += 524288;
    float* XDN1  = S; S += 131072;
    float* XDN2  = S; S += 131072;
    float* PD    = S; S += 131072;
    float* LFD   = S; S += 524288;
    float* AFD12 = S; S += 524288;
    float* AFD21T= S; S += 524288;
    float* Z1    = S; S += 131072;
    float* Z2    = S; S += 131072;
    float* Y1    = S; S += 131072;
    float* Y2    = S; S += 131072;
    float* W1    = S; S += 524288;
    float* W2    = S; S += 524288;
    float* HW1OT = S; S += 524288;
    float* HW2OT = S; S += 524288;
    float* PP    = S; S += 524288;
    unsigned* RSME = (unsigned*)S; S += 8192;   // encoded row maxes (RSME+CSME contiguous)
    unsigned* CSME = (unsigned*)S; S += 8192;
    float* R12   = S; S += 1024;
    float* PART  = S; S += 786432;
    float* MV    = S; S += 512;

    const int CHAN_SMEM = 38720 * 4;
    cudaFuncSetAttribute(chan_fused_k, cudaFuncAttributeMaxDynamicSharedMemorySize, CHAN_SMEM);

    // ---- grams + rowsums (also zeros the encoded max arrays) ----
    rowsum_k<<<16, 256>>>(x1, x2, R12, RSME);
    gramA_k<<<dim3(8, 24), 256>>>(x1, x2, PART);
    reduceA_k<<<384, 256>>>(PART, X1C);           // X1C, X2C, G12

    // ---- fused channel path ----
    chan_fused_k<<<8, 256, CHAN_SMEM>>>(X1C, X2C, R12, w_down, b_down, w_up, b_up, CH1, CH2);
    trio_k<<<dim3(16, 24), 256>>>(CH1, CH2, G12, x1, x2, CH1O, CH2O, PP);

    // ---- big logits (row/col maxes folded into epilogue) ----
    lbgemm_k<<<dim3(16, 16, 8), 256>>>(x1, PP, LB, RSME, CSME);

    // ---- downsampled attention (one direction; other is transpose) ----
    resample_k<<<2048, 256>>>(x1, x2, XDN1, XDN2, Z1, Z2);
    gram_k<<<dim3(2, 8), 256>>>(XDN1, XDN2, PART, 256, 128, 16384, 16384);
    gram_reduce_k<<<128, 256>>>(PART, GD, 2);
    launch_gemm64(false, false, GD, XDN2, PD, 64, 256, 64, 4096, 16384, 16384, 8);
    launch_gemm64(true,  false, XDN1, PD, LFD, 256, 256, 64, 16384, 16384, 65536, 8);
    softLFD_k<<<2080, 256>>>(LFD, AFD12, AFD21T);

    // ---- W = U (AFD (xU)^T) ----
    ypair_k<<<dim3(4, 8, 2), 256>>>(AFD12, AFD21T, Z1, Z2, Y1, Y2);
    upapply2_k<<<4096, 256>>>(Y1, Y2, W1, W2);

    // ---- fused softmax(L) @ W ----
    av_row_k<<<dim3(16, 8), 256>>>(LB, W1, RSME, HW1OT);
    av_col_k<<<dim3(16, 8), 256>>>(LB, W2, CSME, HW2OT);

    // ---- BN + residual + relu + average ----
    bn_all_k<<<256, 256>>>(CH1O, CH2O, HW1OT, HW2OT, MV);
    finalize_k<<<2048, 256>>>(x1, x2, CH1O, CH2O, HW1OT, HW2OT, MV, gamma, beta, out);
}